// round 6
// baseline (speedup 1.0000x reference)
#include <cuda_runtime.h>
#include <cuda_fp16.h>
#include <cstdint>
#include <math.h>

#define BATCH 16
#define SEQ   512
#define DIM   2048
#define NH    16
#define NG    4
#define HD    128
#define MROWS (BATCH*SEQ)   // 8192
#define KVD   (NG*HD)       // 512
#define NQKV  (DIM + 2*KVD) // 3072

// ---------------------------------------------------------------------------
// scratch (device globals — no allocation allowed)
// ---------------------------------------------------------------------------
__device__ __half g_xhi[(size_t)MROWS * DIM];
__device__ __half g_xlo[(size_t)MROWS * DIM];
__device__ __half g_aoh[(size_t)MROWS * DIM];   // attn out hi (b,s,H,hd)
__device__ __half g_aol[(size_t)MROWS * DIM];
__device__ __half g_wh[(size_t)NQKV * DIM];     // [Wq^T; Wk^T; Wv^T] fp16 hi
__device__ __half g_wl[(size_t)NQKV * DIM];
__device__ __half g_woh[(size_t)DIM * DIM];
__device__ __half g_wol[(size_t)DIM * DIM];
__device__ float  g_bqkv[NQKV];                 // [bq; bk; bv]

// attention operand buffers, (b, head, s, hd) layout, fp16 hi/lo
__device__ __half g_qah[(size_t)MROWS * DIM];
__device__ __half g_qal[(size_t)MROWS * DIM];
__device__ __half g_kah[(size_t)MROWS * KVD];
__device__ __half g_kal[(size_t)MROWS * KVD];
__device__ __half g_vah[(size_t)MROWS * KVD];
__device__ __half g_val[(size_t)MROWS * KVD];

// ---------------------------------------------------------------------------
// helpers
// ---------------------------------------------------------------------------
__device__ __forceinline__ uint32_t smem_to_u32(const void* p) {
    uint32_t a;
    asm("{ .reg .u64 t; cvta.to.shared.u64 t, %1; cvt.u32.u64 %0, t; }" : "=r"(a) : "l"(p));
    return a;
}
#define SMEM_SWIZZLE_128B(bo) ((bo) ^ (((bo) >> 3) & 0x70))

__device__ __forceinline__ void cp16(uint32_t s, const void* g) {
    asm volatile("cp.async.cg.shared.global [%0], [%1], 16;" :: "r"(s), "l"(g) : "memory");
}
#define CP_COMMIT() asm volatile("cp.async.commit_group;" ::: "memory")
__device__ __forceinline__ void ldm4(uint32_t* r, uint32_t a) {
    asm volatile("ldmatrix.sync.aligned.m8n8.x4.shared.b16 {%0,%1,%2,%3}, [%4];"
                 : "=r"(r[0]), "=r"(r[1]), "=r"(r[2]), "=r"(r[3]) : "r"(a));
}
__device__ __forceinline__ void ldm4t(uint32_t* r, uint32_t a) {
    asm volatile("ldmatrix.sync.aligned.m8n8.x4.trans.shared.b16 {%0,%1,%2,%3}, [%4];"
                 : "=r"(r[0]), "=r"(r[1]), "=r"(r[2]), "=r"(r[3]) : "r"(a));
}
__device__ __forceinline__ void mma16816(float* d, const uint32_t* a, const uint32_t* b) {
    asm volatile(
        "mma.sync.aligned.m16n8k16.row.col.f32.f16.f16.f32 "
        "{%0,%1,%2,%3},{%4,%5,%6,%7},{%8,%9},{%0,%1,%2,%3};"
        : "+f"(d[0]), "+f"(d[1]), "+f"(d[2]), "+f"(d[3])
        : "r"(a[0]), "r"(a[1]), "r"(a[2]), "r"(a[3]), "r"(b[0]), "r"(b[1]));
}
// fp16-accumulate variant (2 packed half2 accumulators)
__device__ __forceinline__ void mma16816h(uint32_t* d, const uint32_t* a, const uint32_t* b) {
    asm volatile(
        "mma.sync.aligned.m16n8k16.row.col.f16.f16.f16.f16 "
        "{%0,%1},{%2,%3,%4,%5},{%6,%7},{%0,%1};"
        : "+r"(d[0]), "+r"(d[1])
        : "r"(a[0]), "r"(a[1]), "r"(a[2]), "r"(a[3]), "r"(b[0]), "r"(b[1]));
}
__device__ __forceinline__ void merge_corr(float* d, const uint32_t* e) {
    float2 f0 = __half22float2(*(const __half2*)&e[0]);
    float2 f1 = __half22float2(*(const __half2*)&e[1]);
    d[0] += f0.x; d[1] += f0.y; d[2] += f1.x; d[3] += f1.y;
}
__device__ __forceinline__ uint32_t pk2h(float a, float b) {
    __half2 h = __floats2half2_rn(a, b);
    return *reinterpret_cast<uint32_t*>(&h);
}
// store float pair as hi/lo half2
__device__ __forceinline__ void split_store(__half* hp, __half* lp, size_t off,
                                            float a, float b) {
    __half ha = __float2half_rn(a), hb = __float2half_rn(b);
    *(__half2*)&hp[off] = __halves2half2(ha, hb);
    *(__half2*)&lp[off] = __halves2half2(
        __float2half_rn(a - __half2float(ha)), __float2half_rn(b - __half2float(hb)));
}

// ---------------------------------------------------------------------------
// convert fp32 -> fp16 hi + fp16 lo (residual)
// ---------------------------------------------------------------------------
__global__ __launch_bounds__(256) void convert_split(
    const float* __restrict__ in, __half* __restrict__ hi,
    __half* __restrict__ lo, int n4)
{
    int i = blockIdx.x * 256 + threadIdx.x;
    if (i >= n4) return;
    float4 v = ((const float4*)in)[i];
    float hx = __half2float(__float2half_rn(v.x));
    float hy = __half2float(__float2half_rn(v.y));
    float hz = __half2float(__float2half_rn(v.z));
    float hw = __half2float(__float2half_rn(v.w));
    uint2 ph, pl;
    ph.x = pk2h(v.x, v.y); ph.y = pk2h(v.z, v.w);
    pl.x = pk2h(v.x - hx, v.y - hy); pl.y = pk2h(v.z - hz, v.w - hw);
    ((uint2*)hi)[i] = ph;
    ((uint2*)lo)[i] = pl;
}

// ---------------------------------------------------------------------------
// W [K, N] fp32 -> W^T [N, K] fp16 hi/lo
// ---------------------------------------------------------------------------
__global__ __launch_bounds__(256) void transpose_split(
    const float* __restrict__ W, __half* __restrict__ Th,
    __half* __restrict__ Tl, int K, int N)
{
    __shared__ float tile[32][33];
    int n0 = blockIdx.x * 32, k0 = blockIdx.y * 32;
    int tx = threadIdx.x, ty = threadIdx.y;   // 32 x 8
    #pragma unroll
    for (int j = ty; j < 32; j += 8)
        tile[j][tx] = W[(size_t)(k0 + j) * N + n0 + tx];
    __syncthreads();
    #pragma unroll
    for (int j = ty; j < 32; j += 8) {
        float v = tile[tx][j];
        __half h = __float2half_rn(v);
        float r = v - __half2float(h);
        size_t o = (size_t)(n0 + j) * K + k0 + tx;
        Th[o] = h;
        Tl[o] = __float2half_rn(r);
    }
}

__global__ __launch_bounds__(256) void bias_concat(
    const float* __restrict__ bq, const float* __restrict__ bk,
    const float* __restrict__ bv, float* __restrict__ o)
{
    int i = blockIdx.x * 256 + threadIdx.x;
    if (i < DIM) o[i] = bq[i];
    else if (i < DIM + KVD) o[i] = bk[i - DIM];
    else if (i < NQKV) o[i] = bv[i - DIM - KVD];
}

// ---------------------------------------------------------------------------
// shared GEMM tile config
// ---------------------------------------------------------------------------
#define BM 128
#define BN 128
#define BK 64
#define NCH (DIM / BK)   // 32
#define STG_BYTES 65536
#define OFF_AH 0
#define OFF_AL 16384
#define OFF_BH 32768
#define OFF_BL 49152
#define GEMM_SMEM (2 * STG_BYTES)   // 131072

// mainloop shared by both GEMM kernels; leaves merged accum in d.
// main product in fp32 accum; the two small correction products in a
// shared fp16 accumulator (2x issue rate), merged once at the end.
#define GEMM_MAINLOOP(Ahg, Alg, Bhg, Blg)                                          \
    auto load_stage = [&](int s, int kt) {                                         \
        int k0 = kt * BK;                                                          \
        uint32_t base = sb + s * STG_BYTES;                                        \
        _Pragma("unroll")                                                          \
        for (int t = 0; t < 4; t++) {                                              \
            int idx = tid + t * 256;                                               \
            int r = idx >> 3, c16 = idx & 7;                                       \
            uint32_t swz = SMEM_SWIZZLE_128B((uint32_t)(r * 128 + c16 * 16));      \
            size_t ga = (size_t)(by + r) * DIM + k0 + c16 * 8;                     \
            size_t gb = (size_t)(bx + r) * DIM + k0 + c16 * 8;                     \
            cp16(base + OFF_AH + swz, Ahg + ga);                                   \
            cp16(base + OFF_AL + swz, Alg + ga);                                   \
            cp16(base + OFF_BH + swz, Bhg + gb);                                   \
            cp16(base + OFF_BL + swz, Blg + gb);                                   \
        }                                                                          \
    };                                                                             \
    float d[4][4][4];                                                              \
    uint32_t e[4][4][2];                                                           \
    _Pragma("unroll")                                                              \
    for (int i = 0; i < 4; i++)                                                    \
        _Pragma("unroll")                                                          \
        for (int j = 0; j < 4; j++) {                                              \
            _Pragma("unroll")                                                      \
            for (int q = 0; q < 4; q++) d[i][j][q] = 0.f;                          \
            e[i][j][0] = 0u; e[i][j][1] = 0u;                                      \
        }                                                                          \
    load_stage(0, 0);                                                              \
    CP_COMMIT();                                                                   \
    load_stage(1, 1);                                                              \
    CP_COMMIT();                                                                   \
    for (int kt = 0; kt < NCH; kt++) {                                             \
        if (kt < NCH - 1) asm volatile("cp.async.wait_group 1;" ::: "memory");     \
        else              asm volatile("cp.async.wait_group 0;" ::: "memory");     \
        __syncthreads();                                                           \
        int s = kt & 1;                                                            \
        uint32_t base = sb + s * STG_BYTES;                                        \
        int arow = wm * 64 + (lane & 15);                                          \
        int bro  = wn * 32 + (lane & 7) + ((lane >> 4) << 3);                      \
        int bkh  = ((lane >> 3) & 1) << 3;                                         \
        _Pragma("unroll")                                                          \
        for (int ks = 0; ks < 4; ks++) {                                           \
            int acol = ks * 16 + ((lane >> 4) << 3);                               \
            uint32_t ah[4][4], al[4][4], bh[4][2], bl[4][2];                       \
            _Pragma("unroll")                                                      \
            for (int mf = 0; mf < 4; mf++) {                                       \
                uint32_t off = SMEM_SWIZZLE_128B(                                  \
                    (uint32_t)((arow + mf * 16) * 128 + acol * 2));                \
                ldm4(ah[mf], base + OFF_AH + off);                                 \
                ldm4(al[mf], base + OFF_AL + off);                                 \
            }                                                                      \
            _Pragma("unroll")                                                      \
            for (int j2 = 0; j2 < 2; j2++) {                                       \
                uint32_t off = SMEM_SWIZZLE_128B(                                  \
                    (uint32_t)((bro + j2 * 16) * 128 + (ks * 16 + bkh) * 2));      \
                uint32_t r[4];                                                     \
                ldm4(r, base + OFF_BH + off);                                      \
                bh[j2 * 2][0] = r[0]; bh[j2 * 2][1] = r[1];                        \
                bh[j2 * 2 + 1][0] = r[2]; bh[j2 * 2 + 1][1] = r[3];                \
                ldm4(r, base + OFF_BL + off);                                      \
                bl[j2 * 2][0] = r[0]; bl[j2 * 2][1] = r[1];                        \
                bl[j2 * 2 + 1][0] = r[2]; bl[j2 * 2 + 1][1] = r[3];                \
            }                                                                      \
            _Pragma("unroll")                                                      \
            for (int mf = 0; mf < 4; mf++)                                         \
                _Pragma("unroll")                                                  \
                for (int nf = 0; nf < 4; nf++) {                                   \
                    mma16816(d[mf][nf], ah[mf], bh[nf]);                           \
                    mma16816h(e[mf][nf], ah[mf], bl[nf]);                          \
                    mma16816h(e[mf][nf], al[mf], bh[nf]);                          \
                }                                                                  \
        }                                                                          \
        __syncthreads();                                                           \
        if (kt + 2 < NCH) {                                                        \
            load_stage(s, kt + 2);                                                 \
            CP_COMMIT();                                                           \
        }                                                                          \
    }                                                                              \
    _Pragma("unroll")                                                              \
    for (int mf = 0; mf < 4; mf++)                                                 \
        _Pragma("unroll")                                                          \
        for (int nf = 0; nf < 4; nf++)                                             \
            merge_corr(d[mf][nf], e[mf][nf]);

// ---------------------------------------------------------------------------
// Fused QKV GEMM + RMSNorm + RoPE + fp16 split epilogue.
// ---------------------------------------------------------------------------
__global__ __launch_bounds__(256, 1) void gemm_qkv(
    const __half* __restrict__ Ahg, const __half* __restrict__ Alg,
    const __half* __restrict__ Bhg, const __half* __restrict__ Blg,
    const float* __restrict__ bias,
    const float* __restrict__ qns, const float* __restrict__ kns,
    __half* __restrict__ qah, __half* __restrict__ qal,
    __half* __restrict__ kah, __half* __restrict__ kal,
    __half* __restrict__ vah, __half* __restrict__ val)
{
    extern __shared__ char sm[];
    uint32_t sb = smem_to_u32(sm);
    int tid = threadIdx.x, lane = tid & 31, wid = tid >> 5;
    int wm = wid & 1, wn = wid >> 1;
    int bx = blockIdx.x * BN, by = blockIdx.y * BM;

    GEMM_MAINLOOP(Ahg, Alg, Bhg, Blg)

    // ---------------- fused epilogue ----------------
    int hb = blockIdx.x;             // 0..23
    bool needs_norm = (hb < 20);     // q and k blocks

    int c0 = wn * 32 + (lane & 3) * 2;     // hd col base (even)
    #pragma unroll
    for (int mf = 0; mf < 4; mf++)
        #pragma unroll
        for (int nf = 0; nf < 4; nf++) {
            int c = c0 + nf * 8;
            float b0 = bias[bx + c], b1 = bias[bx + c + 1];
            d[mf][nf][0] += b0; d[mf][nf][1] += b1;
            d[mf][nf][2] += b0; d[mf][nf][3] += b1;
        }

    float* ss = (float*)sm;          // [128][4] partial row sums
    __syncthreads();                 // all warps done reading smem stages

    if (needs_norm) {
        #pragma unroll
        for (int mf = 0; mf < 4; mf++) {
            float pA = 0.f, pB = 0.f;
            #pragma unroll
            for (int nf = 0; nf < 4; nf++) {
                pA += d[mf][nf][0] * d[mf][nf][0] + d[mf][nf][1] * d[mf][nf][1];
                pB += d[mf][nf][2] * d[mf][nf][2] + d[mf][nf][3] * d[mf][nf][3];
            }
            pA += __shfl_xor_sync(0xffffffffu, pA, 1);
            pA += __shfl_xor_sync(0xffffffffu, pA, 2);
            pB += __shfl_xor_sync(0xffffffffu, pB, 1);
            pB += __shfl_xor_sync(0xffffffffu, pB, 2);
            if ((lane & 3) == 0) {
                int lr = wm * 64 + mf * 16 + (lane >> 2);
                ss[lr * 4 + wn] = pA;
                ss[(lr + 8) * 4 + wn] = pB;
            }
        }
    }
    __syncthreads();

    const float* nsc = (hb < 16) ? qns : kns;
    float esc = (hb < 16) ? (1.0f / (float)HD) : 1.0f;
    __half *oph, *opl;
    int headmul;
    if (hb < 16)      { oph = qah; opl = qal; headmul = NH; }
    else if (hb < 20) { oph = kah; opl = kal; headmul = NG; }
    else              { oph = vah; opl = val; headmul = NG; }
    int head = (hb < 16) ? hb : ((hb < 20) ? hb - 16 : hb - 20);

    #pragma unroll
    for (int mf = 0; mf < 4; mf++) {
        int lr = wm * 64 + mf * 16 + (lane >> 2);
        int rowA = by + lr, rowB = rowA + 8;
        int posA = rowA & (SEQ - 1), posB = rowB & (SEQ - 1);
        int bA = rowA >> 9, bB = rowB >> 9;
        float rinvA = 1.f, rinvB = 1.f;
        if (needs_norm) {
            float sA = ss[lr * 4] + ss[lr * 4 + 1] + ss[lr * 4 + 2] + ss[lr * 4 + 3];
            float sB = ss[(lr + 8) * 4] + ss[(lr + 8) * 4 + 1] +
                       ss[(lr + 8) * 4 + 2] + ss[(lr + 8) * 4 + 3];
            rinvA = rsqrtf(sA * (1.0f / HD) + 1e-6f);
            rinvB = rsqrtf(sB * (1.0f / HD) + 1e-6f);
        }
        size_t obA = ((size_t)(bA * headmul + head) * SEQ + posA) * HD;
        size_t obB = ((size_t)(bB * headmul + head) * SEQ + posB) * HD;
        #pragma unroll
        for (int nf = 0; nf < 4; nf++) {
            int c = c0 + nf * 8;
            float oA0, oA1, oB0, oB1;
            if (needs_norm) {
                float sc0 = nsc[c], sc1 = nsc[c + 1];
                float invf = expf(-(float)(c >> 1) * (9.210340371976184f / 64.0f));
                float snA, csA, snB, csB;
                sincosf((float)posA * invf, &snA, &csA);
                sincosf((float)posB * invf, &snB, &csB);
                float xA1 = d[mf][nf][0] * rinvA * sc0;
                float xA2 = d[mf][nf][1] * rinvA * sc1;
                float xB1 = d[mf][nf][2] * rinvB * sc0;
                float xB2 = d[mf][nf][3] * rinvB * sc1;
                oA0 = (xA1 * csA - xA2 * snA) * esc;
                oA1 = (xA1 * snA + xA2 * csA) * esc;
                oB0 = (xB1 * csB - xB2 * snB) * esc;
                oB1 = (xB1 * snB + xB2 * csB) * esc;
            } else {
                oA0 = d[mf][nf][0]; oA1 = d[mf][nf][1];
                oB0 = d[mf][nf][2]; oB1 = d[mf][nf][3];
            }
            split_store(oph, opl, obA + c, oA0, oA1);
            split_store(oph, opl, obB + c, oB0, oB1);
        }
    }
}

// ---------------------------------------------------------------------------
// plain HMMA split-3 GEMM with bias, fp32 output (for Wo)
// ---------------------------------------------------------------------------
__global__ __launch_bounds__(256, 1) void gemm_hmma(
    const __half* __restrict__ Ahg, const __half* __restrict__ Alg,
    const __half* __restrict__ Bhg, const __half* __restrict__ Blg,
    const float* __restrict__ bias, float* __restrict__ C, int N)
{
    extern __shared__ char sm[];
    uint32_t sb = smem_to_u32(sm);
    int tid = threadIdx.x, lane = tid & 31, wid = tid >> 5;
    int wm = wid & 1, wn = wid >> 1;
    int bx = blockIdx.x * BN, by = blockIdx.y * BM;

    GEMM_MAINLOOP(Ahg, Alg, Bhg, Blg)

    int row0 = by + wm * 64 + (lane >> 2);
    int col0 = bx + wn * 32 + (lane & 3) * 2;
    #pragma unroll
    for (int mf = 0; mf < 4; mf++)
        #pragma unroll
        for (int nf = 0; nf < 4; nf++) {
            int r = row0 + mf * 16;
            int c = col0 + nf * 8;
            float b0 = bias[c], b1 = bias[c + 1];
            float2 v0 = make_float2(d[mf][nf][0] + b0, d[mf][nf][1] + b1);
            float2 v1 = make_float2(d[mf][nf][2] + b0, d[mf][nf][3] + b1);
            *(float2*)&C[(size_t)r * N + c] = v0;
            *(float2*)&C[(size_t)(r + 8) * N + c] = v1;
        }
}

// ---------------------------------------------------------------------------
// HMMA flash attention (unchanged from round 4/5)
// ---------------------------------------------------------------------------
#define FA_SMEM (196608)

__global__ __launch_bounds__(256, 1) void flash_attn_hmma(
    const __half* __restrict__ qh, const __half* __restrict__ ql,
    const __half* __restrict__ kh, const __half* __restrict__ kl,
    const __half* __restrict__ vh, const __half* __restrict__ vl,
    __half* __restrict__ aoh, __half* __restrict__ aol)
{
    extern __shared__ char sm[];
    uint32_t sb = smem_to_u32(sm);
    int qb = (gridDim.x - 1) - blockIdx.x;
    int h = blockIdx.y, b = blockIdx.z;
    int g = h >> 2;
    int tid = threadIdx.x, lane = tid & 31, wid = tid >> 5;

    const size_t qbase  = ((size_t)(b * NH + h) * SEQ + qb * 128) * HD;
    const size_t kvbase = ((size_t)(b * NG + g) * SEQ) * HD;

    const uint32_t QH = sb, QL = sb + 32768;

    auto load_q = [&]() {
        #pragma unroll
        for (int t = 0; t < 8; t++) {
            int idx = tid + t * 256;
            int r = idx >> 4, c16 = idx & 15;
            uint32_t off = (uint32_t)((c16 >> 3) * 16384) +
                           SMEM_SWIZZLE_128B((uint32_t)(r * 128 + (c16 & 7) * 16));
            size_t go = qbase + (size_t)r * HD + c16 * 8;
            cp16(QH + off, qh + go);
            cp16(QL + off, ql + go);
        }
    };
    auto load_kv = [&](int s, int kt) {
        uint32_t base = sb + 65536 + s * 65536;
        size_t kb = kvbase + (size_t)kt * 64 * HD;
        #pragma unroll
        for (int t = 0; t < 4; t++) {
            int idx = tid + t * 256;
            int r = idx >> 4, c16 = idx & 15;
            uint32_t off = (uint32_t)((c16 >> 3) * 8192) +
                           SMEM_SWIZZLE_128B((uint32_t)(r * 128 + (c16 & 7) * 16));
            size_t go = kb + (size_t)r * HD + c16 * 8;
            cp16(base + off,         kh + go);
            cp16(base + 16384 + off, kl + go);
            cp16(base + 32768 + off, vh + go);
            cp16(base + 49152 + off, vl + go);
        }
    };

    int nkt = 2 * qb + 2;
    load_q();
    load_kv(0, 0);
    CP_COMMIT();
    load_kv(1, 1);
    CP_COMMIT();

    float o[16][4];
    #pragma unroll
    for (int i = 0; i < 16; i++)
        #pragma unroll
        for (int j = 0; j < 4; j++) o[i][j] = 0.f;
    float mA = -1e30f, mB = -1e30f, lA = 0.f, lB = 0.f;

    int row0 = wid * 16;
    int sq = qb * 128 + row0;

    for (int kt = 0; kt < nkt; kt++) {
        if (kt < nkt - 1) asm volatile("cp.async.wait_group 1;" ::: "memory");
        else              asm volatile("cp.async.wait_group 0;" ::: "memory");
        __syncthreads();

        int st = kt & 1;
        uint32_t KHb = sb + 65536 + st * 65536;
        uint32_t KLb = KHb + 16384, VHb = KHb + 32768, VLb = KHb + 49152;

        bool active = (kt * 64 <= sq + 15);
        if (active) {
            float sc[8][4];
            #pragma unroll
            for (int i = 0; i < 8; i++)
                #pragma unroll
                for (int j = 0; j < 4; j++) sc[i][j] = 0.f;

            int aro  = row0 + (lane & 15);
            int kro  = (lane & 7) + ((lane >> 4) << 3);
            int bkh  = ((lane >> 3) & 1) << 3;

            #pragma unroll
            for (int ks = 0; ks < 8; ks++) {
                int chk  = ks >> 2;
                int acol = (ks & 3) * 16 + ((lane >> 4) << 3);
                uint32_t aoff = (uint32_t)(chk * 16384) +
                                SMEM_SWIZZLE_128B((uint32_t)(aro * 128 + acol * 2));
                uint32_t ah[4], al[4];
                ldm4(ah, QH + aoff);
                ldm4(al, QL + aoff);

                int bcol = (ks & 3) * 16 + bkh;
                uint32_t bh[8][2], bl[8][2];
                #pragma unroll
                for (int j2 = 0; j2 < 4; j2++) {
                    uint32_t boff = (uint32_t)(chk * 8192) +
                        SMEM_SWIZZLE_128B((uint32_t)((j2 * 16 + kro) * 128 + bcol * 2));
                    uint32_t r[4];
                    ldm4(r, KHb + boff);
                    bh[2*j2][0] = r[0]; bh[2*j2][1] = r[1];
                    bh[2*j2+1][0] = r[2]; bh[2*j2+1][1] = r[3];
                    ldm4(r, KLb + boff);
                    bl[2*j2][0] = r[0]; bl[2*j2][1] = r[1];
                    bl[2*j2+1][0] = r[2]; bl[2*j2+1][1] = r[3];
                }
                #pragma unroll
                for (int nf = 0; nf < 8; nf++) {
                    mma16816(sc[nf], ah, bh[nf]);
                    mma16816(sc[nf], ah, bl[nf]);
                    mma16816(sc[nf], al, bh[nf]);
                }
            }

            if (kt * 64 + 63 > sq) {
                int rA = sq + (lane >> 2), rB = rA + 8;
                #pragma unroll
                for (int nf = 0; nf < 8; nf++) {
                    int cbase = kt * 64 + nf * 8 + 2 * (lane & 3);
                    if (cbase     > rA) sc[nf][0] = -1e30f;
                    if (cbase + 1 > rA) sc[nf][1] = -1e30f;
                    if (cbase     > rB) sc[nf][2] = -1e30f;
                    if (cbase + 1 > rB) sc[nf][3] = -1e30f;
                }
            }

            float mtA = -1e30f, mtB = -1e30f;
            #pragma unroll
            for (int nf = 0; nf < 8; nf++) {
                mtA = fmaxf(mtA, fmaxf(sc[nf][0], sc[nf][1]));
                mtB = fmaxf(mtB, fmaxf(sc[nf][2], sc[nf][3]));
            }
            mtA = fmaxf(mtA, __shfl_xor_sync(0xffffffffu, mtA, 1));
            mtA = fmaxf(mtA, __shfl_xor_sync(0xffffffffu, mtA, 2));
            mtB = fmaxf(mtB, __shfl_xor_sync(0xffffffffu, mtB, 1));
            mtB = fmaxf(mtB, __shfl_xor_sync(0xffffffffu, mtB, 2));
            float nmA = fmaxf(mA, mtA), nmB = fmaxf(mB, mtB);
            float alA = __expf(mA - nmA), alB = __expf(mB - nmB);

            float suA = 0.f, suB = 0.f;
            #pragma unroll
            for (int nf = 0; nf < 8; nf++) {
                sc[nf][0] = __expf(sc[nf][0] - nmA); suA += sc[nf][0];
                sc[nf][1] = __expf(sc[nf][1] - nmA); suA += sc[nf][1];
                sc[nf][2] = __expf(sc[nf][2] - nmB); suB += sc[nf][2];
                sc[nf][3] = __expf(sc[nf][3] - nmB); suB += sc[nf][3];
            }
            suA += __shfl_xor_sync(0xffffffffu, suA, 1);
            suA += __shfl_xor_sync(0xffffffffu, suA, 2);
            suB += __shfl_xor_sync(0xffffffffu, suB, 1);
            suB += __shfl_xor_sync(0xffffffffu, suB, 2);
            lA = lA * alA + suA;
            lB = lB * alB + suB;
            mA = nmA; mB = nmB;
            #pragma unroll
            for (int nf = 0; nf < 16; nf++) {
                o[nf][0] *= alA; o[nf][1] *= alA;
                o[nf][2] *= alB; o[nf][3] *= alB;
            }

            int vro = (lane & 7) + (((lane >> 3) & 1) << 3);
            int vch = (lane >> 4) << 3;
            #pragma unroll
            for (int kf = 0; kf < 4; kf++) {
                uint32_t aPh[4], aPl[4];
                {
                    float p0 = sc[2*kf][0],   p1 = sc[2*kf][1];
                    float p2 = sc[2*kf][2],   p3 = sc[2*kf][3];
                    float p4 = sc[2*kf+1][0], p5 = sc[2*kf+1][1];
                    float p6 = sc[2*kf+1][2], p7 = sc[2*kf+1][3];
                    __half h0 = __float2half_rn(p0), h1 = __float2half_rn(p1);
                    __half h2 = __float2half_rn(p2), h3 = __float2half_rn(p3);
                    __half h4 = __float2half_rn(p4), h5 = __float2half_rn(p5);
                    __half h6 = __float2half_rn(p6), h7 = __float2half_rn(p7);
                    aPh[0] = pk2h(p0, p1); aPh[1] = pk2h(p2, p3);
                    aPh[2] = pk2h(p4, p5); aPh[3] = pk2h(p6, p7);
                    aPl[0] = pk2h(p0 - __half2float(h0), p1 - __half2float(h1));
                    aPl[1] = pk2h(p2 - __half2float(h2), p3 - __half2float(h3));
                    aPl[2] = pk2h(p4 - __half2float(h4), p5 - __half2float(h5));
                    aPl[3] = pk2h(p6 - __half2float(h6), p7 - __half2float(h7));
                }
                #pragma unroll
                for (int j2 = 0; j2 < 8; j2++) {
                    int chk  = j2 >> 2;
                    int wcol = (j2 & 3) * 16 + vch;
                    uint32_t voff = (uint32_t)(chk * 8192) +
                        SMEM_SWIZZLE_128B((uint32_t)((kf * 16 + vro) * 128 + wcol * 2));
                    uint32_t rh[4], rl[4];
                    ldm4t(rh, VHb + voff);
                    ldm4t(rl, VLb + voff);
                    uint32_t bh0[2] = {rh[0], rh[1]}, bh1[2] = {rh[2], rh[3]};
                    uint32_t bl0[2] = {rl[0], rl[1]}, bl1[2] = {rl[2], rl[3]};
                    mma16816(o[2*j2],   aPh, bh0);
                    mma16816(o[2*j2],   aPh, bl0);
                    mma16816(o[2*j2],   aPl, bh0);
                    mma16816(o[2*j2+1], aPh, bh1);
                    mma16816(o[2*j2+1], aPh, bl1);
                    mma16816(o[2*j2+1], aPl, bh1);
                }
            }
        }
        __syncthreads();

        if (kt + 2 < nkt) {
            load_kv(st, kt + 2);
            CP_COMMIT();
        }
    }

    float rlA = 1.0f / lA, rlB = 1.0f / lB;
    int sA = sq + (lane >> 2), sB = sA + 8;
    size_t oA = ((size_t)(b * SEQ + sA) * NH + h) * HD;
    size_t oB = ((size_t)(b * SEQ + sB) * NH + h) * HD;
    #pragma unroll
    for (int nf = 0; nf < 16; nf++) {
        int hd = nf * 8 + 2 * (lane & 3);
        float e0 = o[nf][0] * rlA, e1 = o[nf][1] * rlA;
        float e2 = o[nf][2] * rlB, e3 = o[nf][3] * rlB;
        split_store(aoh, aol, oA + hd, e0, e1);
        split_store(aoh, aol, oB + hd, e2, e3);
    }
}

// ---------------------------------------------------------------------------
extern "C" void kernel_launch(void* const* d_in, const int* in_sizes, int n_in,
                              void* d_out, int out_size)
{
    const float* x   = (const float*)d_in[0];
    const float* Wq  = (const float*)d_in[1];
    const float* bq  = (const float*)d_in[2];
    const float* Wk  = (const float*)d_in[3];
    const float* bk  = (const float*)d_in[4];
    const float* Wv  = (const float*)d_in[5];
    const float* bv  = (const float*)d_in[6];
    const float* Wo  = (const float*)d_in[7];
    const float* bo  = (const float*)d_in[8];
    const float* qns = (const float*)d_in[9];
    const float* kns = (const float*)d_in[10];
    float* out = (float*)d_out;

    __half *xhi, *xlo, *aoh, *aol, *wh, *wl, *woh, *wol;
    __half *qah, *qal, *kah, *kal, *vah, *val;
    float* bqkv;
    cudaGetSymbolAddress((void**)&xhi, g_xhi);
    cudaGetSymbolAddress((void**)&xlo, g_xlo);
    cudaGetSymbolAddress((void**)&aoh, g_aoh);
    cudaGetSymbolAddress((void**)&aol, g_aol);
    cudaGetSymbolAddress((void**)&wh,  g_wh);
    cudaGetSymbolAddress((void**)&wl,  g_wl);
    cudaGetSymbolAddress((void**)&woh, g_woh);
    cudaGetSymbolAddress((void**)&wol, g_wol);
    cudaGetSymbolAddress((void**)&bqkv, g_bqkv);
    cudaGetSymbolAddress((void**)&qah, g_qah);
    cudaGetSymbolAddress((void**)&qal, g_qal);
    cudaGetSymbolAddress((void**)&kah, g_kah);
    cudaGetSymbolAddress((void**)&kal, g_kal);
    cudaGetSymbolAddress((void**)&vah, g_vah);
    cudaGetSymbolAddress((void**)&val, g_val);

    cudaFuncSetAttribute(gemm_qkv, cudaFuncAttributeMaxDynamicSharedMemorySize, GEMM_SMEM);
    cudaFuncSetAttribute(gemm_hmma, cudaFuncAttributeMaxDynamicSharedMemorySize, GEMM_SMEM);
    cudaFuncSetAttribute(flash_attn_hmma, cudaFuncAttributeMaxDynamicSharedMemorySize, FA_SMEM);

    const int n4 = MROWS * DIM / 4;

    // conversions (weights concatenated into one [3072,2048] hi/lo buffer)
    convert_split<<<(n4 + 255) / 256, 256>>>(x, xhi, xlo, n4);
    transpose_split<<<dim3(DIM / 32, DIM / 32), dim3(32, 8)>>>(Wq, wh, wl, DIM, DIM);
    transpose_split<<<dim3(KVD / 32, DIM / 32), dim3(32, 8)>>>(
        Wk, wh + (size_t)DIM * DIM, wl + (size_t)DIM * DIM, DIM, KVD);
    transpose_split<<<dim3(KVD / 32, DIM / 32), dim3(32, 8)>>>(
        Wv, wh + (size_t)(DIM + KVD) * DIM, wl + (size_t)(DIM + KVD) * DIM, DIM, KVD);
    transpose_split<<<dim3(DIM / 32, DIM / 32), dim3(32, 8)>>>(Wo, woh, wol, DIM, DIM);
    bias_concat<<<(NQKV + 255) / 256, 256>>>(bq, bk, bv, bqkv);

    // fused QKV projection + rmsnorm + rope + split (q carries full 1/hd)
    gemm_qkv<<<dim3(NQKV / BN, MROWS / BM), 256, GEMM_SMEM>>>(
        xhi, xlo, wh, wl, bqkv, qns, kns,
        qah, qal, kah, kal, vah, val);

    // attention (HMMA)
    flash_attn_hmma<<<dim3(SEQ / 128, NH, BATCH), 256, FA_SMEM>>>(
        qah, qal, kah, kal, vah, val, aoh, aol);

    // output projection
    gemm_hmma<<<dim3(DIM / BN, MROWS / BM), 256, GEMM_SMEM>>>(
        aoh, aol, woh, wol, bo, out, DIM);
}

// round 7
// speedup vs baseline: 1.0596x; 1.0596x over previous
#include <cuda_runtime.h>
#include <cuda_fp16.h>
#include <cstdint>
#include <math.h>

#define BATCH 16
#define SEQ   512
#define DIM   2048
#define NH    16
#define NG    4
#define HD    128
#define MROWS (BATCH*SEQ)   // 8192
#define KVD   (NG*HD)       // 512
#define NQKV  (DIM + 2*KVD) // 3072

// ---------------------------------------------------------------------------
// scratch (device globals — no allocation allowed)
// ---------------------------------------------------------------------------
__device__ __half g_xhi[(size_t)MROWS * DIM];
__device__ __half g_xlo[(size_t)MROWS * DIM];
__device__ __half g_aoh[(size_t)MROWS * DIM];   // attn out hi (b,s,H,hd)
__device__ __half g_aol[(size_t)MROWS * DIM];
__device__ __half g_wh[(size_t)NQKV * DIM];     // [Wq^T; Wk^T; Wv^T] fp16 hi
__device__ __half g_wl[(size_t)NQKV * DIM];
__device__ __half g_woh[(size_t)DIM * DIM];
__device__ __half g_wol[(size_t)DIM * DIM];
__device__ float  g_bqkv[NQKV];                 // [bq; bk; bv]

// attention operand buffers, (b, head, s, hd) layout
__device__ __half g_qah[(size_t)MROWS * DIM];   // q fp16 (hi only)
__device__ __half g_kah[(size_t)MROWS * KVD];   // k fp16 (hi only)
__device__ __half g_vah[(size_t)MROWS * KVD];   // v fp16 hi
__device__ __half g_val[(size_t)MROWS * KVD];   // v fp16 lo

// ---------------------------------------------------------------------------
// helpers
// ---------------------------------------------------------------------------
__device__ __forceinline__ uint32_t smem_to_u32(const void* p) {
    uint32_t a;
    asm("{ .reg .u64 t; cvta.to.shared.u64 t, %1; cvt.u32.u64 %0, t; }" : "=r"(a) : "l"(p));
    return a;
}
#define SMEM_SWIZZLE_128B(bo) ((bo) ^ (((bo) >> 3) & 0x70))

__device__ __forceinline__ void cp16(uint32_t s, const void* g) {
    asm volatile("cp.async.cg.shared.global [%0], [%1], 16;" :: "r"(s), "l"(g) : "memory");
}
#define CP_COMMIT() asm volatile("cp.async.commit_group;" ::: "memory")
__device__ __forceinline__ void ldm4(uint32_t* r, uint32_t a) {
    asm volatile("ldmatrix.sync.aligned.m8n8.x4.shared.b16 {%0,%1,%2,%3}, [%4];"
                 : "=r"(r[0]), "=r"(r[1]), "=r"(r[2]), "=r"(r[3]) : "r"(a));
}
__device__ __forceinline__ void ldm4t(uint32_t* r, uint32_t a) {
    asm volatile("ldmatrix.sync.aligned.m8n8.x4.trans.shared.b16 {%0,%1,%2,%3}, [%4];"
                 : "=r"(r[0]), "=r"(r[1]), "=r"(r[2]), "=r"(r[3]) : "r"(a));
}
__device__ __forceinline__ void mma16816(float* d, const uint32_t* a, const uint32_t* b) {
    asm volatile(
        "mma.sync.aligned.m16n8k16.row.col.f32.f16.f16.f32 "
        "{%0,%1,%2,%3},{%4,%5,%6,%7},{%8,%9},{%0,%1,%2,%3};"
        : "+f"(d[0]), "+f"(d[1]), "+f"(d[2]), "+f"(d[3])
        : "r"(a[0]), "r"(a[1]), "r"(a[2]), "r"(a[3]), "r"(b[0]), "r"(b[1]));
}
__device__ __forceinline__ uint32_t pk2h(float a, float b) {
    __half2 h = __floats2half2_rn(a, b);
    return *reinterpret_cast<uint32_t*>(&h);
}
// store float pair as hi/lo half2
__device__ __forceinline__ void split_store(__half* hp, __half* lp, size_t off,
                                            float a, float b) {
    __half ha = __float2half_rn(a), hb = __float2half_rn(b);
    *(__half2*)&hp[off] = __halves2half2(ha, hb);
    *(__half2*)&lp[off] = __halves2half2(
        __float2half_rn(a - __half2float(ha)), __float2half_rn(b - __half2float(hb)));
}

// ---------------------------------------------------------------------------
// convert fp32 -> fp16 hi + fp16 lo (residual)
// ---------------------------------------------------------------------------
__global__ __launch_bounds__(256) void convert_split(
    const float* __restrict__ in, __half* __restrict__ hi,
    __half* __restrict__ lo, int n4)
{
    int i = blockIdx.x * 256 + threadIdx.x;
    if (i >= n4) return;
    float4 v = ((const float4*)in)[i];
    float hx = __half2float(__float2half_rn(v.x));
    float hy = __half2float(__float2half_rn(v.y));
    float hz = __half2float(__float2half_rn(v.z));
    float hw = __half2float(__float2half_rn(v.w));
    uint2 ph, pl;
    ph.x = pk2h(v.x, v.y); ph.y = pk2h(v.z, v.w);
    pl.x = pk2h(v.x - hx, v.y - hy); pl.y = pk2h(v.z - hz, v.w - hw);
    ((uint2*)hi)[i] = ph;
    ((uint2*)lo)[i] = pl;
}

// ---------------------------------------------------------------------------
// W [K, N] fp32 -> W^T [N, K] fp16 hi/lo
// ---------------------------------------------------------------------------
__global__ __launch_bounds__(256) void transpose_split(
    const float* __restrict__ W, __half* __restrict__ Th,
    __half* __restrict__ Tl, int K, int N)
{
    __shared__ float tile[32][33];
    int n0 = blockIdx.x * 32, k0 = blockIdx.y * 32;
    int tx = threadIdx.x, ty = threadIdx.y;   // 32 x 8
    #pragma unroll
    for (int j = ty; j < 32; j += 8)
        tile[j][tx] = W[(size_t)(k0 + j) * N + n0 + tx];
    __syncthreads();
    #pragma unroll
    for (int j = ty; j < 32; j += 8) {
        float v = tile[tx][j];
        __half h = __float2half_rn(v);
        float r = v - __half2float(h);
        size_t o = (size_t)(n0 + j) * K + k0 + tx;
        Th[o] = h;
        Tl[o] = __float2half_rn(r);
    }
}

__global__ __launch_bounds__(256) void bias_concat(
    const float* __restrict__ bq, const float* __restrict__ bk,
    const float* __restrict__ bv, float* __restrict__ o)
{
    int i = blockIdx.x * 256 + threadIdx.x;
    if (i < DIM) o[i] = bq[i];
    else if (i < DIM + KVD) o[i] = bk[i - DIM];
    else if (i < NQKV) o[i] = bv[i - DIM - KVD];
}

// ---------------------------------------------------------------------------
// shared GEMM tile config
// ---------------------------------------------------------------------------
#define BM 128
#define BN 128
#define BK 64
#define NCH (DIM / BK)   // 32
#define STG_BYTES 65536
#define OFF_AH 0
#define OFF_AL 16384
#define OFF_BH 32768
#define OFF_BL 49152
#define GEMM_SMEM (2 * STG_BYTES)   // 131072

// ---------------------------------------------------------------------------
// Fused QKV GEMM + RMSNorm + RoPE epilogue.
// q,k column blocks (hb<20): single-product fp16 GEMM (precision analysis:
// q/k errors are attenuated ~11x by the logit scale before softmax).
// v blocks (hb>=20): full split-3 (v error hits the output 1:1).
// ---------------------------------------------------------------------------
__global__ __launch_bounds__(256, 1) void gemm_qkv(
    const __half* __restrict__ Ahg, const __half* __restrict__ Alg,
    const __half* __restrict__ Bhg, const __half* __restrict__ Blg,
    const float* __restrict__ bias,
    const float* __restrict__ qns, const float* __restrict__ kns,
    __half* __restrict__ qah, __half* __restrict__ kah,
    __half* __restrict__ vah, __half* __restrict__ val)
{
    extern __shared__ char sm[];
    uint32_t sb = smem_to_u32(sm);
    int tid = threadIdx.x, lane = tid & 31, wid = tid >> 5;
    int wm = wid & 1, wn = wid >> 1;
    int bx = blockIdx.x * BN, by = blockIdx.y * BM;
    const bool full = (blockIdx.x >= 20);   // v blocks

    auto load_stage = [&](int s, int kt) {
        int k0 = kt * BK;
        uint32_t base = sb + s * STG_BYTES;
        #pragma unroll
        for (int t = 0; t < 4; t++) {
            int idx = tid + t * 256;
            int r = idx >> 3, c16 = idx & 7;
            uint32_t swz = SMEM_SWIZZLE_128B((uint32_t)(r * 128 + c16 * 16));
            size_t ga = (size_t)(by + r) * DIM + k0 + c16 * 8;
            size_t gb = (size_t)(bx + r) * DIM + k0 + c16 * 8;
            cp16(base + OFF_AH + swz, Ahg + ga);
            cp16(base + OFF_BH + swz, Bhg + gb);
            if (full) {
                cp16(base + OFF_AL + swz, Alg + ga);
                cp16(base + OFF_BL + swz, Blg + gb);
            }
        }
    };

    float d[4][4][4];
    #pragma unroll
    for (int i = 0; i < 4; i++)
        #pragma unroll
        for (int j = 0; j < 4; j++)
            #pragma unroll
            for (int q = 0; q < 4; q++) d[i][j][q] = 0.f;

    load_stage(0, 0);
    CP_COMMIT();
    load_stage(1, 1);
    CP_COMMIT();

    for (int kt = 0; kt < NCH; kt++) {
        if (kt < NCH - 1) asm volatile("cp.async.wait_group 1;" ::: "memory");
        else              asm volatile("cp.async.wait_group 0;" ::: "memory");
        __syncthreads();

        int s = kt & 1;
        uint32_t base = sb + s * STG_BYTES;
        int arow = wm * 64 + (lane & 15);
        int bro  = wn * 32 + (lane & 7) + ((lane >> 4) << 3);
        int bkh  = ((lane >> 3) & 1) << 3;

        #pragma unroll
        for (int ks = 0; ks < 4; ks++) {
            int acol = ks * 16 + ((lane >> 4) << 3);
            uint32_t ah[4][4], al[4][4], bh[4][2], bl[4][2];
            #pragma unroll
            for (int mf = 0; mf < 4; mf++) {
                uint32_t off = SMEM_SWIZZLE_128B(
                    (uint32_t)((arow + mf * 16) * 128 + acol * 2));
                ldm4(ah[mf], base + OFF_AH + off);
                if (full) ldm4(al[mf], base + OFF_AL + off);
            }
            #pragma unroll
            for (int j2 = 0; j2 < 2; j2++) {
                uint32_t off = SMEM_SWIZZLE_128B(
                    (uint32_t)((bro + j2 * 16) * 128 + (ks * 16 + bkh) * 2));
                uint32_t r[4];
                ldm4(r, base + OFF_BH + off);
                bh[j2 * 2][0] = r[0]; bh[j2 * 2][1] = r[1];
                bh[j2 * 2 + 1][0] = r[2]; bh[j2 * 2 + 1][1] = r[3];
                if (full) {
                    ldm4(r, base + OFF_BL + off);
                    bl[j2 * 2][0] = r[0]; bl[j2 * 2][1] = r[1];
                    bl[j2 * 2 + 1][0] = r[2]; bl[j2 * 2 + 1][1] = r[3];
                }
            }
            #pragma unroll
            for (int mf = 0; mf < 4; mf++)
                #pragma unroll
                for (int nf = 0; nf < 4; nf++) {
                    mma16816(d[mf][nf], ah[mf], bh[nf]);
                    if (full) {
                        mma16816(d[mf][nf], ah[mf], bl[nf]);
                        mma16816(d[mf][nf], al[mf], bh[nf]);
                    }
                }
        }
        __syncthreads();

        if (kt + 2 < NCH) {
            load_stage(s, kt + 2);
            CP_COMMIT();
        }
    }

    // ---------------- fused epilogue ----------------
    int hb = blockIdx.x;             // 0..23
    bool needs_norm = (hb < 20);     // q and k blocks

    int c0 = wn * 32 + (lane & 3) * 2;     // hd col base (even)
    #pragma unroll
    for (int mf = 0; mf < 4; mf++)
        #pragma unroll
        for (int nf = 0; nf < 4; nf++) {
            int c = c0 + nf * 8;
            float b0 = bias[bx + c], b1 = bias[bx + c + 1];
            d[mf][nf][0] += b0; d[mf][nf][1] += b1;
            d[mf][nf][2] += b0; d[mf][nf][3] += b1;
        }

    float* ss = (float*)sm;          // [128][4] partial row sums
    __syncthreads();                 // all warps done reading smem stages

    if (needs_norm) {
        #pragma unroll
        for (int mf = 0; mf < 4; mf++) {
            float pA = 0.f, pB = 0.f;
            #pragma unroll
            for (int nf = 0; nf < 4; nf++) {
                pA += d[mf][nf][0] * d[mf][nf][0] + d[mf][nf][1] * d[mf][nf][1];
                pB += d[mf][nf][2] * d[mf][nf][2] + d[mf][nf][3] * d[mf][nf][3];
            }
            pA += __shfl_xor_sync(0xffffffffu, pA, 1);
            pA += __shfl_xor_sync(0xffffffffu, pA, 2);
            pB += __shfl_xor_sync(0xffffffffu, pB, 1);
            pB += __shfl_xor_sync(0xffffffffu, pB, 2);
            if ((lane & 3) == 0) {
                int lr = wm * 64 + mf * 16 + (lane >> 2);
                ss[lr * 4 + wn] = pA;
                ss[(lr + 8) * 4 + wn] = pB;
            }
        }
    }
    __syncthreads();

    const float* nsc = (hb < 16) ? qns : kns;
    float esc = (hb < 16) ? (1.0f / (float)HD) : 1.0f;
    __half* oph;
    int headmul;
    if (hb < 16)      { oph = qah; headmul = NH; }
    else if (hb < 20) { oph = kah; headmul = NG; }
    else              { oph = vah; headmul = NG; }
    int head = (hb < 16) ? hb : ((hb < 20) ? hb - 16 : hb - 20);

    #pragma unroll
    for (int mf = 0; mf < 4; mf++) {
        int lr = wm * 64 + mf * 16 + (lane >> 2);
        int rowA = by + lr, rowB = rowA + 8;
        int posA = rowA & (SEQ - 1), posB = rowB & (SEQ - 1);
        int bA = rowA >> 9, bB = rowB >> 9;
        float rinvA = 1.f, rinvB = 1.f;
        if (needs_norm) {
            float sA = ss[lr * 4] + ss[lr * 4 + 1] + ss[lr * 4 + 2] + ss[lr * 4 + 3];
            float sB = ss[(lr + 8) * 4] + ss[(lr + 8) * 4 + 1] +
                       ss[(lr + 8) * 4 + 2] + ss[(lr + 8) * 4 + 3];
            rinvA = rsqrtf(sA * (1.0f / HD) + 1e-6f);
            rinvB = rsqrtf(sB * (1.0f / HD) + 1e-6f);
        }
        size_t obA = ((size_t)(bA * headmul + head) * SEQ + posA) * HD;
        size_t obB = ((size_t)(bB * headmul + head) * SEQ + posB) * HD;
        #pragma unroll
        for (int nf = 0; nf < 4; nf++) {
            int c = c0 + nf * 8;
            if (needs_norm) {
                float sc0 = nsc[c], sc1 = nsc[c + 1];
                float invf = expf(-(float)(c >> 1) * (9.210340371976184f / 64.0f));
                float snA, csA, snB, csB;
                sincosf((float)posA * invf, &snA, &csA);
                sincosf((float)posB * invf, &snB, &csB);
                float xA1 = d[mf][nf][0] * rinvA * sc0;
                float xA2 = d[mf][nf][1] * rinvA * sc1;
                float xB1 = d[mf][nf][2] * rinvB * sc0;
                float xB2 = d[mf][nf][3] * rinvB * sc1;
                *(__half2*)&oph[obA + c] = __floats2half2_rn(
                    (xA1 * csA - xA2 * snA) * esc, (xA1 * snA + xA2 * csA) * esc);
                *(__half2*)&oph[obB + c] = __floats2half2_rn(
                    (xB1 * csB - xB2 * snB) * esc, (xB1 * snB + xB2 * csB) * esc);
            } else {
                split_store(vah, val, obA + c, d[mf][nf][0], d[mf][nf][1]);
                split_store(vah, val, obB + c, d[mf][nf][2], d[mf][nf][3]);
            }
        }
    }
}

// ---------------------------------------------------------------------------
// plain HMMA split-3 GEMM with bias, fp32 output (for Wo) — round-5 proven
// ---------------------------------------------------------------------------
__global__ __launch_bounds__(256, 1) void gemm_hmma(
    const __half* __restrict__ Ahg, const __half* __restrict__ Alg,
    const __half* __restrict__ Bhg, const __half* __restrict__ Blg,
    const float* __restrict__ bias, float* __restrict__ C, int N)
{
    extern __shared__ char sm[];
    uint32_t sb = smem_to_u32(sm);
    int tid = threadIdx.x, lane = tid & 31, wid = tid >> 5;
    int wm = wid & 1, wn = wid >> 1;
    int bx = blockIdx.x * BN, by = blockIdx.y * BM;

    auto load_stage = [&](int s, int kt) {
        int k0 = kt * BK;
        uint32_t base = sb + s * STG_BYTES;
        #pragma unroll
        for (int t = 0; t < 4; t++) {
            int idx = tid + t * 256;
            int r = idx >> 3, c16 = idx & 7;
            uint32_t swz = SMEM_SWIZZLE_128B((uint32_t)(r * 128 + c16 * 16));
            size_t ga = (size_t)(by + r) * DIM + k0 + c16 * 8;
            size_t gb = (size_t)(bx + r) * DIM + k0 + c16 * 8;
            cp16(base + OFF_AH + swz, Ahg + ga);
            cp16(base + OFF_AL + swz, Alg + ga);
            cp16(base + OFF_BH + swz, Bhg + gb);
            cp16(base + OFF_BL + swz, Blg + gb);
        }
    };

    float d[4][4][4];
    #pragma unroll
    for (int i = 0; i < 4; i++)
        #pragma unroll
        for (int j = 0; j < 4; j++)
            #pragma unroll
            for (int q = 0; q < 4; q++) d[i][j][q] = 0.f;

    load_stage(0, 0);
    CP_COMMIT();
    load_stage(1, 1);
    CP_COMMIT();

    for (int kt = 0; kt < NCH; kt++) {
        if (kt < NCH - 1) asm volatile("cp.async.wait_group 1;" ::: "memory");
        else              asm volatile("cp.async.wait_group 0;" ::: "memory");
        __syncthreads();

        int s = kt & 1;
        uint32_t base = sb + s * STG_BYTES;
        int arow = wm * 64 + (lane & 15);
        int bro  = wn * 32 + (lane & 7) + ((lane >> 4) << 3);
        int bkh  = ((lane >> 3) & 1) << 3;

        #pragma unroll
        for (int ks = 0; ks < 4; ks++) {
            int acol = ks * 16 + ((lane >> 4) << 3);
            uint32_t ah[4][4], al[4][4], bh[4][2], bl[4][2];
            #pragma unroll
            for (int mf = 0; mf < 4; mf++) {
                uint32_t off = SMEM_SWIZZLE_128B(
                    (uint32_t)((arow + mf * 16) * 128 + acol * 2));
                ldm4(ah[mf], base + OFF_AH + off);
                ldm4(al[mf], base + OFF_AL + off);
            }
            #pragma unroll
            for (int j2 = 0; j2 < 2; j2++) {
                uint32_t off = SMEM_SWIZZLE_128B(
                    (uint32_t)((bro + j2 * 16) * 128 + (ks * 16 + bkh) * 2));
                uint32_t r[4];
                ldm4(r, base + OFF_BH + off);
                bh[j2 * 2][0] = r[0]; bh[j2 * 2][1] = r[1];
                bh[j2 * 2 + 1][0] = r[2]; bh[j2 * 2 + 1][1] = r[3];
                ldm4(r, base + OFF_BL + off);
                bl[j2 * 2][0] = r[0]; bl[j2 * 2][1] = r[1];
                bl[j2 * 2 + 1][0] = r[2]; bl[j2 * 2 + 1][1] = r[3];
            }
            #pragma unroll
            for (int mf = 0; mf < 4; mf++)
                #pragma unroll
                for (int nf = 0; nf < 4; nf++) {
                    mma16816(d[mf][nf], ah[mf], bh[nf]);
                    mma16816(d[mf][nf], ah[mf], bl[nf]);
                    mma16816(d[mf][nf], al[mf], bh[nf]);
                }
        }
        __syncthreads();

        if (kt + 2 < NCH) {
            load_stage(s, kt + 2);
            CP_COMMIT();
        }
    }

    int row0 = by + wm * 64 + (lane >> 2);
    int col0 = bx + wn * 32 + (lane & 3) * 2;
    #pragma unroll
    for (int mf = 0; mf < 4; mf++)
        #pragma unroll
        for (int nf = 0; nf < 4; nf++) {
            int r = row0 + mf * 16;
            int c = col0 + nf * 8;
            float b0 = bias[c], b1 = bias[c + 1];
            float2 v0 = make_float2(d[mf][nf][0] + b0, d[mf][nf][1] + b1);
            float2 v1 = make_float2(d[mf][nf][2] + b0, d[mf][nf][3] + b1);
            *(float2*)&C[(size_t)r * N + c] = v0;
            *(float2*)&C[(size_t)(r + 8) * N + c] = v1;
        }
}

// ---------------------------------------------------------------------------
// HMMA flash attention. Q/K fp16 hi-only (S single-product); P·V split-3.
// smem: Q 32KB + 2-stage (K 16K + Vh 16K + Vl 16K) = 128KB
// ---------------------------------------------------------------------------
#define FA_STG 49152
#define FA_SMEM (32768 + 2 * FA_STG)   // 131072

__global__ __launch_bounds__(256, 1) void flash_attn_hmma(
    const __half* __restrict__ qh, const __half* __restrict__ kh,
    const __half* __restrict__ vh, const __half* __restrict__ vl,
    __half* __restrict__ aoh, __half* __restrict__ aol)
{
    extern __shared__ char sm[];
    uint32_t sb = smem_to_u32(sm);
    int qb = (gridDim.x - 1) - blockIdx.x;
    int h = blockIdx.y, b = blockIdx.z;
    int g = h >> 2;
    int tid = threadIdx.x, lane = tid & 31, wid = tid >> 5;

    const size_t qbase  = ((size_t)(b * NH + h) * SEQ + qb * 128) * HD;
    const size_t kvbase = ((size_t)(b * NG + g) * SEQ) * HD;

    const uint32_t QH = sb;

    auto load_q = [&]() {
        #pragma unroll
        for (int t = 0; t < 8; t++) {
            int idx = tid + t * 256;
            int r = idx >> 4, c16 = idx & 15;
            uint32_t off = (uint32_t)((c16 >> 3) * 16384) +
                           SMEM_SWIZZLE_128B((uint32_t)(r * 128 + (c16 & 7) * 16));
            cp16(QH + off, qh + qbase + (size_t)r * HD + c16 * 8);
        }
    };
    auto load_kv = [&](int s, int kt) {
        uint32_t base = sb + 32768 + s * FA_STG;
        size_t kb = kvbase + (size_t)kt * 64 * HD;
        #pragma unroll
        for (int t = 0; t < 4; t++) {
            int idx = tid + t * 256;
            int r = idx >> 4, c16 = idx & 15;
            uint32_t off = (uint32_t)((c16 >> 3) * 8192) +
                           SMEM_SWIZZLE_128B((uint32_t)(r * 128 + (c16 & 7) * 16));
            size_t go = kb + (size_t)r * HD + c16 * 8;
            cp16(base + off,         kh + go);
            cp16(base + 16384 + off, vh + go);
            cp16(base + 32768 + off, vl + go);
        }
    };

    int nkt = 2 * qb + 2;
    load_q();
    load_kv(0, 0);
    CP_COMMIT();
    load_kv(1, 1);
    CP_COMMIT();

    float o[16][4];
    #pragma unroll
    for (int i = 0; i < 16; i++)
        #pragma unroll
        for (int j = 0; j < 4; j++) o[i][j] = 0.f;
    float mA = -1e30f, mB = -1e30f, lA = 0.f, lB = 0.f;

    int row0 = wid * 16;
    int sq = qb * 128 + row0;

    for (int kt = 0; kt < nkt; kt++) {
        if (kt < nkt - 1) asm volatile("cp.async.wait_group 1;" ::: "memory");
        else              asm volatile("cp.async.wait_group 0;" ::: "memory");
        __syncthreads();

        int st = kt & 1;
        uint32_t KHb = sb + 32768 + st * FA_STG;
        uint32_t VHb = KHb + 16384, VLb = KHb + 32768;

        bool active = (kt * 64 <= sq + 15);
        if (active) {
            float sc[8][4];
            #pragma unroll
            for (int i = 0; i < 8; i++)
                #pragma unroll
                for (int j = 0; j < 4; j++) sc[i][j] = 0.f;

            int aro  = row0 + (lane & 15);
            int kro  = (lane & 7) + ((lane >> 4) << 3);
            int bkh  = ((lane >> 3) & 1) << 3;

            // S = Qh Kh^T (single product)
            #pragma unroll
            for (int ks = 0; ks < 8; ks++) {
                int chk  = ks >> 2;
                int acol = (ks & 3) * 16 + ((lane >> 4) << 3);
                uint32_t aoff = (uint32_t)(chk * 16384) +
                                SMEM_SWIZZLE_128B((uint32_t)(aro * 128 + acol * 2));
                uint32_t ah[4];
                ldm4(ah, QH + aoff);

                int bcol = (ks & 3) * 16 + bkh;
                uint32_t bh[8][2];
                #pragma unroll
                for (int j2 = 0; j2 < 4; j2++) {
                    uint32_t boff = (uint32_t)(chk * 8192) +
                        SMEM_SWIZZLE_128B((uint32_t)((j2 * 16 + kro) * 128 + bcol * 2));
                    uint32_t r[4];
                    ldm4(r, KHb + boff);
                    bh[2*j2][0] = r[0]; bh[2*j2][1] = r[1];
                    bh[2*j2+1][0] = r[2]; bh[2*j2+1][1] = r[3];
                }
                #pragma unroll
                for (int nf = 0; nf < 8; nf++)
                    mma16816(sc[nf], ah, bh[nf]);
            }

            if (kt * 64 + 63 > sq) {
                int rA = sq + (lane >> 2), rB = rA + 8;
                #pragma unroll
                for (int nf = 0; nf < 8; nf++) {
                    int cbase = kt * 64 + nf * 8 + 2 * (lane & 3);
                    if (cbase     > rA) sc[nf][0] = -1e30f;
                    if (cbase + 1 > rA) sc[nf][1] = -1e30f;
                    if (cbase     > rB) sc[nf][2] = -1e30f;
                    if (cbase + 1 > rB) sc[nf][3] = -1e30f;
                }
            }

            float mtA = -1e30f, mtB = -1e30f;
            #pragma unroll
            for (int nf = 0; nf < 8; nf++) {
                mtA = fmaxf(mtA, fmaxf(sc[nf][0], sc[nf][1]));
                mtB = fmaxf(mtB, fmaxf(sc[nf][2], sc[nf][3]));
            }
            mtA = fmaxf(mtA, __shfl_xor_sync(0xffffffffu, mtA, 1));
            mtA = fmaxf(mtA, __shfl_xor_sync(0xffffffffu, mtA, 2));
            mtB = fmaxf(mtB, __shfl_xor_sync(0xffffffffu, mtB, 1));
            mtB = fmaxf(mtB, __shfl_xor_sync(0xffffffffu, mtB, 2));
            float nmA = fmaxf(mA, mtA), nmB = fmaxf(mB, mtB);
            float alA = __expf(mA - nmA), alB = __expf(mB - nmB);

            float suA = 0.f, suB = 0.f;
            #pragma unroll
            for (int nf = 0; nf < 8; nf++) {
                sc[nf][0] = __expf(sc[nf][0] - nmA); suA += sc[nf][0];
                sc[nf][1] = __expf(sc[nf][1] - nmA); suA += sc[nf][1];
                sc[nf][2] = __expf(sc[nf][2] - nmB); suB += sc[nf][2];
                sc[nf][3] = __expf(sc[nf][3] - nmB); suB += sc[nf][3];
            }
            suA += __shfl_xor_sync(0xffffffffu, suA, 1);
            suA += __shfl_xor_sync(0xffffffffu, suA, 2);
            suB += __shfl_xor_sync(0xffffffffu, suB, 1);
            suB += __shfl_xor_sync(0xffffffffu, suB, 2);
            lA = lA * alA + suA;
            lB = lB * alB + suB;
            mA = nmA; mB = nmB;
            #pragma unroll
            for (int nf = 0; nf < 16; nf++) {
                o[nf][0] *= alA; o[nf][1] *= alA;
                o[nf][2] *= alB; o[nf][3] *= alB;
            }

            int vro = (lane & 7) + (((lane >> 3) & 1) << 3);
            int vch = (lane >> 4) << 3;
            #pragma unroll
            for (int kf = 0; kf < 4; kf++) {
                uint32_t aPh[4], aPl[4];
                {
                    float p0 = sc[2*kf][0],   p1 = sc[2*kf][1];
                    float p2 = sc[2*kf][2],   p3 = sc[2*kf][3];
                    float p4 = sc[2*kf+1][0], p5 = sc[2*kf+1][1];
                    float p6 = sc[2*kf+1][2], p7 = sc[2*kf+1][3];
                    __half h0 = __float2half_rn(p0), h1 = __float2half_rn(p1);
                    __half h2 = __float2half_rn(p2), h3 = __float2half_rn(p3);
                    __half h4 = __float2half_rn(p4), h5 = __float2half_rn(p5);
                    __half h6 = __float2half_rn(p6), h7 = __float2half_rn(p7);
                    aPh[0] = pk2h(p0, p1); aPh[1] = pk2h(p2, p3);
                    aPh[2] = pk2h(p4, p5); aPh[3] = pk2h(p6, p7);
                    aPl[0] = pk2h(p0 - __half2float(h0), p1 - __half2float(h1));
                    aPl[1] = pk2h(p2 - __half2float(h2), p3 - __half2float(h3));
                    aPl[2] = pk2h(p4 - __half2float(h4), p5 - __half2float(h5));
                    aPl[3] = pk2h(p6 - __half2float(h6), p7 - __half2float(h7));
                }
                #pragma unroll
                for (int j2 = 0; j2 < 8; j2++) {
                    int chk  = j2 >> 2;
                    int wcol = (j2 & 3) * 16 + vch;
                    uint32_t voff = (uint32_t)(chk * 8192) +
                        SMEM_SWIZZLE_128B((uint32_t)((kf * 16 + vro) * 128 + wcol * 2));
                    uint32_t rh[4], rl[4];
                    ldm4t(rh, VHb + voff);
                    ldm4t(rl, VLb + voff);
                    uint32_t bh0[2] = {rh[0], rh[1]}, bh1[2] = {rh[2], rh[3]};
                    uint32_t bl0[2] = {rl[0], rl[1]}, bl1[2] = {rl[2], rl[3]};
                    mma16816(o[2*j2],   aPh, bh0);
                    mma16816(o[2*j2],   aPh, bl0);
                    mma16816(o[2*j2],   aPl, bh0);
                    mma16816(o[2*j2+1], aPh, bh1);
                    mma16816(o[2*j2+1], aPh, bl1);
                    mma16816(o[2*j2+1], aPl, bh1);
                }
            }
        }
        __syncthreads();

        if (kt + 2 < nkt) {
            load_kv(st, kt + 2);
            CP_COMMIT();
        }
    }

    float rlA = 1.0f / lA, rlB = 1.0f / lB;
    int sA = sq + (lane >> 2), sB = sA + 8;
    size_t oA = ((size_t)(b * SEQ + sA) * NH + h) * HD;
    size_t oB = ((size_t)(b * SEQ + sB) * NH + h) * HD;
    #pragma unroll
    for (int nf = 0; nf < 16; nf++) {
        int hd = nf * 8 + 2 * (lane & 3);
        float e0 = o[nf][0] * rlA, e1 = o[nf][1] * rlA;
        float e2 = o[nf][2] * rlB, e3 = o[nf][3] * rlB;
        split_store(aoh, aol, oA + hd, e0, e1);
        split_store(aoh, aol, oB + hd, e2, e3);
    }
}

// ---------------------------------------------------------------------------
extern "C" void kernel_launch(void* const* d_in, const int* in_sizes, int n_in,
                              void* d_out, int out_size)
{
    const float* x   = (const float*)d_in[0];
    const float* Wq  = (const float*)d_in[1];
    const float* bq  = (const float*)d_in[2];
    const float* Wk  = (const float*)d_in[3];
    const float* bk  = (const float*)d_in[4];
    const float* Wv  = (const float*)d_in[5];
    const float* bv  = (const float*)d_in[6];
    const float* Wo  = (const float*)d_in[7];
    const float* bo  = (const float*)d_in[8];
    const float* qns = (const float*)d_in[9];
    const float* kns = (const float*)d_in[10];
    float* out = (float*)d_out;

    __half *xhi, *xlo, *aoh, *aol, *wh, *wl, *woh, *wol;
    __half *qah, *kah, *vah, *val;
    float* bqkv;
    cudaGetSymbolAddress((void**)&xhi, g_xhi);
    cudaGetSymbolAddress((void**)&xlo, g_xlo);
    cudaGetSymbolAddress((void**)&aoh, g_aoh);
    cudaGetSymbolAddress((void**)&aol, g_aol);
    cudaGetSymbolAddress((void**)&wh,  g_wh);
    cudaGetSymbolAddress((void**)&wl,  g_wl);
    cudaGetSymbolAddress((void**)&woh, g_woh);
    cudaGetSymbolAddress((void**)&wol, g_wol);
    cudaGetSymbolAddress((void**)&bqkv, g_bqkv);
    cudaGetSymbolAddress((void**)&qah, g_qah);
    cudaGetSymbolAddress((void**)&kah, g_kah);
    cudaGetSymbolAddress((void**)&vah, g_vah);
    cudaGetSymbolAddress((void**)&val, g_val);

    cudaFuncSetAttribute(gemm_qkv, cudaFuncAttributeMaxDynamicSharedMemorySize, GEMM_SMEM);
    cudaFuncSetAttribute(gemm_hmma, cudaFuncAttributeMaxDynamicSharedMemorySize, GEMM_SMEM);
    cudaFuncSetAttribute(flash_attn_hmma, cudaFuncAttributeMaxDynamicSharedMemorySize, FA_SMEM);

    const int n4 = MROWS * DIM / 4;

    // conversions (weights concatenated into one [3072,2048] hi/lo buffer)
    convert_split<<<(n4 + 255) / 256, 256>>>(x, xhi, xlo, n4);
    transpose_split<<<dim3(DIM / 32, DIM / 32), dim3(32, 8)>>>(Wq, wh, wl, DIM, DIM);
    transpose_split<<<dim3(KVD / 32, DIM / 32), dim3(32, 8)>>>(
        Wk, wh + (size_t)DIM * DIM, wl + (size_t)DIM * DIM, DIM, KVD);
    transpose_split<<<dim3(KVD / 32, DIM / 32), dim3(32, 8)>>>(
        Wv, wh + (size_t)(DIM + KVD) * DIM, wl + (size_t)(DIM + KVD) * DIM, DIM, KVD);
    transpose_split<<<dim3(DIM / 32, DIM / 32), dim3(32, 8)>>>(Wo, woh, wol, DIM, DIM);
    bias_concat<<<(NQKV + 255) / 256, 256>>>(bq, bk, bv, bqkv);

    // fused QKV projection + rmsnorm + rope (q carries full 1/hd)
    gemm_qkv<<<dim3(NQKV / BN, MROWS / BM), 256, GEMM_SMEM>>>(
        xhi, xlo, wh, wl, bqkv, qns, kns,
        qah, kah, vah, val);

    // attention (HMMA)
    flash_attn_hmma<<<dim3(SEQ / 128, NH, BATCH), 256, FA_SMEM>>>(
        qah, kah, vah, val, aoh, aol);

    // output projection
    gemm_hmma<<<dim3(DIM / BN, MROWS / BM), 256, GEMM_SMEM>>>(
        aoh, aol, woh, wol, bo, out, DIM);
}

// round 8
// speedup vs baseline: 1.0843x; 1.0233x over previous
#include <cuda_runtime.h>
#include <cuda_fp16.h>
#include <cstdint>
#include <math.h>

#define BATCH 16
#define SEQ   512
#define DIM   2048
#define NH    16
#define NG    4
#define HD    128
#define MROWS (BATCH*SEQ)   // 8192
#define KVD   (NG*HD)       // 512
#define NQKV  (DIM + 2*KVD) // 3072

// ---------------------------------------------------------------------------
// scratch (device globals — no allocation allowed)
// ---------------------------------------------------------------------------
__device__ __half g_xhi[(size_t)MROWS * DIM];
__device__ __half g_xlo[(size_t)MROWS * DIM];
__device__ __half g_aoh[(size_t)MROWS * DIM];   // attn out hi (b,s,H,hd)
__device__ __half g_aol[(size_t)MROWS * DIM];
__device__ __half g_wh[(size_t)NQKV * DIM];     // [Wq^T; Wk^T; Wv^T] fp16 hi
__device__ __half g_wl[(size_t)NQKV * DIM];
__device__ __half g_woh[(size_t)DIM * DIM];
__device__ __half g_wol[(size_t)DIM * DIM];
__device__ float  g_bqkv[NQKV];                 // [bq; bk; bv]

// attention operand buffers, (b, head, s, hd) layout
__device__ __half g_qah[(size_t)MROWS * DIM];   // q fp16 (hi only)
__device__ __half g_kah[(size_t)MROWS * KVD];   // k fp16 (hi only)
__device__ __half g_vah[(size_t)MROWS * KVD];   // v fp16 hi
__device__ __half g_val[(size_t)MROWS * KVD];   // v fp16 lo

// ---------------------------------------------------------------------------
// helpers
// ---------------------------------------------------------------------------
__device__ __forceinline__ uint32_t smem_to_u32(const void* p) {
    uint32_t a;
    asm("{ .reg .u64 t; cvta.to.shared.u64 t, %1; cvt.u32.u64 %0, t; }" : "=r"(a) : "l"(p));
    return a;
}
#define SMEM_SWIZZLE_128B(bo) ((bo) ^ (((bo) >> 3) & 0x70))

__device__ __forceinline__ void cp16(uint32_t s, const void* g) {
    asm volatile("cp.async.cg.shared.global [%0], [%1], 16;" :: "r"(s), "l"(g) : "memory");
}
#define CP_COMMIT() asm volatile("cp.async.commit_group;" ::: "memory")
#define CP_WAIT2()  asm volatile("cp.async.wait_group 2;" ::: "memory")
__device__ __forceinline__ void ldm4(uint32_t* r, uint32_t a) {
    asm volatile("ldmatrix.sync.aligned.m8n8.x4.shared.b16 {%0,%1,%2,%3}, [%4];"
                 : "=r"(r[0]), "=r"(r[1]), "=r"(r[2]), "=r"(r[3]) : "r"(a));
}
__device__ __forceinline__ void ldm4t(uint32_t* r, uint32_t a) {
    asm volatile("ldmatrix.sync.aligned.m8n8.x4.trans.shared.b16 {%0,%1,%2,%3}, [%4];"
                 : "=r"(r[0]), "=r"(r[1]), "=r"(r[2]), "=r"(r[3]) : "r"(a));
}
__device__ __forceinline__ void mma16816(float* d, const uint32_t* a, const uint32_t* b) {
    asm volatile(
        "mma.sync.aligned.m16n8k16.row.col.f32.f16.f16.f32 "
        "{%0,%1,%2,%3},{%4,%5,%6,%7},{%8,%9},{%0,%1,%2,%3};"
        : "+f"(d[0]), "+f"(d[1]), "+f"(d[2]), "+f"(d[3])
        : "r"(a[0]), "r"(a[1]), "r"(a[2]), "r"(a[3]), "r"(b[0]), "r"(b[1]));
}
__device__ __forceinline__ uint32_t pk2h(float a, float b) {
    __half2 h = __floats2half2_rn(a, b);
    return *reinterpret_cast<uint32_t*>(&h);
}
// store float pair as hi/lo half2
__device__ __forceinline__ void split_store(__half* hp, __half* lp, size_t off,
                                            float a, float b) {
    __half ha = __float2half_rn(a), hb = __float2half_rn(b);
    *(__half2*)&hp[off] = __halves2half2(ha, hb);
    *(__half2*)&lp[off] = __halves2half2(
        __float2half_rn(a - __half2float(ha)), __float2half_rn(b - __half2float(hb)));
}

// ---------------------------------------------------------------------------
// convert fp32 -> fp16 hi + fp16 lo (residual)
// ---------------------------------------------------------------------------
__global__ __launch_bounds__(256) void convert_split(
    const float* __restrict__ in, __half* __restrict__ hi,
    __half* __restrict__ lo, int n4)
{
    int i = blockIdx.x * 256 + threadIdx.x;
    if (i >= n4) return;
    float4 v = ((const float4*)in)[i];
    float hx = __half2float(__float2half_rn(v.x));
    float hy = __half2float(__float2half_rn(v.y));
    float hz = __half2float(__float2half_rn(v.z));
    float hw = __half2float(__float2half_rn(v.w));
    uint2 ph, pl;
    ph.x = pk2h(v.x, v.y); ph.y = pk2h(v.z, v.w);
    pl.x = pk2h(v.x - hx, v.y - hy); pl.y = pk2h(v.z - hz, v.w - hw);
    ((uint2*)hi)[i] = ph;
    ((uint2*)lo)[i] = pl;
}

// ---------------------------------------------------------------------------
// W [K, N] fp32 -> W^T [N, K] fp16 hi/lo
// ---------------------------------------------------------------------------
__global__ __launch_bounds__(256) void transpose_split(
    const float* __restrict__ W, __half* __restrict__ Th,
    __half* __restrict__ Tl, int K, int N)
{
    __shared__ float tile[32][33];
    int n0 = blockIdx.x * 32, k0 = blockIdx.y * 32;
    int tx = threadIdx.x, ty = threadIdx.y;   // 32 x 8
    #pragma unroll
    for (int j = ty; j < 32; j += 8)
        tile[j][tx] = W[(size_t)(k0 + j) * N + n0 + tx];
    __syncthreads();
    #pragma unroll
    for (int j = ty; j < 32; j += 8) {
        float v = tile[tx][j];
        __half h = __float2half_rn(v);
        float r = v - __half2float(h);
        size_t o = (size_t)(n0 + j) * K + k0 + tx;
        Th[o] = h;
        Tl[o] = __float2half_rn(r);
    }
}

__global__ __launch_bounds__(256) void bias_concat(
    const float* __restrict__ bq, const float* __restrict__ bk,
    const float* __restrict__ bv, float* __restrict__ o)
{
    int i = blockIdx.x * 256 + threadIdx.x;
    if (i < DIM) o[i] = bq[i];
    else if (i < DIM + KVD) o[i] = bk[i - DIM];
    else if (i < NQKV) o[i] = bv[i - DIM - KVD];
}

// ---------------------------------------------------------------------------
// shared GEMM tile config — 3-stage cp.async pipeline
// ---------------------------------------------------------------------------
#define BM 128
#define BN 128
#define BK 64
#define NCH (DIM / BK)   // 32
#define STG_BYTES 65536
#define OFF_AH 0
#define OFF_AL 16384
#define OFF_BH 32768
#define OFF_BL 49152
#define GEMM_SMEM (3 * STG_BYTES)   // 196608

// ---------------------------------------------------------------------------
// Fused QKV GEMM + RMSNorm + RoPE epilogue.
// q,k column blocks (hb<20): single-product fp16 GEMM.
// v blocks (hb>=20): full split-3.
// ---------------------------------------------------------------------------
__global__ __launch_bounds__(256, 1) void gemm_qkv(
    const __half* __restrict__ Ahg, const __half* __restrict__ Alg,
    const __half* __restrict__ Bhg, const __half* __restrict__ Blg,
    const float* __restrict__ bias,
    const float* __restrict__ qns, const float* __restrict__ kns,
    __half* __restrict__ qah, __half* __restrict__ kah,
    __half* __restrict__ vah, __half* __restrict__ val)
{
    extern __shared__ char sm[];
    uint32_t sb = smem_to_u32(sm);
    int tid = threadIdx.x, lane = tid & 31, wid = tid >> 5;
    int wm = wid & 1, wn = wid >> 1;
    int bx = blockIdx.x * BN, by = blockIdx.y * BM;
    const bool full = (blockIdx.x >= 20);   // v blocks

    auto load_stage = [&](int s, int kt) {
        int k0 = kt * BK;
        uint32_t base = sb + s * STG_BYTES;
        #pragma unroll
        for (int t = 0; t < 4; t++) {
            int idx = tid + t * 256;
            int r = idx >> 3, c16 = idx & 7;
            uint32_t swz = SMEM_SWIZZLE_128B((uint32_t)(r * 128 + c16 * 16));
            size_t ga = (size_t)(by + r) * DIM + k0 + c16 * 8;
            size_t gb = (size_t)(bx + r) * DIM + k0 + c16 * 8;
            cp16(base + OFF_AH + swz, Ahg + ga);
            cp16(base + OFF_BH + swz, Bhg + gb);
            if (full) {
                cp16(base + OFF_AL + swz, Alg + ga);
                cp16(base + OFF_BL + swz, Blg + gb);
            }
        }
    };

    float d[4][4][4];
    #pragma unroll
    for (int i = 0; i < 4; i++)
        #pragma unroll
        for (int j = 0; j < 4; j++)
            #pragma unroll
            for (int q = 0; q < 4; q++) d[i][j][q] = 0.f;

    load_stage(0, 0); CP_COMMIT();
    load_stage(1, 1); CP_COMMIT();
    load_stage(2, 2); CP_COMMIT();

    for (int kt = 0; kt < NCH; kt++) {
        CP_WAIT2();                 // load(kt) done (issued 3 iters back)
        __syncthreads();

        int s = kt % 3;
        uint32_t base = sb + s * STG_BYTES;
        int arow = wm * 64 + (lane & 15);
        int bro  = wn * 32 + (lane & 7) + ((lane >> 4) << 3);
        int bkh  = ((lane >> 3) & 1) << 3;

        #pragma unroll
        for (int ks = 0; ks < 4; ks++) {
            int acol = ks * 16 + ((lane >> 4) << 3);
            uint32_t ah[4][4], al[4][4], bh[4][2], bl[4][2];
            #pragma unroll
            for (int mf = 0; mf < 4; mf++) {
                uint32_t off = SMEM_SWIZZLE_128B(
                    (uint32_t)((arow + mf * 16) * 128 + acol * 2));
                ldm4(ah[mf], base + OFF_AH + off);
                if (full) ldm4(al[mf], base + OFF_AL + off);
            }
            #pragma unroll
            for (int j2 = 0; j2 < 2; j2++) {
                uint32_t off = SMEM_SWIZZLE_128B(
                    (uint32_t)((bro + j2 * 16) * 128 + (ks * 16 + bkh) * 2));
                uint32_t r[4];
                ldm4(r, base + OFF_BH + off);
                bh[j2 * 2][0] = r[0]; bh[j2 * 2][1] = r[1];
                bh[j2 * 2 + 1][0] = r[2]; bh[j2 * 2 + 1][1] = r[3];
                if (full) {
                    ldm4(r, base + OFF_BL + off);
                    bl[j2 * 2][0] = r[0]; bl[j2 * 2][1] = r[1];
                    bl[j2 * 2 + 1][0] = r[2]; bl[j2 * 2 + 1][1] = r[3];
                }
            }
            #pragma unroll
            for (int mf = 0; mf < 4; mf++)
                #pragma unroll
                for (int nf = 0; nf < 4; nf++) {
                    mma16816(d[mf][nf], ah[mf], bh[nf]);
                    if (full) {
                        mma16816(d[mf][nf], ah[mf], bl[nf]);
                        mma16816(d[mf][nf], al[mf], bh[nf]);
                    }
                }
        }
        __syncthreads();

        if (kt + 3 < NCH) load_stage(s, kt + 3);
        CP_COMMIT();                // keep group count aligned (may be empty)
    }

    // ---------------- fused epilogue ----------------
    int hb = blockIdx.x;             // 0..23
    bool needs_norm = (hb < 20);     // q and k blocks

    int c0 = wn * 32 + (lane & 3) * 2;     // hd col base (even)
    #pragma unroll
    for (int mf = 0; mf < 4; mf++)
        #pragma unroll
        for (int nf = 0; nf < 4; nf++) {
            int c = c0 + nf * 8;
            float b0 = bias[bx + c], b1 = bias[bx + c + 1];
            d[mf][nf][0] += b0; d[mf][nf][1] += b1;
            d[mf][nf][2] += b0; d[mf][nf][3] += b1;
        }

    float* ss = (float*)sm;          // [128][4] partial row sums
    __syncthreads();                 // all warps done reading smem stages

    if (needs_norm) {
        #pragma unroll
        for (int mf = 0; mf < 4; mf++) {
            float pA = 0.f, pB = 0.f;
            #pragma unroll
            for (int nf = 0; nf < 4; nf++) {
                pA += d[mf][nf][0] * d[mf][nf][0] + d[mf][nf][1] * d[mf][nf][1];
                pB += d[mf][nf][2] * d[mf][nf][2] + d[mf][nf][3] * d[mf][nf][3];
            }
            pA += __shfl_xor_sync(0xffffffffu, pA, 1);
            pA += __shfl_xor_sync(0xffffffffu, pA, 2);
            pB += __shfl_xor_sync(0xffffffffu, pB, 1);
            pB += __shfl_xor_sync(0xffffffffu, pB, 2);
            if ((lane & 3) == 0) {
                int lr = wm * 64 + mf * 16 + (lane >> 2);
                ss[lr * 4 + wn] = pA;
                ss[(lr + 8) * 4 + wn] = pB;
            }
        }
    }
    __syncthreads();

    const float* nsc = (hb < 16) ? qns : kns;
    float esc = (hb < 16) ? (1.0f / (float)HD) : 1.0f;
    __half* oph;
    int headmul;
    if (hb < 16)      { oph = qah; headmul = NH; }
    else if (hb < 20) { oph = kah; headmul = NG; }
    else              { oph = vah; headmul = NG; }
    int head = (hb < 16) ? hb : ((hb < 20) ? hb - 16 : hb - 20);

    #pragma unroll
    for (int mf = 0; mf < 4; mf++) {
        int lr = wm * 64 + mf * 16 + (lane >> 2);
        int rowA = by + lr, rowB = rowA + 8;
        int posA = rowA & (SEQ - 1), posB = rowB & (SEQ - 1);
        int bA = rowA >> 9, bB = rowB >> 9;
        float rinvA = 1.f, rinvB = 1.f;
        if (needs_norm) {
            float sA = ss[lr * 4] + ss[lr * 4 + 1] + ss[lr * 4 + 2] + ss[lr * 4 + 3];
            float sB = ss[(lr + 8) * 4] + ss[(lr + 8) * 4 + 1] +
                       ss[(lr + 8) * 4 + 2] + ss[(lr + 8) * 4 + 3];
            rinvA = rsqrtf(sA * (1.0f / HD) + 1e-6f);
            rinvB = rsqrtf(sB * (1.0f / HD) + 1e-6f);
        }
        size_t obA = ((size_t)(bA * headmul + head) * SEQ + posA) * HD;
        size_t obB = ((size_t)(bB * headmul + head) * SEQ + posB) * HD;
        #pragma unroll
        for (int nf = 0; nf < 4; nf++) {
            int c = c0 + nf * 8;
            if (needs_norm) {
                float sc0 = nsc[c], sc1 = nsc[c + 1];
                float invf = __expf(-(float)(c >> 1) * (9.210340371976184f / 64.0f));
                float snA, csA, snB, csB;
                __sincosf((float)posA * invf, &snA, &csA);
                __sincosf((float)posB * invf, &snB, &csB);
                float xA1 = d[mf][nf][0] * rinvA * sc0;
                float xA2 = d[mf][nf][1] * rinvA * sc1;
                float xB1 = d[mf][nf][2] * rinvB * sc0;
                float xB2 = d[mf][nf][3] * rinvB * sc1;
                *(__half2*)&oph[obA + c] = __floats2half2_rn(
                    (xA1 * csA - xA2 * snA) * esc, (xA1 * snA + xA2 * csA) * esc);
                *(__half2*)&oph[obB + c] = __floats2half2_rn(
                    (xB1 * csB - xB2 * snB) * esc, (xB1 * snB + xB2 * csB) * esc);
            } else {
                split_store(vah, val, obA + c, d[mf][nf][0], d[mf][nf][1]);
                split_store(vah, val, obB + c, d[mf][nf][2], d[mf][nf][3]);
            }
        }
    }
}

// ---------------------------------------------------------------------------
// plain HMMA split-3 GEMM with bias, fp32 output (for Wo) — 3-stage
// ---------------------------------------------------------------------------
__global__ __launch_bounds__(256, 1) void gemm_hmma(
    const __half* __restrict__ Ahg, const __half* __restrict__ Alg,
    const __half* __restrict__ Bhg, const __half* __restrict__ Blg,
    const float* __restrict__ bias, float* __restrict__ C, int N)
{
    extern __shared__ char sm[];
    uint32_t sb = smem_to_u32(sm);
    int tid = threadIdx.x, lane = tid & 31, wid = tid >> 5;
    int wm = wid & 1, wn = wid >> 1;
    int bx = blockIdx.x * BN, by = blockIdx.y * BM;

    auto load_stage = [&](int s, int kt) {
        int k0 = kt * BK;
        uint32_t base = sb + s * STG_BYTES;
        #pragma unroll
        for (int t = 0; t < 4; t++) {
            int idx = tid + t * 256;
            int r = idx >> 3, c16 = idx & 7;
            uint32_t swz = SMEM_SWIZZLE_128B((uint32_t)(r * 128 + c16 * 16));
            size_t ga = (size_t)(by + r) * DIM + k0 + c16 * 8;
            size_t gb = (size_t)(bx + r) * DIM + k0 + c16 * 8;
            cp16(base + OFF_AH + swz, Ahg + ga);
            cp16(base + OFF_AL + swz, Alg + ga);
            cp16(base + OFF_BH + swz, Bhg + gb);
            cp16(base + OFF_BL + swz, Blg + gb);
        }
    };

    float d[4][4][4];
    #pragma unroll
    for (int i = 0; i < 4; i++)
        #pragma unroll
        for (int j = 0; j < 4; j++)
            #pragma unroll
            for (int q = 0; q < 4; q++) d[i][j][q] = 0.f;

    load_stage(0, 0); CP_COMMIT();
    load_stage(1, 1); CP_COMMIT();
    load_stage(2, 2); CP_COMMIT();

    for (int kt = 0; kt < NCH; kt++) {
        CP_WAIT2();
        __syncthreads();

        int s = kt % 3;
        uint32_t base = sb + s * STG_BYTES;
        int arow = wm * 64 + (lane & 15);
        int bro  = wn * 32 + (lane & 7) + ((lane >> 4) << 3);
        int bkh  = ((lane >> 3) & 1) << 3;

        #pragma unroll
        for (int ks = 0; ks < 4; ks++) {
            int acol = ks * 16 + ((lane >> 4) << 3);
            uint32_t ah[4][4], al[4][4], bh[4][2], bl[4][2];
            #pragma unroll
            for (int mf = 0; mf < 4; mf++) {
                uint32_t off = SMEM_SWIZZLE_128B(
                    (uint32_t)((arow + mf * 16) * 128 + acol * 2));
                ldm4(ah[mf], base + OFF_AH + off);
                ldm4(al[mf], base + OFF_AL + off);
            }
            #pragma unroll
            for (int j2 = 0; j2 < 2; j2++) {
                uint32_t off = SMEM_SWIZZLE_128B(
                    (uint32_t)((bro + j2 * 16) * 128 + (ks * 16 + bkh) * 2));
                uint32_t r[4];
                ldm4(r, base + OFF_BH + off);
                bh[j2 * 2][0] = r[0]; bh[j2 * 2][1] = r[1];
                bh[j2 * 2 + 1][0] = r[2]; bh[j2 * 2 + 1][1] = r[3];
                ldm4(r, base + OFF_BL + off);
                bl[j2 * 2][0] = r[0]; bl[j2 * 2][1] = r[1];
                bl[j2 * 2 + 1][0] = r[2]; bl[j2 * 2 + 1][1] = r[3];
            }
            #pragma unroll
            for (int mf = 0; mf < 4; mf++)
                #pragma unroll
                for (int nf = 0; nf < 4; nf++) {
                    mma16816(d[mf][nf], ah[mf], bh[nf]);
                    mma16816(d[mf][nf], ah[mf], bl[nf]);
                    mma16816(d[mf][nf], al[mf], bh[nf]);
                }
        }
        __syncthreads();

        if (kt + 3 < NCH) load_stage(s, kt + 3);
        CP_COMMIT();
    }

    int row0 = by + wm * 64 + (lane >> 2);
    int col0 = bx + wn * 32 + (lane & 3) * 2;
    #pragma unroll
    for (int mf = 0; mf < 4; mf++)
        #pragma unroll
        for (int nf = 0; nf < 4; nf++) {
            int r = row0 + mf * 16;
            int c = col0 + nf * 8;
            float b0 = bias[c], b1 = bias[c + 1];
            float2 v0 = make_float2(d[mf][nf][0] + b0, d[mf][nf][1] + b1);
            float2 v1 = make_float2(d[mf][nf][2] + b0, d[mf][nf][3] + b1);
            *(float2*)&C[(size_t)r * N + c] = v0;
            *(float2*)&C[(size_t)(r + 8) * N + c] = v1;
        }
}

// ---------------------------------------------------------------------------
// HMMA flash attention. Q/K fp16 hi-only (S single-product); P·V split-3.
// 3-stage pipeline: Q 32KB + 3 x (K 16K + Vh 16K + Vl 16K) = 176KB
// ---------------------------------------------------------------------------
#define FA_STG 49152
#define FA_SMEM (32768 + 3 * FA_STG)   // 180224

__global__ __launch_bounds__(256, 1) void flash_attn_hmma(
    const __half* __restrict__ qh, const __half* __restrict__ kh,
    const __half* __restrict__ vh, const __half* __restrict__ vl,
    __half* __restrict__ aoh, __half* __restrict__ aol)
{
    extern __shared__ char sm[];
    uint32_t sb = smem_to_u32(sm);
    int qb = (gridDim.x - 1) - blockIdx.x;
    int h = blockIdx.y, b = blockIdx.z;
    int g = h >> 2;
    int tid = threadIdx.x, lane = tid & 31, wid = tid >> 5;

    const size_t qbase  = ((size_t)(b * NH + h) * SEQ + qb * 128) * HD;
    const size_t kvbase = ((size_t)(b * NG + g) * SEQ) * HD;

    const uint32_t QH = sb;

    auto load_q = [&]() {
        #pragma unroll
        for (int t = 0; t < 8; t++) {
            int idx = tid + t * 256;
            int r = idx >> 4, c16 = idx & 15;
            uint32_t off = (uint32_t)((c16 >> 3) * 16384) +
                           SMEM_SWIZZLE_128B((uint32_t)(r * 128 + (c16 & 7) * 16));
            cp16(QH + off, qh + qbase + (size_t)r * HD + c16 * 8);
        }
    };
    auto load_kv = [&](int s, int kt) {
        uint32_t base = sb + 32768 + s * FA_STG;
        size_t kb = kvbase + (size_t)kt * 64 * HD;
        #pragma unroll
        for (int t = 0; t < 4; t++) {
            int idx = tid + t * 256;
            int r = idx >> 4, c16 = idx & 15;
            uint32_t off = (uint32_t)((c16 >> 3) * 8192) +
                           SMEM_SWIZZLE_128B((uint32_t)(r * 128 + (c16 & 7) * 16));
            size_t go = kb + (size_t)r * HD + c16 * 8;
            cp16(base + off,         kh + go);
            cp16(base + 16384 + off, vh + go);
            cp16(base + 32768 + off, vl + go);
        }
    };

    int nkt = 2 * qb + 2;
    load_q();
    if (0 < nkt) load_kv(0, 0);
    CP_COMMIT();
    if (1 < nkt) load_kv(1, 1);
    CP_COMMIT();
    if (2 < nkt) load_kv(2, 2);
    CP_COMMIT();

    float o[16][4];
    #pragma unroll
    for (int i = 0; i < 16; i++)
        #pragma unroll
        for (int j = 0; j < 4; j++) o[i][j] = 0.f;
    float mA = -1e30f, mB = -1e30f, lA = 0.f, lB = 0.f;

    int row0 = wid * 16;
    int sq = qb * 128 + row0;

    for (int kt = 0; kt < nkt; kt++) {
        CP_WAIT2();
        __syncthreads();

        int st = kt % 3;
        uint32_t KHb = sb + 32768 + st * FA_STG;
        uint32_t VHb = KHb + 16384, VLb = KHb + 32768;

        bool active = (kt * 64 <= sq + 15);
        if (active) {
            float sc[8][4];
            #pragma unroll
            for (int i = 0; i < 8; i++)
                #pragma unroll
                for (int j = 0; j < 4; j++) sc[i][j] = 0.f;

            int aro  = row0 + (lane & 15);
            int kro  = (lane & 7) + ((lane >> 4) << 3);
            int bkh  = ((lane >> 3) & 1) << 3;

            // S = Qh Kh^T (single product)
            #pragma unroll
            for (int ks = 0; ks < 8; ks++) {
                int chk  = ks >> 2;
                int acol = (ks & 3) * 16 + ((lane >> 4) << 3);
                uint32_t aoff = (uint32_t)(chk * 16384) +
                                SMEM_SWIZZLE_128B((uint32_t)(aro * 128 + acol * 2));
                uint32_t ah[4];
                ldm4(ah, QH + aoff);

                int bcol = (ks & 3) * 16 + bkh;
                uint32_t bh[8][2];
                #pragma unroll
                for (int j2 = 0; j2 < 4; j2++) {
                    uint32_t boff = (uint32_t)(chk * 8192) +
                        SMEM_SWIZZLE_128B((uint32_t)((j2 * 16 + kro) * 128 + bcol * 2));
                    uint32_t r[4];
                    ldm4(r, KHb + boff);
                    bh[2*j2][0] = r[0]; bh[2*j2][1] = r[1];
                    bh[2*j2+1][0] = r[2]; bh[2*j2+1][1] = r[3];
                }
                #pragma unroll
                for (int nf = 0; nf < 8; nf++)
                    mma16816(sc[nf], ah, bh[nf]);
            }

            if (kt * 64 + 63 > sq) {
                int rA = sq + (lane >> 2), rB = rA + 8;
                #pragma unroll
                for (int nf = 0; nf < 8; nf++) {
                    int cbase = kt * 64 + nf * 8 + 2 * (lane & 3);
                    if (cbase     > rA) sc[nf][0] = -1e30f;
                    if (cbase + 1 > rA) sc[nf][1] = -1e30f;
                    if (cbase     > rB) sc[nf][2] = -1e30f;
                    if (cbase + 1 > rB) sc[nf][3] = -1e30f;
                }
            }

            float mtA = -1e30f, mtB = -1e30f;
            #pragma unroll
            for (int nf = 0; nf < 8; nf++) {
                mtA = fmaxf(mtA, fmaxf(sc[nf][0], sc[nf][1]));
                mtB = fmaxf(mtB, fmaxf(sc[nf][2], sc[nf][3]));
            }
            mtA = fmaxf(mtA, __shfl_xor_sync(0xffffffffu, mtA, 1));
            mtA = fmaxf(mtA, __shfl_xor_sync(0xffffffffu, mtA, 2));
            mtB = fmaxf(mtB, __shfl_xor_sync(0xffffffffu, mtB, 1));
            mtB = fmaxf(mtB, __shfl_xor_sync(0xffffffffu, mtB, 2));
            float nmA = fmaxf(mA, mtA), nmB = fmaxf(mB, mtB);
            float alA = __expf(mA - nmA), alB = __expf(mB - nmB);

            float suA = 0.f, suB = 0.f;
            #pragma unroll
            for (int nf = 0; nf < 8; nf++) {
                sc[nf][0] = __expf(sc[nf][0] - nmA); suA += sc[nf][0];
                sc[nf][1] = __expf(sc[nf][1] - nmA); suA += sc[nf][1];
                sc[nf][2] = __expf(sc[nf][2] - nmB); suB += sc[nf][2];
                sc[nf][3] = __expf(sc[nf][3] - nmB); suB += sc[nf][3];
            }
            suA += __shfl_xor_sync(0xffffffffu, suA, 1);
            suA += __shfl_xor_sync(0xffffffffu, suA, 2);
            suB += __shfl_xor_sync(0xffffffffu, suB, 1);
            suB += __shfl_xor_sync(0xffffffffu, suB, 2);
            lA = lA * alA + suA;
            lB = lB * alB + suB;
            mA = nmA; mB = nmB;
            #pragma unroll
            for (int nf = 0; nf < 16; nf++) {
                o[nf][0] *= alA; o[nf][1] *= alA;
                o[nf][2] *= alB; o[nf][3] *= alB;
            }

            int vro = (lane & 7) + (((lane >> 3) & 1) << 3);
            int vch = (lane >> 4) << 3;
            #pragma unroll
            for (int kf = 0; kf < 4; kf++) {
                uint32_t aPh[4], aPl[4];
                {
                    float p0 = sc[2*kf][0],   p1 = sc[2*kf][1];
                    float p2 = sc[2*kf][2],   p3 = sc[2*kf][3];
                    float p4 = sc[2*kf+1][0], p5 = sc[2*kf+1][1];
                    float p6 = sc[2*kf+1][2], p7 = sc[2*kf+1][3];
                    __half h0 = __float2half_rn(p0), h1 = __float2half_rn(p1);
                    __half h2 = __float2half_rn(p2), h3 = __float2half_rn(p3);
                    __half h4 = __float2half_rn(p4), h5 = __float2half_rn(p5);
                    __half h6 = __float2half_rn(p6), h7 = __float2half_rn(p7);
                    aPh[0] = pk2h(p0, p1); aPh[1] = pk2h(p2, p3);
                    aPh[2] = pk2h(p4, p5); aPh[3] = pk2h(p6, p7);
                    aPl[0] = pk2h(p0 - __half2float(h0), p1 - __half2float(h1));
                    aPl[1] = pk2h(p2 - __half2float(h2), p3 - __half2float(h3));
                    aPl[2] = pk2h(p4 - __half2float(h4), p5 - __half2float(h5));
                    aPl[3] = pk2h(p6 - __half2float(h6), p7 - __half2float(h7));
                }
                #pragma unroll
                for (int j2 = 0; j2 < 8; j2++) {
                    int chk  = j2 >> 2;
                    int wcol = (j2 & 3) * 16 + vch;
                    uint32_t voff = (uint32_t)(chk * 8192) +
                        SMEM_SWIZZLE_128B((uint32_t)((kf * 16 + vro) * 128 + wcol * 2));
                    uint32_t rh[4], rl[4];
                    ldm4t(rh, VHb + voff);
                    ldm4t(rl, VLb + voff);
                    uint32_t bh0[2] = {rh[0], rh[1]}, bh1[2] = {rh[2], rh[3]};
                    uint32_t bl0[2] = {rl[0], rl[1]}, bl1[2] = {rl[2], rl[3]};
                    mma16816(o[2*j2],   aPh, bh0);
                    mma16816(o[2*j2],   aPh, bl0);
                    mma16816(o[2*j2],   aPl, bh0);
                    mma16816(o[2*j2+1], aPh, bh1);
                    mma16816(o[2*j2+1], aPh, bl1);
                    mma16816(o[2*j2+1], aPl, bh1);
                }
            }
        }
        __syncthreads();

        if (kt + 3 < nkt) load_kv(kt % 3, kt + 3);
        CP_COMMIT();
    }

    float rlA = 1.0f / lA, rlB = 1.0f / lB;
    int sA = sq + (lane >> 2), sB = sA + 8;
    size_t oA = ((size_t)(b * SEQ + sA) * NH + h) * HD;
    size_t oB = ((size_t)(b * SEQ + sB) * NH + h) * HD;
    #pragma unroll
    for (int nf = 0; nf < 16; nf++) {
        int hd = nf * 8 + 2 * (lane & 3);
        float e0 = o[nf][0] * rlA, e1 = o[nf][1] * rlA;
        float e2 = o[nf][2] * rlB, e3 = o[nf][3] * rlB;
        split_store(aoh, aol, oA + hd, e0, e1);
        split_store(aoh, aol, oB + hd, e2, e3);
    }
}

// ---------------------------------------------------------------------------
extern "C" void kernel_launch(void* const* d_in, const int* in_sizes, int n_in,
                              void* d_out, int out_size)
{
    const float* x   = (const float*)d_in[0];
    const float* Wq  = (const float*)d_in[1];
    const float* bq  = (const float*)d_in[2];
    const float* Wk  = (const float*)d_in[3];
    const float* bk  = (const float*)d_in[4];
    const float* Wv  = (const float*)d_in[5];
    const float* bv  = (const float*)d_in[6];
    const float* Wo  = (const float*)d_in[7];
    const float* bo  = (const float*)d_in[8];
    const float* qns = (const float*)d_in[9];
    const float* kns = (const float*)d_in[10];
    float* out = (float*)d_out;

    __half *xhi, *xlo, *aoh, *aol, *wh, *wl, *woh, *wol;
    __half *qah, *kah, *vah, *val;
    float* bqkv;
    cudaGetSymbolAddress((void**)&xhi, g_xhi);
    cudaGetSymbolAddress((void**)&xlo, g_xlo);
    cudaGetSymbolAddress((void**)&aoh, g_aoh);
    cudaGetSymbolAddress((void**)&aol, g_aol);
    cudaGetSymbolAddress((void**)&wh,  g_wh);
    cudaGetSymbolAddress((void**)&wl,  g_wl);
    cudaGetSymbolAddress((void**)&woh, g_woh);
    cudaGetSymbolAddress((void**)&wol, g_wol);
    cudaGetSymbolAddress((void**)&bqkv, g_bqkv);
    cudaGetSymbolAddress((void**)&qah, g_qah);
    cudaGetSymbolAddress((void**)&kah, g_kah);
    cudaGetSymbolAddress((void**)&vah, g_vah);
    cudaGetSymbolAddress((void**)&val, g_val);

    cudaFuncSetAttribute(gemm_qkv, cudaFuncAttributeMaxDynamicSharedMemorySize, GEMM_SMEM);
    cudaFuncSetAttribute(gemm_hmma, cudaFuncAttributeMaxDynamicSharedMemorySize, GEMM_SMEM);
    cudaFuncSetAttribute(flash_attn_hmma, cudaFuncAttributeMaxDynamicSharedMemorySize, FA_SMEM);

    const int n4 = MROWS * DIM / 4;

    // conversions (weights concatenated into one [3072,2048] hi/lo buffer)
    convert_split<<<(n4 + 255) / 256, 256>>>(x, xhi, xlo, n4);
    transpose_split<<<dim3(DIM / 32, DIM / 32), dim3(32, 8)>>>(Wq, wh, wl, DIM, DIM);
    transpose_split<<<dim3(KVD / 32, DIM / 32), dim3(32, 8)>>>(
        Wk, wh + (size_t)DIM * DIM, wl + (size_t)DIM * DIM, DIM, KVD);
    transpose_split<<<dim3(KVD / 32, DIM / 32), dim3(32, 8)>>>(
        Wv, wh + (size_t)(DIM + KVD) * DIM, wl + (size_t)(DIM + KVD) * DIM, DIM, KVD);
    transpose_split<<<dim3(DIM / 32, DIM / 32), dim3(32, 8)>>>(Wo, woh, wol, DIM, DIM);
    bias_concat<<<(NQKV + 255) / 256, 256>>>(bq, bk, bv, bqkv);

    // fused QKV projection + rmsnorm + rope (q carries full 1/hd)
    gemm_qkv<<<dim3(NQKV / BN, MROWS / BM), 256, GEMM_SMEM>>>(
        xhi, xlo, wh, wl, bqkv, qns, kns,
        qah, kah, vah, val);

    // attention (HMMA)
    flash_attn_hmma<<<dim3(SEQ / 128, NH, BATCH), 256, FA_SMEM>>>(
        qah, kah, vah, val, aoh, aol);

    // output projection
    gemm_hmma<<<dim3(DIM / BN, MROWS / BM), 256, GEMM_SMEM>>>(
        aoh, aol, woh, wol, bo, out, DIM);
}

// round 9
// speedup vs baseline: 1.2115x; 1.1173x over previous
#include <cuda_runtime.h>
#include <cuda_fp16.h>
#include <cstdint>
#include <math.h>

#define BATCH 16
#define SEQ   512
#define DIM   2048
#define NH    16
#define NG    4
#define HD    128
#define MROWS (BATCH*SEQ)   // 8192
#define KVD   (NG*HD)       // 512
#define NQKV  (DIM + 2*KVD) // 3072

// ---------------------------------------------------------------------------
// scratch (device globals — no allocation allowed)
// ---------------------------------------------------------------------------
__device__ __half g_xhi[(size_t)MROWS * DIM];
__device__ __half g_xlo[(size_t)MROWS * DIM];
__device__ __half g_aoh[(size_t)MROWS * DIM];   // attn out fp16 (b,s,H,hd)
__device__ __half g_wh[(size_t)NQKV * DIM];     // [Wq^T; Wk^T; Wv^T] fp16 hi
__device__ __half g_wl[(size_t)NQKV * DIM];
__device__ __half g_woh[(size_t)DIM * DIM];
__device__ __half g_wol[(size_t)DIM * DIM];
__device__ float  g_bqkv[NQKV];                 // [bq; bk; bv]

// attention operand buffers, (b, head, s, hd) layout
__device__ __half g_qah[(size_t)MROWS * DIM];   // q fp16 (hi only)
__device__ __half g_kah[(size_t)MROWS * KVD];   // k fp16 (hi only)
__device__ __half g_vah[(size_t)MROWS * KVD];   // v fp16 hi
__device__ __half g_val[(size_t)MROWS * KVD];   // v fp16 lo

// ---------------------------------------------------------------------------
// helpers
// ---------------------------------------------------------------------------
__device__ __forceinline__ uint32_t smem_to_u32(const void* p) {
    uint32_t a;
    asm("{ .reg .u64 t; cvta.to.shared.u64 t, %1; cvt.u32.u64 %0, t; }" : "=r"(a) : "l"(p));
    return a;
}
#define SMEM_SWIZZLE_128B(bo) ((bo) ^ (((bo) >> 3) & 0x70))

__device__ __forceinline__ void cp16(uint32_t s, const void* g) {
    asm volatile("cp.async.cg.shared.global [%0], [%1], 16;" :: "r"(s), "l"(g) : "memory");
}
#define CP_COMMIT() asm volatile("cp.async.commit_group;" ::: "memory")
#define CP_WAIT2()  asm volatile("cp.async.wait_group 2;" ::: "memory")
__device__ __forceinline__ void ldm4(uint32_t* r, uint32_t a) {
    asm volatile("ldmatrix.sync.aligned.m8n8.x4.shared.b16 {%0,%1,%2,%3}, [%4];"
                 : "=r"(r[0]), "=r"(r[1]), "=r"(r[2]), "=r"(r[3]) : "r"(a));
}
__device__ __forceinline__ void ldm4t(uint32_t* r, uint32_t a) {
    asm volatile("ldmatrix.sync.aligned.m8n8.x4.trans.shared.b16 {%0,%1,%2,%3}, [%4];"
                 : "=r"(r[0]), "=r"(r[1]), "=r"(r[2]), "=r"(r[3]) : "r"(a));
}
__device__ __forceinline__ void mma16816(float* d, const uint32_t* a, const uint32_t* b) {
    asm volatile(
        "mma.sync.aligned.m16n8k16.row.col.f32.f16.f16.f32 "
        "{%0,%1,%2,%3},{%4,%5,%6,%7},{%8,%9},{%0,%1,%2,%3};"
        : "+f"(d[0]), "+f"(d[1]), "+f"(d[2]), "+f"(d[3])
        : "r"(a[0]), "r"(a[1]), "r"(a[2]), "r"(a[3]), "r"(b[0]), "r"(b[1]));
}
__device__ __forceinline__ uint32_t pk2h(float a, float b) {
    __half2 h = __floats2half2_rn(a, b);
    return *reinterpret_cast<uint32_t*>(&h);
}
// store float pair as hi/lo half2
__device__ __forceinline__ void split_store(__half* hp, __half* lp, size_t off,
                                            float a, float b) {
    __half ha = __float2half_rn(a), hb = __float2half_rn(b);
    *(__half2*)&hp[off] = __halves2half2(ha, hb);
    *(__half2*)&lp[off] = __halves2half2(
        __float2half_rn(a - __half2float(ha)), __float2half_rn(b - __half2float(hb)));
}

// ---------------------------------------------------------------------------
// convert fp32 -> fp16 hi + fp16 lo (residual)
// ---------------------------------------------------------------------------
__global__ __launch_bounds__(256) void convert_split(
    const float* __restrict__ in, __half* __restrict__ hi,
    __half* __restrict__ lo, int n4)
{
    int i = blockIdx.x * 256 + threadIdx.x;
    if (i >= n4) return;
    float4 v = ((const float4*)in)[i];
    float hx = __half2float(__float2half_rn(v.x));
    float hy = __half2float(__float2half_rn(v.y));
    float hz = __half2float(__float2half_rn(v.z));
    float hw = __half2float(__float2half_rn(v.w));
    uint2 ph, pl;
    ph.x = pk2h(v.x, v.y); ph.y = pk2h(v.z, v.w);
    pl.x = pk2h(v.x - hx, v.y - hy); pl.y = pk2h(v.z - hz, v.w - hw);
    ((uint2*)hi)[i] = ph;
    ((uint2*)lo)[i] = pl;
}

// ---------------------------------------------------------------------------
// W [K, N] fp32 -> W^T [N, K] fp16 hi/lo
// ---------------------------------------------------------------------------
__global__ __launch_bounds__(256) void transpose_split(
    const float* __restrict__ W, __half* __restrict__ Th,
    __half* __restrict__ Tl, int K, int N)
{
    __shared__ float tile[32][33];
    int n0 = blockIdx.x * 32, k0 = blockIdx.y * 32;
    int tx = threadIdx.x, ty = threadIdx.y;   // 32 x 8
    #pragma unroll
    for (int j = ty; j < 32; j += 8)
        tile[j][tx] = W[(size_t)(k0 + j) * N + n0 + tx];
    __syncthreads();
    #pragma unroll
    for (int j = ty; j < 32; j += 8) {
        float v = tile[tx][j];
        __half h = __float2half_rn(v);
        float r = v - __half2float(h);
        size_t o = (size_t)(n0 + j) * K + k0 + tx;
        Th[o] = h;
        Tl[o] = __float2half_rn(r);
    }
}

__global__ __launch_bounds__(256) void bias_concat(
    const float* __restrict__ bq, const float* __restrict__ bk,
    const float* __restrict__ bv, float* __restrict__ o)
{
    int i = blockIdx.x * 256 + threadIdx.x;
    if (i < DIM) o[i] = bq[i];
    else if (i < DIM + KVD) o[i] = bk[i - DIM];
    else if (i < NQKV) o[i] = bv[i - DIM - KVD];
}

// ---------------------------------------------------------------------------
// shared GEMM tile config — 3-stage cp.async pipeline
// ---------------------------------------------------------------------------
#define BM 128
#define BN 128
#define BK 64
#define NCH (DIM / BK)   // 32
#define STG_BYTES 65536
#define OFF_AH 0
#define OFF_AL 16384
#define OFF_BH 32768
#define OFF_BL 49152
#define GEMM_SMEM (3 * STG_BYTES)   // 196608

// Wo GEMM: split-2 (A hi only), stage = AH 16K + BH 16K + BL 16K
#define WSTG_BYTES 49152
#define W_OFF_AH 0
#define W_OFF_BH 16384
#define W_OFF_BL 32768
#define WGEMM_SMEM (3 * WSTG_BYTES)  // 147456

// ---------------------------------------------------------------------------
// Fused QKV GEMM + RMSNorm + RoPE epilogue (unchanged from R8).
// ---------------------------------------------------------------------------
__global__ __launch_bounds__(256, 1) void gemm_qkv(
    const __half* __restrict__ Ahg, const __half* __restrict__ Alg,
    const __half* __restrict__ Bhg, const __half* __restrict__ Blg,
    const float* __restrict__ bias,
    const float* __restrict__ qns, const float* __restrict__ kns,
    __half* __restrict__ qah, __half* __restrict__ kah,
    __half* __restrict__ vah, __half* __restrict__ val)
{
    extern __shared__ char sm[];
    uint32_t sb = smem_to_u32(sm);
    int tid = threadIdx.x, lane = tid & 31, wid = tid >> 5;
    int wm = wid & 1, wn = wid >> 1;
    int bx = blockIdx.x * BN, by = blockIdx.y * BM;
    const bool full = (blockIdx.x >= 20);   // v blocks

    auto load_stage = [&](int s, int kt) {
        int k0 = kt * BK;
        uint32_t base = sb + s * STG_BYTES;
        #pragma unroll
        for (int t = 0; t < 4; t++) {
            int idx = tid + t * 256;
            int r = idx >> 3, c16 = idx & 7;
            uint32_t swz = SMEM_SWIZZLE_128B((uint32_t)(r * 128 + c16 * 16));
            size_t ga = (size_t)(by + r) * DIM + k0 + c16 * 8;
            size_t gb = (size_t)(bx + r) * DIM + k0 + c16 * 8;
            cp16(base + OFF_AH + swz, Ahg + ga);
            cp16(base + OFF_BH + swz, Bhg + gb);
            if (full) {
                cp16(base + OFF_AL + swz, Alg + ga);
                cp16(base + OFF_BL + swz, Blg + gb);
            }
        }
    };

    float d[4][4][4];
    #pragma unroll
    for (int i = 0; i < 4; i++)
        #pragma unroll
        for (int j = 0; j < 4; j++)
            #pragma unroll
            for (int q = 0; q < 4; q++) d[i][j][q] = 0.f;

    load_stage(0, 0); CP_COMMIT();
    load_stage(1, 1); CP_COMMIT();
    load_stage(2, 2); CP_COMMIT();

    for (int kt = 0; kt < NCH; kt++) {
        CP_WAIT2();
        __syncthreads();

        int s = kt % 3;
        uint32_t base = sb + s * STG_BYTES;
        int arow = wm * 64 + (lane & 15);
        int bro  = wn * 32 + (lane & 7) + ((lane >> 4) << 3);
        int bkh  = ((lane >> 3) & 1) << 3;

        #pragma unroll
        for (int ks = 0; ks < 4; ks++) {
            int acol = ks * 16 + ((lane >> 4) << 3);
            uint32_t ah[4][4], al[4][4], bh[4][2], bl[4][2];
            #pragma unroll
            for (int mf = 0; mf < 4; mf++) {
                uint32_t off = SMEM_SWIZZLE_128B(
                    (uint32_t)((arow + mf * 16) * 128 + acol * 2));
                ldm4(ah[mf], base + OFF_AH + off);
                if (full) ldm4(al[mf], base + OFF_AL + off);
            }
            #pragma unroll
            for (int j2 = 0; j2 < 2; j2++) {
                uint32_t off = SMEM_SWIZZLE_128B(
                    (uint32_t)((bro + j2 * 16) * 128 + (ks * 16 + bkh) * 2));
                uint32_t r[4];
                ldm4(r, base + OFF_BH + off);
                bh[j2 * 2][0] = r[0]; bh[j2 * 2][1] = r[1];
                bh[j2 * 2 + 1][0] = r[2]; bh[j2 * 2 + 1][1] = r[3];
                if (full) {
                    ldm4(r, base + OFF_BL + off);
                    bl[j2 * 2][0] = r[0]; bl[j2 * 2][1] = r[1];
                    bl[j2 * 2 + 1][0] = r[2]; bl[j2 * 2 + 1][1] = r[3];
                }
            }
            #pragma unroll
            for (int mf = 0; mf < 4; mf++)
                #pragma unroll
                for (int nf = 0; nf < 4; nf++) {
                    mma16816(d[mf][nf], ah[mf], bh[nf]);
                    if (full) {
                        mma16816(d[mf][nf], ah[mf], bl[nf]);
                        mma16816(d[mf][nf], al[mf], bh[nf]);
                    }
                }
        }
        __syncthreads();

        if (kt + 3 < NCH) load_stage(s, kt + 3);
        CP_COMMIT();
    }

    // ---------------- fused epilogue ----------------
    int hb = blockIdx.x;             // 0..23
    bool needs_norm = (hb < 20);     // q and k blocks

    int c0 = wn * 32 + (lane & 3) * 2;     // hd col base (even)
    #pragma unroll
    for (int mf = 0; mf < 4; mf++)
        #pragma unroll
        for (int nf = 0; nf < 4; nf++) {
            int c = c0 + nf * 8;
            float b0 = bias[bx + c], b1 = bias[bx + c + 1];
            d[mf][nf][0] += b0; d[mf][nf][1] += b1;
            d[mf][nf][2] += b0; d[mf][nf][3] += b1;
        }

    float* ss = (float*)sm;          // [128][4] partial row sums
    __syncthreads();

    if (needs_norm) {
        #pragma unroll
        for (int mf = 0; mf < 4; mf++) {
            float pA = 0.f, pB = 0.f;
            #pragma unroll
            for (int nf = 0; nf < 4; nf++) {
                pA += d[mf][nf][0] * d[mf][nf][0] + d[mf][nf][1] * d[mf][nf][1];
                pB += d[mf][nf][2] * d[mf][nf][2] + d[mf][nf][3] * d[mf][nf][3];
            }
            pA += __shfl_xor_sync(0xffffffffu, pA, 1);
            pA += __shfl_xor_sync(0xffffffffu, pA, 2);
            pB += __shfl_xor_sync(0xffffffffu, pB, 1);
            pB += __shfl_xor_sync(0xffffffffu, pB, 2);
            if ((lane & 3) == 0) {
                int lr = wm * 64 + mf * 16 + (lane >> 2);
                ss[lr * 4 + wn] = pA;
                ss[(lr + 8) * 4 + wn] = pB;
            }
        }
    }
    __syncthreads();

    const float* nsc = (hb < 16) ? qns : kns;
    float esc = (hb < 16) ? (1.0f / (float)HD) : 1.0f;
    __half* oph;
    int headmul;
    if (hb < 16)      { oph = qah; headmul = NH; }
    else if (hb < 20) { oph = kah; headmul = NG; }
    else              { oph = vah; headmul = NG; }
    int head = (hb < 16) ? hb : ((hb < 20) ? hb - 16 : hb - 20);

    #pragma unroll
    for (int mf = 0; mf < 4; mf++) {
        int lr = wm * 64 + mf * 16 + (lane >> 2);
        int rowA = by + lr, rowB = rowA + 8;
        int posA = rowA & (SEQ - 1), posB = rowB & (SEQ - 1);
        int bA = rowA >> 9, bB = rowB >> 9;
        float rinvA = 1.f, rinvB = 1.f;
        if (needs_norm) {
            float sA = ss[lr * 4] + ss[lr * 4 + 1] + ss[lr * 4 + 2] + ss[lr * 4 + 3];
            float sB = ss[(lr + 8) * 4] + ss[(lr + 8) * 4 + 1] +
                       ss[(lr + 8) * 4 + 2] + ss[(lr + 8) * 4 + 3];
            rinvA = rsqrtf(sA * (1.0f / HD) + 1e-6f);
            rinvB = rsqrtf(sB * (1.0f / HD) + 1e-6f);
        }
        size_t obA = ((size_t)(bA * headmul + head) * SEQ + posA) * HD;
        size_t obB = ((size_t)(bB * headmul + head) * SEQ + posB) * HD;
        #pragma unroll
        for (int nf = 0; nf < 4; nf++) {
            int c = c0 + nf * 8;
            if (needs_norm) {
                float sc0 = nsc[c], sc1 = nsc[c + 1];
                float invf = __expf(-(float)(c >> 1) * (9.210340371976184f / 64.0f));
                float snA, csA, snB, csB;
                __sincosf((float)posA * invf, &snA, &csA);
                __sincosf((float)posB * invf, &snB, &csB);
                float xA1 = d[mf][nf][0] * rinvA * sc0;
                float xA2 = d[mf][nf][1] * rinvA * sc1;
                float xB1 = d[mf][nf][2] * rinvB * sc0;
                float xB2 = d[mf][nf][3] * rinvB * sc1;
                *(__half2*)&oph[obA + c] = __floats2half2_rn(
                    (xA1 * csA - xA2 * snA) * esc, (xA1 * snA + xA2 * csA) * esc);
                *(__half2*)&oph[obB + c] = __floats2half2_rn(
                    (xB1 * csB - xB2 * snB) * esc, (xB1 * snB + xB2 * csB) * esc);
            } else {
                split_store(vah, val, obA + c, d[mf][nf][0], d[mf][nf][1]);
                split_store(vah, val, obB + c, d[mf][nf][2], d[mf][nf][3]);
            }
        }
    }
}

// ---------------------------------------------------------------------------
// Wo GEMM: split-2 (A fp16 hi only; W hi+lo), bias, fp32 output.
// Error analysis: dropped Al·W term ≈ 2^-11/√3 ≈ 1.7e-4 relative.
// ---------------------------------------------------------------------------
__global__ __launch_bounds__(256, 1) void gemm_wo(
    const __half* __restrict__ Ahg,
    const __half* __restrict__ Bhg, const __half* __restrict__ Blg,
    const float* __restrict__ bias, float* __restrict__ C, int N)
{
    extern __shared__ char sm[];
    uint32_t sb = smem_to_u32(sm);
    int tid = threadIdx.x, lane = tid & 31, wid = tid >> 5;
    int wm = wid & 1, wn = wid >> 1;
    int bx = blockIdx.x * BN, by = blockIdx.y * BM;

    auto load_stage = [&](int s, int kt) {
        int k0 = kt * BK;
        uint32_t base = sb + s * WSTG_BYTES;
        #pragma unroll
        for (int t = 0; t < 4; t++) {
            int idx = tid + t * 256;
            int r = idx >> 3, c16 = idx & 7;
            uint32_t swz = SMEM_SWIZZLE_128B((uint32_t)(r * 128 + c16 * 16));
            size_t ga = (size_t)(by + r) * DIM + k0 + c16 * 8;
            size_t gb = (size_t)(bx + r) * DIM + k0 + c16 * 8;
            cp16(base + W_OFF_AH + swz, Ahg + ga);
            cp16(base + W_OFF_BH + swz, Bhg + gb);
            cp16(base + W_OFF_BL + swz, Blg + gb);
        }
    };

    float d[4][4][4];
    #pragma unroll
    for (int i = 0; i < 4; i++)
        #pragma unroll
        for (int j = 0; j < 4; j++)
            #pragma unroll
            for (int q = 0; q < 4; q++) d[i][j][q] = 0.f;

    load_stage(0, 0); CP_COMMIT();
    load_stage(1, 1); CP_COMMIT();
    load_stage(2, 2); CP_COMMIT();

    for (int kt = 0; kt < NCH; kt++) {
        CP_WAIT2();
        __syncthreads();

        int s = kt % 3;
        uint32_t base = sb + s * WSTG_BYTES;
        int arow = wm * 64 + (lane & 15);
        int bro  = wn * 32 + (lane & 7) + ((lane >> 4) << 3);
        int bkh  = ((lane >> 3) & 1) << 3;

        #pragma unroll
        for (int ks = 0; ks < 4; ks++) {
            int acol = ks * 16 + ((lane >> 4) << 3);
            uint32_t ah[4][4], bh[4][2], bl[4][2];
            #pragma unroll
            for (int mf = 0; mf < 4; mf++) {
                uint32_t off = SMEM_SWIZZLE_128B(
                    (uint32_t)((arow + mf * 16) * 128 + acol * 2));
                ldm4(ah[mf], base + W_OFF_AH + off);
            }
            #pragma unroll
            for (int j2 = 0; j2 < 2; j2++) {
                uint32_t off = SMEM_SWIZZLE_128B(
                    (uint32_t)((bro + j2 * 16) * 128 + (ks * 16 + bkh) * 2));
                uint32_t r[4];
                ldm4(r, base + W_OFF_BH + off);
                bh[j2 * 2][0] = r[0]; bh[j2 * 2][1] = r[1];
                bh[j2 * 2 + 1][0] = r[2]; bh[j2 * 2 + 1][1] = r[3];
                ldm4(r, base + W_OFF_BL + off);
                bl[j2 * 2][0] = r[0]; bl[j2 * 2][1] = r[1];
                bl[j2 * 2 + 1][0] = r[2]; bl[j2 * 2 + 1][1] = r[3];
            }
            #pragma unroll
            for (int mf = 0; mf < 4; mf++)
                #pragma unroll
                for (int nf = 0; nf < 4; nf++) {
                    mma16816(d[mf][nf], ah[mf], bh[nf]);
                    mma16816(d[mf][nf], ah[mf], bl[nf]);
                }
        }
        __syncthreads();

        if (kt + 3 < NCH) load_stage(s, kt + 3);
        CP_COMMIT();
    }

    int row0 = by + wm * 64 + (lane >> 2);
    int col0 = bx + wn * 32 + (lane & 3) * 2;
    #pragma unroll
    for (int mf = 0; mf < 4; mf++)
        #pragma unroll
        for (int nf = 0; nf < 4; nf++) {
            int r = row0 + mf * 16;
            int c = col0 + nf * 8;
            float b0 = bias[c], b1 = bias[c + 1];
            float2 v0 = make_float2(d[mf][nf][0] + b0, d[mf][nf][1] + b1);
            float2 v1 = make_float2(d[mf][nf][2] + b0, d[mf][nf][3] + b1);
            *(float2*)&C[(size_t)r * N + c] = v0;
            *(float2*)&C[(size_t)(r + 8) * N + c] = v1;
        }
}

// ---------------------------------------------------------------------------
// HMMA flash attention. Q/K fp16 hi-only (S single-product); P·V split-3.
// Output: fp16 hi only (Wo GEMM is split-2 on A).
// ---------------------------------------------------------------------------
#define FA_STG 49152
#define FA_SMEM (32768 + 3 * FA_STG)   // 180224

__global__ __launch_bounds__(256, 1) void flash_attn_hmma(
    const __half* __restrict__ qh, const __half* __restrict__ kh,
    const __half* __restrict__ vh, const __half* __restrict__ vl,
    __half* __restrict__ aoh)
{
    extern __shared__ char sm[];
    uint32_t sb = smem_to_u32(sm);
    int qb = (gridDim.x - 1) - blockIdx.x;
    int h = blockIdx.y, b = blockIdx.z;
    int g = h >> 2;
    int tid = threadIdx.x, lane = tid & 31, wid = tid >> 5;

    const size_t qbase  = ((size_t)(b * NH + h) * SEQ + qb * 128) * HD;
    const size_t kvbase = ((size_t)(b * NG + g) * SEQ) * HD;

    const uint32_t QH = sb;

    auto load_q = [&]() {
        #pragma unroll
        for (int t = 0; t < 8; t++) {
            int idx = tid + t * 256;
            int r = idx >> 4, c16 = idx & 15;
            uint32_t off = (uint32_t)((c16 >> 3) * 16384) +
                           SMEM_SWIZZLE_128B((uint32_t)(r * 128 + (c16 & 7) * 16));
            cp16(QH + off, qh + qbase + (size_t)r * HD + c16 * 8);
        }
    };
    auto load_kv = [&](int s, int kt) {
        uint32_t base = sb + 32768 + s * FA_STG;
        size_t kb = kvbase + (size_t)kt * 64 * HD;
        #pragma unroll
        for (int t = 0; t < 4; t++) {
            int idx = tid + t * 256;
            int r = idx >> 4, c16 = idx & 15;
            uint32_t off = (uint32_t)((c16 >> 3) * 8192) +
                           SMEM_SWIZZLE_128B((uint32_t)(r * 128 + (c16 & 7) * 16));
            size_t go = kb + (size_t)r * HD + c16 * 8;
            cp16(base + off,         kh + go);
            cp16(base + 16384 + off, vh + go);
            cp16(base + 32768 + off, vl + go);
        }
    };

    int nkt = 2 * qb + 2;
    load_q();
    if (0 < nkt) load_kv(0, 0);
    CP_COMMIT();
    if (1 < nkt) load_kv(1, 1);
    CP_COMMIT();
    if (2 < nkt) load_kv(2, 2);
    CP_COMMIT();

    float o[16][4];
    #pragma unroll
    for (int i = 0; i < 16; i++)
        #pragma unroll
        for (int j = 0; j < 4; j++) o[i][j] = 0.f;
    float mA = -1e30f, mB = -1e30f, lA = 0.f, lB = 0.f;

    int row0 = wid * 16;
    int sq = qb * 128 + row0;

    for (int kt = 0; kt < nkt; kt++) {
        CP_WAIT2();
        __syncthreads();

        int st = kt % 3;
        uint32_t KHb = sb + 32768 + st * FA_STG;
        uint32_t VHb = KHb + 16384, VLb = KHb + 32768;

        bool active = (kt * 64 <= sq + 15);
        if (active) {
            float sc[8][4];
            #pragma unroll
            for (int i = 0; i < 8; i++)
                #pragma unroll
                for (int j = 0; j < 4; j++) sc[i][j] = 0.f;

            int aro  = row0 + (lane & 15);
            int kro  = (lane & 7) + ((lane >> 4) << 3);
            int bkh  = ((lane >> 3) & 1) << 3;

            #pragma unroll
            for (int ks = 0; ks < 8; ks++) {
                int chk  = ks >> 2;
                int acol = (ks & 3) * 16 + ((lane >> 4) << 3);
                uint32_t aoff = (uint32_t)(chk * 16384) +
                                SMEM_SWIZZLE_128B((uint32_t)(aro * 128 + acol * 2));
                uint32_t ah[4];
                ldm4(ah, QH + aoff);

                int bcol = (ks & 3) * 16 + bkh;
                uint32_t bh[8][2];
                #pragma unroll
                for (int j2 = 0; j2 < 4; j2++) {
                    uint32_t boff = (uint32_t)(chk * 8192) +
                        SMEM_SWIZZLE_128B((uint32_t)((j2 * 16 + kro) * 128 + bcol * 2));
                    uint32_t r[4];
                    ldm4(r, KHb + boff);
                    bh[2*j2][0] = r[0]; bh[2*j2][1] = r[1];
                    bh[2*j2+1][0] = r[2]; bh[2*j2+1][1] = r[3];
                }
                #pragma unroll
                for (int nf = 0; nf < 8; nf++)
                    mma16816(sc[nf], ah, bh[nf]);
            }

            if (kt * 64 + 63 > sq) {
                int rA = sq + (lane >> 2), rB = rA + 8;
                #pragma unroll
                for (int nf = 0; nf < 8; nf++) {
                    int cbase = kt * 64 + nf * 8 + 2 * (lane & 3);
                    if (cbase     > rA) sc[nf][0] = -1e30f;
                    if (cbase + 1 > rA) sc[nf][1] = -1e30f;
                    if (cbase     > rB) sc[nf][2] = -1e30f;
                    if (cbase + 1 > rB) sc[nf][3] = -1e30f;
                }
            }

            float mtA = -1e30f, mtB = -1e30f;
            #pragma unroll
            for (int nf = 0; nf < 8; nf++) {
                mtA = fmaxf(mtA, fmaxf(sc[nf][0], sc[nf][1]));
                mtB = fmaxf(mtB, fmaxf(sc[nf][2], sc[nf][3]));
            }
            mtA = fmaxf(mtA, __shfl_xor_sync(0xffffffffu, mtA, 1));
            mtA = fmaxf(mtA, __shfl_xor_sync(0xffffffffu, mtA, 2));
            mtB = fmaxf(mtB, __shfl_xor_sync(0xffffffffu, mtB, 1));
            mtB = fmaxf(mtB, __shfl_xor_sync(0xffffffffu, mtB, 2));
            float nmA = fmaxf(mA, mtA), nmB = fmaxf(mB, mtB);
            float alA = __expf(mA - nmA), alB = __expf(mB - nmB);

            float suA = 0.f, suB = 0.f;
            #pragma unroll
            for (int nf = 0; nf < 8; nf++) {
                sc[nf][0] = __expf(sc[nf][0] - nmA); suA += sc[nf][0];
                sc[nf][1] = __expf(sc[nf][1] - nmA); suA += sc[nf][1];
                sc[nf][2] = __expf(sc[nf][2] - nmB); suB += sc[nf][2];
                sc[nf][3] = __expf(sc[nf][3] - nmB); suB += sc[nf][3];
            }
            suA += __shfl_xor_sync(0xffffffffu, suA, 1);
            suA += __shfl_xor_sync(0xffffffffu, suA, 2);
            suB += __shfl_xor_sync(0xffffffffu, suB, 1);
            suB += __shfl_xor_sync(0xffffffffu, suB, 2);
            lA = lA * alA + suA;
            lB = lB * alB + suB;
            mA = nmA; mB = nmB;
            #pragma unroll
            for (int nf = 0; nf < 16; nf++) {
                o[nf][0] *= alA; o[nf][1] *= alA;
                o[nf][2] *= alB; o[nf][3] *= alB;
            }

            int vro = (lane & 7) + (((lane >> 3) & 1) << 3);
            int vch = (lane >> 4) << 3;
            #pragma unroll
            for (int kf = 0; kf < 4; kf++) {
                uint32_t aPh[4], aPl[4];
                {
                    float p0 = sc[2*kf][0],   p1 = sc[2*kf][1];
                    float p2 = sc[2*kf][2],   p3 = sc[2*kf][3];
                    float p4 = sc[2*kf+1][0], p5 = sc[2*kf+1][1];
                    float p6 = sc[2*kf+1][2], p7 = sc[2*kf+1][3];
                    __half h0 = __float2half_rn(p0), h1 = __float2half_rn(p1);
                    __half h2 = __float2half_rn(p2), h3 = __float2half_rn(p3);
                    __half h4 = __float2half_rn(p4), h5 = __float2half_rn(p5);
                    __half h6 = __float2half_rn(p6), h7 = __float2half_rn(p7);
                    aPh[0] = pk2h(p0, p1); aPh[1] = pk2h(p2, p3);
                    aPh[2] = pk2h(p4, p5); aPh[3] = pk2h(p6, p7);
                    aPl[0] = pk2h(p0 - __half2float(h0), p1 - __half2float(h1));
                    aPl[1] = pk2h(p2 - __half2float(h2), p3 - __half2float(h3));
                    aPl[2] = pk2h(p4 - __half2float(h4), p5 - __half2float(h5));
                    aPl[3] = pk2h(p6 - __half2float(h6), p7 - __half2float(h7));
                }
                #pragma unroll
                for (int j2 = 0; j2 < 8; j2++) {
                    int chk  = j2 >> 2;
                    int wcol = (j2 & 3) * 16 + vch;
                    uint32_t voff = (uint32_t)(chk * 8192) +
                        SMEM_SWIZZLE_128B((uint32_t)((kf * 16 + vro) * 128 + wcol * 2));
                    uint32_t rh[4], rl[4];
                    ldm4t(rh, VHb + voff);
                    ldm4t(rl, VLb + voff);
                    uint32_t bh0[2] = {rh[0], rh[1]}, bh1[2] = {rh[2], rh[3]};
                    uint32_t bl0[2] = {rl[0], rl[1]}, bl1[2] = {rl[2], rl[3]};
                    mma16816(o[2*j2],   aPh, bh0);
                    mma16816(o[2*j2],   aPh, bl0);
                    mma16816(o[2*j2],   aPl, bh0);
                    mma16816(o[2*j2+1], aPh, bh1);
                    mma16816(o[2*j2+1], aPh, bl1);
                    mma16816(o[2*j2+1], aPl, bh1);
                }
            }
        }
        __syncthreads();

        if (kt + 3 < nkt) load_kv(kt % 3, kt + 3);
        CP_COMMIT();
    }

    float rlA = 1.0f / lA, rlB = 1.0f / lB;
    int sA = sq + (lane >> 2), sB = sA + 8;
    size_t oA = ((size_t)(b * SEQ + sA) * NH + h) * HD;
    size_t oB = ((size_t)(b * SEQ + sB) * NH + h) * HD;
    #pragma unroll
    for (int nf = 0; nf < 16; nf++) {
        int hd = nf * 8 + 2 * (lane & 3);
        *(__half2*)&aoh[oA + hd] = __floats2half2_rn(o[nf][0] * rlA, o[nf][1] * rlA);
        *(__half2*)&aoh[oB + hd] = __floats2half2_rn(o[nf][2] * rlB, o[nf][3] * rlB);
    }
}

// ---------------------------------------------------------------------------
extern "C" void kernel_launch(void* const* d_in, const int* in_sizes, int n_in,
                              void* d_out, int out_size)
{
    const float* x   = (const float*)d_in[0];
    const float* Wq  = (const float*)d_in[1];
    const float* bq  = (const float*)d_in[2];
    const float* Wk  = (const float*)d_in[3];
    const float* bk  = (const float*)d_in[4];
    const float* Wv  = (const float*)d_in[5];
    const float* bv  = (const float*)d_in[6];
    const float* Wo  = (const float*)d_in[7];
    const float* bo  = (const float*)d_in[8];
    const float* qns = (const float*)d_in[9];
    const float* kns = (const float*)d_in[10];
    float* out = (float*)d_out;

    __half *xhi, *xlo, *aoh, *wh, *wl, *woh, *wol;
    __half *qah, *kah, *vah, *val;
    float* bqkv;
    cudaGetSymbolAddress((void**)&xhi, g_xhi);
    cudaGetSymbolAddress((void**)&xlo, g_xlo);
    cudaGetSymbolAddress((void**)&aoh, g_aoh);
    cudaGetSymbolAddress((void**)&wh,  g_wh);
    cudaGetSymbolAddress((void**)&wl,  g_wl);
    cudaGetSymbolAddress((void**)&woh, g_woh);
    cudaGetSymbolAddress((void**)&wol, g_wol);
    cudaGetSymbolAddress((void**)&bqkv, g_bqkv);
    cudaGetSymbolAddress((void**)&qah, g_qah);
    cudaGetSymbolAddress((void**)&kah, g_kah);
    cudaGetSymbolAddress((void**)&vah, g_vah);
    cudaGetSymbolAddress((void**)&val, g_val);

    cudaFuncSetAttribute(gemm_qkv, cudaFuncAttributeMaxDynamicSharedMemorySize, GEMM_SMEM);
    cudaFuncSetAttribute(gemm_wo, cudaFuncAttributeMaxDynamicSharedMemorySize, WGEMM_SMEM);
    cudaFuncSetAttribute(flash_attn_hmma, cudaFuncAttributeMaxDynamicSharedMemorySize, FA_SMEM);

    const int n4 = MROWS * DIM / 4;

    // conversions (weights concatenated into one [3072,2048] hi/lo buffer)
    convert_split<<<(n4 + 255) / 256, 256>>>(x, xhi, xlo, n4);
    transpose_split<<<dim3(DIM / 32, DIM / 32), dim3(32, 8)>>>(Wq, wh, wl, DIM, DIM);
    transpose_split<<<dim3(KVD / 32, DIM / 32), dim3(32, 8)>>>(
        Wk, wh + (size_t)DIM * DIM, wl + (size_t)DIM * DIM, DIM, KVD);
    transpose_split<<<dim3(KVD / 32, DIM / 32), dim3(32, 8)>>>(
        Wv, wh + (size_t)(DIM + KVD) * DIM, wl + (size_t)(DIM + KVD) * DIM, DIM, KVD);
    transpose_split<<<dim3(DIM / 32, DIM / 32), dim3(32, 8)>>>(Wo, woh, wol, DIM, DIM);
    bias_concat<<<(NQKV + 255) / 256, 256>>>(bq, bk, bv, bqkv);

    // fused QKV projection + rmsnorm + rope (q carries full 1/hd)
    gemm_qkv<<<dim3(NQKV / BN, MROWS / BM), 256, GEMM_SMEM>>>(
        xhi, xlo, wh, wl, bqkv, qns, kns,
        qah, kah, vah, val);

    // attention (HMMA)
    flash_attn_hmma<<<dim3(SEQ / 128, NH, BATCH), 256, FA_SMEM>>>(
        qah, kah, vah, val, aoh);

    // output projection (split-2: A hi only)
    gemm_wo<<<dim3(DIM / BN, MROWS / BM), 256, WGEMM_SMEM>>>(
        aoh, woh, wol, bo, out, DIM);
}

// round 10
// speedup vs baseline: 1.8810x; 1.5527x over previous
#include <cuda_runtime.h>
#include <cuda_fp16.h>
#include <cstdint>
#include <math.h>

#define BATCH 16
#define SEQ   512
#define DIM   2048
#define NH    16
#define NG    4
#define HD    128
#define MROWS (BATCH*SEQ)   // 8192
#define KVD   (NG*HD)       // 512
#define NQKV  (DIM + 2*KVD) // 3072

// ---------------------------------------------------------------------------
// scratch (device globals — no allocation allowed)
// ---------------------------------------------------------------------------
__device__ __half g_xhi[(size_t)MROWS * DIM];
__device__ __half g_aoh[(size_t)MROWS * DIM];   // attn out fp16 (b,s,H,hd)
__device__ __half g_wh[(size_t)NQKV * DIM];     // [Wq^T; Wk^T; Wv^T] fp16 hi
__device__ __half g_woh[(size_t)DIM * DIM];
__device__ __half g_wol[(size_t)DIM * DIM];
__device__ float  g_bqkv[NQKV];                 // [bq; bk; bv]

// attention operand buffers, (b, head, s, hd) layout, plain fp16
__device__ __half g_qah[(size_t)MROWS * DIM];
__device__ __half g_kah[(size_t)MROWS * KVD];
__device__ __half g_vah[(size_t)MROWS * KVD];

// ---------------------------------------------------------------------------
// helpers
// ---------------------------------------------------------------------------
__device__ __forceinline__ uint32_t smem_to_u32(const void* p) {
    uint32_t a;
    asm("{ .reg .u64 t; cvta.to.shared.u64 t, %1; cvt.u32.u64 %0, t; }" : "=r"(a) : "l"(p));
    return a;
}
#define SMEM_SWIZZLE_128B(bo) ((bo) ^ (((bo) >> 3) & 0x70))

__device__ __forceinline__ void cp16(uint32_t s, const void* g) {
    asm volatile("cp.async.cg.shared.global [%0], [%1], 16;" :: "r"(s), "l"(g) : "memory");
}
#define CP_COMMIT() asm volatile("cp.async.commit_group;" ::: "memory")
#define CP_WAIT2()  asm volatile("cp.async.wait_group 2;" ::: "memory")
__device__ __forceinline__ void ldm4(uint32_t* r, uint32_t a) {
    asm volatile("ldmatrix.sync.aligned.m8n8.x4.shared.b16 {%0,%1,%2,%3}, [%4];"
                 : "=r"(r[0]), "=r"(r[1]), "=r"(r[2]), "=r"(r[3]) : "r"(a));
}
__device__ __forceinline__ void ldm4t(uint32_t* r, uint32_t a) {
    asm volatile("ldmatrix.sync.aligned.m8n8.x4.trans.shared.b16 {%0,%1,%2,%3}, [%4];"
                 : "=r"(r[0]), "=r"(r[1]), "=r"(r[2]), "=r"(r[3]) : "r"(a));
}
__device__ __forceinline__ void mma16816(float* d, const uint32_t* a, const uint32_t* b) {
    asm volatile(
        "mma.sync.aligned.m16n8k16.row.col.f32.f16.f16.f32 "
        "{%0,%1,%2,%3},{%4,%5,%6,%7},{%8,%9},{%0,%1,%2,%3};"
        : "+f"(d[0]), "+f"(d[1]), "+f"(d[2]), "+f"(d[3])
        : "r"(a[0]), "r"(a[1]), "r"(a[2]), "r"(a[3]), "r"(b[0]), "r"(b[1]));
}
__device__ __forceinline__ uint32_t pk2h(float a, float b) {
    __half2 h = __floats2half2_rn(a, b);
    return *reinterpret_cast<uint32_t*>(&h);
}

// ---------------------------------------------------------------------------
// convert fp32 -> fp16 (hi only)
// ---------------------------------------------------------------------------
__global__ __launch_bounds__(256) void convert_h(
    const float* __restrict__ in, __half* __restrict__ hi, int n4)
{
    int i = blockIdx.x * 256 + threadIdx.x;
    if (i >= n4) return;
    float4 v = ((const float4*)in)[i];
    uint2 ph;
    ph.x = pk2h(v.x, v.y); ph.y = pk2h(v.z, v.w);
    ((uint2*)hi)[i] = ph;
}

// ---------------------------------------------------------------------------
// W [K, N] fp32 -> W^T [N, K] fp16 (hi only)
// ---------------------------------------------------------------------------
__global__ __launch_bounds__(256) void transpose_h(
    const float* __restrict__ W, __half* __restrict__ Th, int K, int N)
{
    __shared__ float tile[32][33];
    int n0 = blockIdx.x * 32, k0 = blockIdx.y * 32;
    int tx = threadIdx.x, ty = threadIdx.y;   // 32 x 8
    #pragma unroll
    for (int j = ty; j < 32; j += 8)
        tile[j][tx] = W[(size_t)(k0 + j) * N + n0 + tx];
    __syncthreads();
    #pragma unroll
    for (int j = ty; j < 32; j += 8)
        Th[(size_t)(n0 + j) * K + k0 + tx] = __float2half_rn(tile[tx][j]);
}

// ---------------------------------------------------------------------------
// W [K, N] fp32 -> W^T [N, K] fp16 hi/lo (for Wo only)
// ---------------------------------------------------------------------------
__global__ __launch_bounds__(256) void transpose_split(
    const float* __restrict__ W, __half* __restrict__ Th,
    __half* __restrict__ Tl, int K, int N)
{
    __shared__ float tile[32][33];
    int n0 = blockIdx.x * 32, k0 = blockIdx.y * 32;
    int tx = threadIdx.x, ty = threadIdx.y;
    #pragma unroll
    for (int j = ty; j < 32; j += 8)
        tile[j][tx] = W[(size_t)(k0 + j) * N + n0 + tx];
    __syncthreads();
    #pragma unroll
    for (int j = ty; j < 32; j += 8) {
        float v = tile[tx][j];
        __half h = __float2half_rn(v);
        float r = v - __half2float(h);
        size_t o = (size_t)(n0 + j) * K + k0 + tx;
        Th[o] = h;
        Tl[o] = __float2half_rn(r);
    }
}

__global__ __launch_bounds__(256) void bias_concat(
    const float* __restrict__ bq, const float* __restrict__ bk,
    const float* __restrict__ bv, float* __restrict__ o)
{
    int i = blockIdx.x * 256 + threadIdx.x;
    if (i < DIM) o[i] = bq[i];
    else if (i < DIM + KVD) o[i] = bk[i - DIM];
    else if (i < NQKV) o[i] = bv[i - DIM - KVD];
}

// ---------------------------------------------------------------------------
// tile config
// ---------------------------------------------------------------------------
#define BM 128
#define BN 128
#define BK 64
#define NCH (DIM / BK)   // 32

// qkv GEMM: plain fp16, stage = AH 16K + BH 16K
#define QSTG_BYTES 32768
#define Q_OFF_AH 0
#define Q_OFF_BH 16384
#define QGEMM_SMEM (3 * QSTG_BYTES)   // 98304

// Wo GEMM: split-2 (A hi only; W hi+lo), stage = AH + BH + BL
#define WSTG_BYTES 49152
#define W_OFF_AH 0
#define W_OFF_BH 16384
#define W_OFF_BL 32768
#define WGEMM_SMEM (3 * WSTG_BYTES)   // 147456

// ---------------------------------------------------------------------------
// Fused QKV GEMM + RMSNorm + RoPE epilogue. Plain fp16 throughout.
// ---------------------------------------------------------------------------
__global__ __launch_bounds__(256, 1) void gemm_qkv(
    const __half* __restrict__ Ahg, const __half* __restrict__ Bhg,
    const float* __restrict__ bias,
    const float* __restrict__ qns, const float* __restrict__ kns,
    __half* __restrict__ qah, __half* __restrict__ kah,
    __half* __restrict__ vah)
{
    extern __shared__ char sm[];
    uint32_t sb = smem_to_u32(sm);
    int tid = threadIdx.x, lane = tid & 31, wid = tid >> 5;
    int wm = wid & 1, wn = wid >> 1;
    int bx = blockIdx.x * BN, by = blockIdx.y * BM;

    auto load_stage = [&](int s, int kt) {
        int k0 = kt * BK;
        uint32_t base = sb + s * QSTG_BYTES;
        #pragma unroll
        for (int t = 0; t < 4; t++) {
            int idx = tid + t * 256;
            int r = idx >> 3, c16 = idx & 7;
            uint32_t swz = SMEM_SWIZZLE_128B((uint32_t)(r * 128 + c16 * 16));
            cp16(base + Q_OFF_AH + swz, Ahg + (size_t)(by + r) * DIM + k0 + c16 * 8);
            cp16(base + Q_OFF_BH + swz, Bhg + (size_t)(bx + r) * DIM + k0 + c16 * 8);
        }
    };

    float d[4][4][4];
    #pragma unroll
    for (int i = 0; i < 4; i++)
        #pragma unroll
        for (int j = 0; j < 4; j++)
            #pragma unroll
            for (int q = 0; q < 4; q++) d[i][j][q] = 0.f;

    load_stage(0, 0); CP_COMMIT();
    load_stage(1, 1); CP_COMMIT();
    load_stage(2, 2); CP_COMMIT();

    for (int kt = 0; kt < NCH; kt++) {
        CP_WAIT2();
        __syncthreads();

        int s = kt % 3;
        uint32_t base = sb + s * QSTG_BYTES;
        int arow = wm * 64 + (lane & 15);
        int bro  = wn * 32 + (lane & 7) + ((lane >> 4) << 3);
        int bkh  = ((lane >> 3) & 1) << 3;

        #pragma unroll
        for (int ks = 0; ks < 4; ks++) {
            int acol = ks * 16 + ((lane >> 4) << 3);
            uint32_t ah[4][4], bh[4][2];
            #pragma unroll
            for (int mf = 0; mf < 4; mf++) {
                uint32_t off = SMEM_SWIZZLE_128B(
                    (uint32_t)((arow + mf * 16) * 128 + acol * 2));
                ldm4(ah[mf], base + Q_OFF_AH + off);
            }
            #pragma unroll
            for (int j2 = 0; j2 < 2; j2++) {
                uint32_t off = SMEM_SWIZZLE_128B(
                    (uint32_t)((bro + j2 * 16) * 128 + (ks * 16 + bkh) * 2));
                uint32_t r[4];
                ldm4(r, base + Q_OFF_BH + off);
                bh[j2 * 2][0] = r[0]; bh[j2 * 2][1] = r[1];
                bh[j2 * 2 + 1][0] = r[2]; bh[j2 * 2 + 1][1] = r[3];
            }
            #pragma unroll
            for (int mf = 0; mf < 4; mf++)
                #pragma unroll
                for (int nf = 0; nf < 4; nf++)
                    mma16816(d[mf][nf], ah[mf], bh[nf]);
        }
        __syncthreads();

        if (kt + 3 < NCH) load_stage(s, kt + 3);
        CP_COMMIT();
    }

    // ---------------- fused epilogue ----------------
    int hb = blockIdx.x;             // 0..23
    bool needs_norm = (hb < 20);     // q and k blocks

    int c0 = wn * 32 + (lane & 3) * 2;
    #pragma unroll
    for (int mf = 0; mf < 4; mf++)
        #pragma unroll
        for (int nf = 0; nf < 4; nf++) {
            int c = c0 + nf * 8;
            float b0 = bias[bx + c], b1 = bias[bx + c + 1];
            d[mf][nf][0] += b0; d[mf][nf][1] += b1;
            d[mf][nf][2] += b0; d[mf][nf][3] += b1;
        }

    float* ss = (float*)sm;          // [128][4] partial row sums
    __syncthreads();

    if (needs_norm) {
        #pragma unroll
        for (int mf = 0; mf < 4; mf++) {
            float pA = 0.f, pB = 0.f;
            #pragma unroll
            for (int nf = 0; nf < 4; nf++) {
                pA += d[mf][nf][0] * d[mf][nf][0] + d[mf][nf][1] * d[mf][nf][1];
                pB += d[mf][nf][2] * d[mf][nf][2] + d[mf][nf][3] * d[mf][nf][3];
            }
            pA += __shfl_xor_sync(0xffffffffu, pA, 1);
            pA += __shfl_xor_sync(0xffffffffu, pA, 2);
            pB += __shfl_xor_sync(0xffffffffu, pB, 1);
            pB += __shfl_xor_sync(0xffffffffu, pB, 2);
            if ((lane & 3) == 0) {
                int lr = wm * 64 + mf * 16 + (lane >> 2);
                ss[lr * 4 + wn] = pA;
                ss[(lr + 8) * 4 + wn] = pB;
            }
        }
    }
    __syncthreads();

    const float* nsc = (hb < 16) ? qns : kns;
    float esc = (hb < 16) ? (1.0f / (float)HD) : 1.0f;
    __half* oph;
    int headmul;
    if (hb < 16)      { oph = qah; headmul = NH; }
    else if (hb < 20) { oph = kah; headmul = NG; }
    else              { oph = vah; headmul = NG; }
    int head = (hb < 16) ? hb : ((hb < 20) ? hb - 16 : hb - 20);

    #pragma unroll
    for (int mf = 0; mf < 4; mf++) {
        int lr = wm * 64 + mf * 16 + (lane >> 2);
        int rowA = by + lr, rowB = rowA + 8;
        int posA = rowA & (SEQ - 1), posB = rowB & (SEQ - 1);
        int bA = rowA >> 9, bB = rowB >> 9;
        float rinvA = 1.f, rinvB = 1.f;
        if (needs_norm) {
            float sA = ss[lr * 4] + ss[lr * 4 + 1] + ss[lr * 4 + 2] + ss[lr * 4 + 3];
            float sB = ss[(lr + 8) * 4] + ss[(lr + 8) * 4 + 1] +
                       ss[(lr + 8) * 4 + 2] + ss[(lr + 8) * 4 + 3];
            rinvA = rsqrtf(sA * (1.0f / HD) + 1e-6f);
            rinvB = rsqrtf(sB * (1.0f / HD) + 1e-6f);
        }
        size_t obA = ((size_t)(bA * headmul + head) * SEQ + posA) * HD;
        size_t obB = ((size_t)(bB * headmul + head) * SEQ + posB) * HD;
        #pragma unroll
        for (int nf = 0; nf < 4; nf++) {
            int c = c0 + nf * 8;
            if (needs_norm) {
                float sc0 = nsc[c], sc1 = nsc[c + 1];
                float invf = __expf(-(float)(c >> 1) * (9.210340371976184f / 64.0f));
                float snA, csA, snB, csB;
                __sincosf((float)posA * invf, &snA, &csA);
                __sincosf((float)posB * invf, &snB, &csB);
                float xA1 = d[mf][nf][0] * rinvA * sc0;
                float xA2 = d[mf][nf][1] * rinvA * sc1;
                float xB1 = d[mf][nf][2] * rinvB * sc0;
                float xB2 = d[mf][nf][3] * rinvB * sc1;
                *(__half2*)&oph[obA + c] = __floats2half2_rn(
                    (xA1 * csA - xA2 * snA) * esc, (xA1 * snA + xA2 * csA) * esc);
                *(__half2*)&oph[obB + c] = __floats2half2_rn(
                    (xB1 * csB - xB2 * snB) * esc, (xB1 * snB + xB2 * csB) * esc);
            } else {
                *(__half2*)&vah[obA + c] = __floats2half2_rn(d[mf][nf][0], d[mf][nf][1]);
                *(__half2*)&vah[obB + c] = __floats2half2_rn(d[mf][nf][2], d[mf][nf][3]);
            }
        }
    }
}

// ---------------------------------------------------------------------------
// Wo GEMM: split-2 (A fp16 hi only; W hi+lo), bias, fp32 output.
// ---------------------------------------------------------------------------
__global__ __launch_bounds__(256, 1) void gemm_wo(
    const __half* __restrict__ Ahg,
    const __half* __restrict__ Bhg, const __half* __restrict__ Blg,
    const float* __restrict__ bias, float* __restrict__ C, int N)
{
    extern __shared__ char sm[];
    uint32_t sb = smem_to_u32(sm);
    int tid = threadIdx.x, lane = tid & 31, wid = tid >> 5;
    int wm = wid & 1, wn = wid >> 1;
    int bx = blockIdx.x * BN, by = blockIdx.y * BM;

    auto load_stage = [&](int s, int kt) {
        int k0 = kt * BK;
        uint32_t base = sb + s * WSTG_BYTES;
        #pragma unroll
        for (int t = 0; t < 4; t++) {
            int idx = tid + t * 256;
            int r = idx >> 3, c16 = idx & 7;
            uint32_t swz = SMEM_SWIZZLE_128B((uint32_t)(r * 128 + c16 * 16));
            size_t ga = (size_t)(by + r) * DIM + k0 + c16 * 8;
            size_t gb = (size_t)(bx + r) * DIM + k0 + c16 * 8;
            cp16(base + W_OFF_AH + swz, Ahg + ga);
            cp16(base + W_OFF_BH + swz, Bhg + gb);
            cp16(base + W_OFF_BL + swz, Blg + gb);
        }
    };

    float d[4][4][4];
    #pragma unroll
    for (int i = 0; i < 4; i++)
        #pragma unroll
        for (int j = 0; j < 4; j++)
            #pragma unroll
            for (int q = 0; q < 4; q++) d[i][j][q] = 0.f;

    load_stage(0, 0); CP_COMMIT();
    load_stage(1, 1); CP_COMMIT();
    load_stage(2, 2); CP_COMMIT();

    for (int kt = 0; kt < NCH; kt++) {
        CP_WAIT2();
        __syncthreads();

        int s = kt % 3;
        uint32_t base = sb + s * WSTG_BYTES;
        int arow = wm * 64 + (lane & 15);
        int bro  = wn * 32 + (lane & 7) + ((lane >> 4) << 3);
        int bkh  = ((lane >> 3) & 1) << 3;

        #pragma unroll
        for (int ks = 0; ks < 4; ks++) {
            int acol = ks * 16 + ((lane >> 4) << 3);
            uint32_t ah[4][4], bh[4][2], bl[4][2];
            #pragma unroll
            for (int mf = 0; mf < 4; mf++) {
                uint32_t off = SMEM_SWIZZLE_128B(
                    (uint32_t)((arow + mf * 16) * 128 + acol * 2));
                ldm4(ah[mf], base + W_OFF_AH + off);
            }
            #pragma unroll
            for (int j2 = 0; j2 < 2; j2++) {
                uint32_t off = SMEM_SWIZZLE_128B(
                    (uint32_t)((bro + j2 * 16) * 128 + (ks * 16 + bkh) * 2));
                uint32_t r[4];
                ldm4(r, base + W_OFF_BH + off);
                bh[j2 * 2][0] = r[0]; bh[j2 * 2][1] = r[1];
                bh[j2 * 2 + 1][0] = r[2]; bh[j2 * 2 + 1][1] = r[3];
                ldm4(r, base + W_OFF_BL + off);
                bl[j2 * 2][0] = r[0]; bl[j2 * 2][1] = r[1];
                bl[j2 * 2 + 1][0] = r[2]; bl[j2 * 2 + 1][1] = r[3];
            }
            #pragma unroll
            for (int mf = 0; mf < 4; mf++)
                #pragma unroll
                for (int nf = 0; nf < 4; nf++) {
                    mma16816(d[mf][nf], ah[mf], bh[nf]);
                    mma16816(d[mf][nf], ah[mf], bl[nf]);
                }
        }
        __syncthreads();

        if (kt + 3 < NCH) load_stage(s, kt + 3);
        CP_COMMIT();
    }

    int row0 = by + wm * 64 + (lane >> 2);
    int col0 = bx + wn * 32 + (lane & 3) * 2;
    #pragma unroll
    for (int mf = 0; mf < 4; mf++)
        #pragma unroll
        for (int nf = 0; nf < 4; nf++) {
            int r = row0 + mf * 16;
            int c = col0 + nf * 8;
            float b0 = bias[c], b1 = bias[c + 1];
            float2 v0 = make_float2(d[mf][nf][0] + b0, d[mf][nf][1] + b1);
            float2 v1 = make_float2(d[mf][nf][2] + b0, d[mf][nf][3] + b1);
            *(float2*)&C[(size_t)r * N + c] = v0;
            *(float2*)&C[(size_t)(r + 8) * N + c] = v1;
        }
}

// ---------------------------------------------------------------------------
// HMMA flash attention. All operands plain fp16, single-product MMAs.
// smem: Q 32KB + 3 x (K 16K + V 16K) = 128KB
// ---------------------------------------------------------------------------
#define FA_STG 32768
#define FA_SMEM (32768 + 3 * FA_STG)   // 131072

__global__ __launch_bounds__(256, 1) void flash_attn_hmma(
    const __half* __restrict__ qh, const __half* __restrict__ kh,
    const __half* __restrict__ vh, __half* __restrict__ aoh)
{
    extern __shared__ char sm[];
    uint32_t sb = smem_to_u32(sm);
    int qb = (gridDim.x - 1) - blockIdx.x;
    int h = blockIdx.y, b = blockIdx.z;
    int g = h >> 2;
    int tid = threadIdx.x, lane = tid & 31, wid = tid >> 5;

    const size_t qbase  = ((size_t)(b * NH + h) * SEQ + qb * 128) * HD;
    const size_t kvbase = ((size_t)(b * NG + g) * SEQ) * HD;

    const uint32_t QH = sb;

    auto load_q = [&]() {
        #pragma unroll
        for (int t = 0; t < 8; t++) {
            int idx = tid + t * 256;
            int r = idx >> 4, c16 = idx & 15;
            uint32_t off = (uint32_t)((c16 >> 3) * 16384) +
                           SMEM_SWIZZLE_128B((uint32_t)(r * 128 + (c16 & 7) * 16));
            cp16(QH + off, qh + qbase + (size_t)r * HD + c16 * 8);
        }
    };
    auto load_kv = [&](int s, int kt) {
        uint32_t base = sb + 32768 + s * FA_STG;
        size_t kb = kvbase + (size_t)kt * 64 * HD;
        #pragma unroll
        for (int t = 0; t < 4; t++) {
            int idx = tid + t * 256;
            int r = idx >> 4, c16 = idx & 15;
            uint32_t off = (uint32_t)((c16 >> 3) * 8192) +
                           SMEM_SWIZZLE_128B((uint32_t)(r * 128 + (c16 & 7) * 16));
            size_t go = kb + (size_t)r * HD + c16 * 8;
            cp16(base + off,         kh + go);
            cp16(base + 16384 + off, vh + go);
        }
    };

    int nkt = 2 * qb + 2;
    load_q();
    if (0 < nkt) load_kv(0, 0);
    CP_COMMIT();
    if (1 < nkt) load_kv(1, 1);
    CP_COMMIT();
    if (2 < nkt) load_kv(2, 2);
    CP_COMMIT();

    float o[16][4];
    #pragma unroll
    for (int i = 0; i < 16; i++)
        #pragma unroll
        for (int j = 0; j < 4; j++) o[i][j] = 0.f;
    float mA = -1e30f, mB = -1e30f, lA = 0.f, lB = 0.f;

    int row0 = wid * 16;
    int sq = qb * 128 + row0;

    for (int kt = 0; kt < nkt; kt++) {
        CP_WAIT2();
        __syncthreads();

        int st = kt % 3;
        uint32_t KHb = sb + 32768 + st * FA_STG;
        uint32_t VHb = KHb + 16384;

        bool active = (kt * 64 <= sq + 15);
        if (active) {
            float sc[8][4];
            #pragma unroll
            for (int i = 0; i < 8; i++)
                #pragma unroll
                for (int j = 0; j < 4; j++) sc[i][j] = 0.f;

            int aro  = row0 + (lane & 15);
            int kro  = (lane & 7) + ((lane >> 4) << 3);
            int bkh  = ((lane >> 3) & 1) << 3;

            // S = Q K^T
            #pragma unroll
            for (int ks = 0; ks < 8; ks++) {
                int chk  = ks >> 2;
                int acol = (ks & 3) * 16 + ((lane >> 4) << 3);
                uint32_t aoff = (uint32_t)(chk * 16384) +
                                SMEM_SWIZZLE_128B((uint32_t)(aro * 128 + acol * 2));
                uint32_t ah[4];
                ldm4(ah, QH + aoff);

                int bcol = (ks & 3) * 16 + bkh;
                uint32_t bh[8][2];
                #pragma unroll
                for (int j2 = 0; j2 < 4; j2++) {
                    uint32_t boff = (uint32_t)(chk * 8192) +
                        SMEM_SWIZZLE_128B((uint32_t)((j2 * 16 + kro) * 128 + bcol * 2));
                    uint32_t r[4];
                    ldm4(r, KHb + boff);
                    bh[2*j2][0] = r[0]; bh[2*j2][1] = r[1];
                    bh[2*j2+1][0] = r[2]; bh[2*j2+1][1] = r[3];
                }
                #pragma unroll
                for (int nf = 0; nf < 8; nf++)
                    mma16816(sc[nf], ah, bh[nf]);
            }

            if (kt * 64 + 63 > sq) {
                int rA = sq + (lane >> 2), rB = rA + 8;
                #pragma unroll
                for (int nf = 0; nf < 8; nf++) {
                    int cbase = kt * 64 + nf * 8 + 2 * (lane & 3);
                    if (cbase     > rA) sc[nf][0] = -1e30f;
                    if (cbase + 1 > rA) sc[nf][1] = -1e30f;
                    if (cbase     > rB) sc[nf][2] = -1e30f;
                    if (cbase + 1 > rB) sc[nf][3] = -1e30f;
                }
            }

            float mtA = -1e30f, mtB = -1e30f;
            #pragma unroll
            for (int nf = 0; nf < 8; nf++) {
                mtA = fmaxf(mtA, fmaxf(sc[nf][0], sc[nf][1]));
                mtB = fmaxf(mtB, fmaxf(sc[nf][2], sc[nf][3]));
            }
            mtA = fmaxf(mtA, __shfl_xor_sync(0xffffffffu, mtA, 1));
            mtA = fmaxf(mtA, __shfl_xor_sync(0xffffffffu, mtA, 2));
            mtB = fmaxf(mtB, __shfl_xor_sync(0xffffffffu, mtB, 1));
            mtB = fmaxf(mtB, __shfl_xor_sync(0xffffffffu, mtB, 2));
            float nmA = fmaxf(mA, mtA), nmB = fmaxf(mB, mtB);
            float alA = __expf(mA - nmA), alB = __expf(mB - nmB);

            float suA = 0.f, suB = 0.f;
            #pragma unroll
            for (int nf = 0; nf < 8; nf++) {
                sc[nf][0] = __expf(sc[nf][0] - nmA); suA += sc[nf][0];
                sc[nf][1] = __expf(sc[nf][1] - nmA); suA += sc[nf][1];
                sc[nf][2] = __expf(sc[nf][2] - nmB); suB += sc[nf][2];
                sc[nf][3] = __expf(sc[nf][3] - nmB); suB += sc[nf][3];
            }
            suA += __shfl_xor_sync(0xffffffffu, suA, 1);
            suA += __shfl_xor_sync(0xffffffffu, suA, 2);
            suB += __shfl_xor_sync(0xffffffffu, suB, 1);
            suB += __shfl_xor_sync(0xffffffffu, suB, 2);
            lA = lA * alA + suA;
            lB = lB * alB + suB;
            mA = nmA; mB = nmB;
            #pragma unroll
            for (int nf = 0; nf < 16; nf++) {
                o[nf][0] *= alA; o[nf][1] *= alA;
                o[nf][2] *= alB; o[nf][3] *= alB;
            }

            // O += P V (plain fp16)
            int vro = (lane & 7) + (((lane >> 3) & 1) << 3);
            int vch = (lane >> 4) << 3;
            #pragma unroll
            for (int kf = 0; kf < 4; kf++) {
                uint32_t aPh[4];
                aPh[0] = pk2h(sc[2*kf][0],   sc[2*kf][1]);
                aPh[1] = pk2h(sc[2*kf][2],   sc[2*kf][3]);
                aPh[2] = pk2h(sc[2*kf+1][0], sc[2*kf+1][1]);
                aPh[3] = pk2h(sc[2*kf+1][2], sc[2*kf+1][3]);
                #pragma unroll
                for (int j2 = 0; j2 < 8; j2++) {
                    int chk  = j2 >> 2;
                    int wcol = (j2 & 3) * 16 + vch;
                    uint32_t voff = (uint32_t)(chk * 8192) +
                        SMEM_SWIZZLE_128B((uint32_t)((kf * 16 + vro) * 128 + wcol * 2));
                    uint32_t rh[4];
                    ldm4t(rh, VHb + voff);
                    uint32_t bh0[2] = {rh[0], rh[1]}, bh1[2] = {rh[2], rh[3]};
                    mma16816(o[2*j2],   aPh, bh0);
                    mma16816(o[2*j2+1], aPh, bh1);
                }
            }
        }
        __syncthreads();

        if (kt + 3 < nkt) load_kv(kt % 3, kt + 3);
        CP_COMMIT();
    }

    float rlA = 1.0f / lA, rlB = 1.0f / lB;
    int sA = sq + (lane >> 2), sB = sA + 8;
    size_t oA = ((size_t)(b * SEQ + sA) * NH + h) * HD;
    size_t oB = ((size_t)(b * SEQ + sB) * NH + h) * HD;
    #pragma unroll
    for (int nf = 0; nf < 16; nf++) {
        int hd = nf * 8 + 2 * (lane & 3);
        *(__half2*)&aoh[oA + hd] = __floats2half2_rn(o[nf][0] * rlA, o[nf][1] * rlA);
        *(__half2*)&aoh[oB + hd] = __floats2half2_rn(o[nf][2] * rlB, o[nf][3] * rlB);
    }
}

// ---------------------------------------------------------------------------
extern "C" void kernel_launch(void* const* d_in, const int* in_sizes, int n_in,
                              void* d_out, int out_size)
{
    const float* x   = (const float*)d_in[0];
    const float* Wq  = (const float*)d_in[1];
    const float* bq  = (const float*)d_in[2];
    const float* Wk  = (const float*)d_in[3];
    const float* bk  = (const float*)d_in[4];
    const float* Wv  = (const float*)d_in[5];
    const float* bv  = (const float*)d_in[6];
    const float* Wo  = (const float*)d_in[7];
    const float* bo  = (const float*)d_in[8];
    const float* qns = (const float*)d_in[9];
    const float* kns = (const float*)d_in[10];
    float* out = (float*)d_out;

    __half *xhi, *aoh, *wh, *woh, *wol;
    __half *qah, *kah, *vah;
    float* bqkv;
    cudaGetSymbolAddress((void**)&xhi, g_xhi);
    cudaGetSymbolAddress((void**)&aoh, g_aoh);
    cudaGetSymbolAddress((void**)&wh,  g_wh);
    cudaGetSymbolAddress((void**)&woh, g_woh);
    cudaGetSymbolAddress((void**)&wol, g_wol);
    cudaGetSymbolAddress((void**)&bqkv, g_bqkv);
    cudaGetSymbolAddress((void**)&qah, g_qah);
    cudaGetSymbolAddress((void**)&kah, g_kah);
    cudaGetSymbolAddress((void**)&vah, g_vah);

    cudaFuncSetAttribute(gemm_qkv, cudaFuncAttributeMaxDynamicSharedMemorySize, QGEMM_SMEM);
    cudaFuncSetAttribute(gemm_wo, cudaFuncAttributeMaxDynamicSharedMemorySize, WGEMM_SMEM);
    cudaFuncSetAttribute(flash_attn_hmma, cudaFuncAttributeMaxDynamicSharedMemorySize, FA_SMEM);

    const int n4 = MROWS * DIM / 4;

    // conversions
    convert_h<<<(n4 + 255) / 256, 256>>>(x, xhi, n4);
    transpose_h<<<dim3(DIM / 32, DIM / 32), dim3(32, 8)>>>(Wq, wh, DIM, DIM);
    transpose_h<<<dim3(KVD / 32, DIM / 32), dim3(32, 8)>>>(
        Wk, wh + (size_t)DIM * DIM, DIM, KVD);
    transpose_h<<<dim3(KVD / 32, DIM / 32), dim3(32, 8)>>>(
        Wv, wh + (size_t)(DIM + KVD) * DIM, DIM, KVD);
    transpose_split<<<dim3(DIM / 32, DIM / 32), dim3(32, 8)>>>(Wo, woh, wol, DIM, DIM);
    bias_concat<<<(NQKV + 255) / 256, 256>>>(bq, bk, bv, bqkv);

    // fused QKV projection + rmsnorm + rope (q carries full 1/hd)
    gemm_qkv<<<dim3(NQKV / BN, MROWS / BM), 256, QGEMM_SMEM>>>(
        xhi, wh, bqkv, qns, kns, qah, kah, vah);

    // attention (HMMA, plain fp16)
    flash_attn_hmma<<<dim3(SEQ / 128, NH, BATCH), 256, FA_SMEM>>>(
        qah, kah, vah, aoh);

    // output projection (split-2: A hi only, W hi+lo)
    gemm_wo<<<dim3(DIM / BN, MROWS / BM), 256, WGEMM_SMEM>>>(
        aoh, woh, wol, bo, out, DIM);
}

// round 11
// speedup vs baseline: 2.2562x; 1.1994x over previous
#include <cuda_runtime.h>
#include <cuda_fp16.h>
#include <cstdint>
#include <math.h>

#define BATCH 16
#define SEQ   512
#define DIM   2048
#define NH    16
#define NG    4
#define HD    128
#define MROWS (BATCH*SEQ)   // 8192
#define KVD   (NG*HD)       // 512
#define NQKV  (DIM + 2*KVD) // 3072

// ---------------------------------------------------------------------------
// scratch (device globals — no allocation allowed)
// ---------------------------------------------------------------------------
__device__ __half g_xhi[(size_t)MROWS * DIM];
__device__ __half g_aoh[(size_t)MROWS * DIM];   // attn out fp16 (b,s,H,hd)
__device__ __half g_wh[(size_t)NQKV * DIM];     // [Wq^T; Wk^T; Wv^T] fp16
__device__ __half g_woh[(size_t)DIM * DIM];     // Wo^T fp16
__device__ float  g_bqkv[NQKV];                 // [bq; bk; bv]

// attention operand buffers, (b, head, s, hd) layout, plain fp16
__device__ __half g_qah[(size_t)MROWS * DIM];
__device__ __half g_kah[(size_t)MROWS * KVD];
__device__ __half g_vah[(size_t)MROWS * KVD];

// ---------------------------------------------------------------------------
// helpers
// ---------------------------------------------------------------------------
__device__ __forceinline__ uint32_t smem_to_u32(const void* p) {
    uint32_t a;
    asm("{ .reg .u64 t; cvta.to.shared.u64 t, %1; cvt.u32.u64 %0, t; }" : "=r"(a) : "l"(p));
    return a;
}
#define SMEM_SWIZZLE_128B(bo) ((bo) ^ (((bo) >> 3) & 0x70))

__device__ __forceinline__ void cp16(uint32_t s, const void* g) {
    asm volatile("cp.async.cg.shared.global [%0], [%1], 16;" :: "r"(s), "l"(g) : "memory");
}
#define CP_COMMIT() asm volatile("cp.async.commit_group;" ::: "memory")
#define CP_WAIT2()  asm volatile("cp.async.wait_group 2;" ::: "memory")
__device__ __forceinline__ void ldm4(uint32_t* r, uint32_t a) {
    asm volatile("ldmatrix.sync.aligned.m8n8.x4.shared.b16 {%0,%1,%2,%3}, [%4];"
                 : "=r"(r[0]), "=r"(r[1]), "=r"(r[2]), "=r"(r[3]) : "r"(a));
}
__device__ __forceinline__ void ldm4t(uint32_t* r, uint32_t a) {
    asm volatile("ldmatrix.sync.aligned.m8n8.x4.trans.shared.b16 {%0,%1,%2,%3}, [%4];"
                 : "=r"(r[0]), "=r"(r[1]), "=r"(r[2]), "=r"(r[3]) : "r"(a));
}
__device__ __forceinline__ void mma16816(float* d, const uint32_t* a, const uint32_t* b) {
    asm volatile(
        "mma.sync.aligned.m16n8k16.row.col.f32.f16.f16.f32 "
        "{%0,%1,%2,%3},{%4,%5,%6,%7},{%8,%9},{%0,%1,%2,%3};"
        : "+f"(d[0]), "+f"(d[1]), "+f"(d[2]), "+f"(d[3])
        : "r"(a[0]), "r"(a[1]), "r"(a[2]), "r"(a[3]), "r"(b[0]), "r"(b[1]));
}
__device__ __forceinline__ uint32_t pk2h(float a, float b) {
    __half2 h = __floats2half2_rn(a, b);
    return *reinterpret_cast<uint32_t*>(&h);
}

// ---------------------------------------------------------------------------
// convert fp32 -> fp16
// ---------------------------------------------------------------------------
__global__ __launch_bounds__(256) void convert_h(
    const float* __restrict__ in, __half* __restrict__ hi, int n4)
{
    int i = blockIdx.x * 256 + threadIdx.x;
    if (i >= n4) return;
    float4 v = ((const float4*)in)[i];
    uint2 ph;
    ph.x = pk2h(v.x, v.y); ph.y = pk2h(v.z, v.w);
    ((uint2*)hi)[i] = ph;
}

// ---------------------------------------------------------------------------
// W [K, N] fp32 -> W^T [N, K] fp16
// ---------------------------------------------------------------------------
__global__ __launch_bounds__(256) void transpose_h(
    const float* __restrict__ W, __half* __restrict__ Th, int K, int N)
{
    __shared__ float tile[32][33];
    int n0 = blockIdx.x * 32, k0 = blockIdx.y * 32;
    int tx = threadIdx.x, ty = threadIdx.y;   // 32 x 8
    #pragma unroll
    for (int j = ty; j < 32; j += 8)
        tile[j][tx] = W[(size_t)(k0 + j) * N + n0 + tx];
    __syncthreads();
    #pragma unroll
    for (int j = ty; j < 32; j += 8)
        Th[(size_t)(n0 + j) * K + k0 + tx] = __float2half_rn(tile[tx][j]);
}

__global__ __launch_bounds__(256) void bias_concat(
    const float* __restrict__ bq, const float* __restrict__ bk,
    const float* __restrict__ bv, float* __restrict__ o)
{
    int i = blockIdx.x * 256 + threadIdx.x;
    if (i < DIM) o[i] = bq[i];
    else if (i < DIM + KVD) o[i] = bk[i - DIM];
    else if (i < NQKV) o[i] = bv[i - DIM - KVD];
}

// ---------------------------------------------------------------------------
// tile config — plain fp16 GEMM, stage = AH 16K + BH 16K, 3-stage
// ---------------------------------------------------------------------------
#define BM 128
#define BN 128
#define BK 64
#define NCH (DIM / BK)   // 32
#define QSTG_BYTES 32768
#define Q_OFF_AH 0
#define Q_OFF_BH 16384
#define QGEMM_SMEM (3 * QSTG_BYTES)   // 98304

// ---------------------------------------------------------------------------
// Fused QKV GEMM + RMSNorm + RoPE epilogue. Plain fp16 throughout.
// ---------------------------------------------------------------------------
__global__ __launch_bounds__(256, 1) void gemm_qkv(
    const __half* __restrict__ Ahg, const __half* __restrict__ Bhg,
    const float* __restrict__ bias,
    const float* __restrict__ qns, const float* __restrict__ kns,
    __half* __restrict__ qah, __half* __restrict__ kah,
    __half* __restrict__ vah)
{
    extern __shared__ char sm[];
    uint32_t sb = smem_to_u32(sm);
    int tid = threadIdx.x, lane = tid & 31, wid = tid >> 5;
    int wm = wid & 1, wn = wid >> 1;
    int bx = blockIdx.x * BN, by = blockIdx.y * BM;

    auto load_stage = [&](int s, int kt) {
        int k0 = kt * BK;
        uint32_t base = sb + s * QSTG_BYTES;
        #pragma unroll
        for (int t = 0; t < 4; t++) {
            int idx = tid + t * 256;
            int r = idx >> 3, c16 = idx & 7;
            uint32_t swz = SMEM_SWIZZLE_128B((uint32_t)(r * 128 + c16 * 16));
            cp16(base + Q_OFF_AH + swz, Ahg + (size_t)(by + r) * DIM + k0 + c16 * 8);
            cp16(base + Q_OFF_BH + swz, Bhg + (size_t)(bx + r) * DIM + k0 + c16 * 8);
        }
    };

    float d[4][4][4];
    #pragma unroll
    for (int i = 0; i < 4; i++)
        #pragma unroll
        for (int j = 0; j < 4; j++)
            #pragma unroll
            for (int q = 0; q < 4; q++) d[i][j][q] = 0.f;

    load_stage(0, 0); CP_COMMIT();
    load_stage(1, 1); CP_COMMIT();
    load_stage(2, 2); CP_COMMIT();

    for (int kt = 0; kt < NCH; kt++) {
        CP_WAIT2();
        __syncthreads();

        int s = kt % 3;
        uint32_t base = sb + s * QSTG_BYTES;
        int arow = wm * 64 + (lane & 15);
        int bro  = wn * 32 + (lane & 7) + ((lane >> 4) << 3);
        int bkh  = ((lane >> 3) & 1) << 3;

        #pragma unroll
        for (int ks = 0; ks < 4; ks++) {
            int acol = ks * 16 + ((lane >> 4) << 3);
            uint32_t ah[4][4], bh[4][2];
            #pragma unroll
            for (int mf = 0; mf < 4; mf++) {
                uint32_t off = SMEM_SWIZZLE_128B(
                    (uint32_t)((arow + mf * 16) * 128 + acol * 2));
                ldm4(ah[mf], base + Q_OFF_AH + off);
            }
            #pragma unroll
            for (int j2 = 0; j2 < 2; j2++) {
                uint32_t off = SMEM_SWIZZLE_128B(
                    (uint32_t)((bro + j2 * 16) * 128 + (ks * 16 + bkh) * 2));
                uint32_t r[4];
                ldm4(r, base + Q_OFF_BH + off);
                bh[j2 * 2][0] = r[0]; bh[j2 * 2][1] = r[1];
                bh[j2 * 2 + 1][0] = r[2]; bh[j2 * 2 + 1][1] = r[3];
            }
            #pragma unroll
            for (int mf = 0; mf < 4; mf++)
                #pragma unroll
                for (int nf = 0; nf < 4; nf++)
                    mma16816(d[mf][nf], ah[mf], bh[nf]);
        }
        __syncthreads();

        if (kt + 3 < NCH) load_stage(s, kt + 3);
        CP_COMMIT();
    }

    // ---------------- fused epilogue ----------------
    int hb = blockIdx.x;             // 0..23
    bool needs_norm = (hb < 20);     // q and k blocks

    int c0 = wn * 32 + (lane & 3) * 2;
    #pragma unroll
    for (int mf = 0; mf < 4; mf++)
        #pragma unroll
        for (int nf = 0; nf < 4; nf++) {
            int c = c0 + nf * 8;
            float b0 = bias[bx + c], b1 = bias[bx + c + 1];
            d[mf][nf][0] += b0; d[mf][nf][1] += b1;
            d[mf][nf][2] += b0; d[mf][nf][3] += b1;
        }

    float* ss = (float*)sm;          // [128][4] partial row sums
    __syncthreads();

    if (needs_norm) {
        #pragma unroll
        for (int mf = 0; mf < 4; mf++) {
            float pA = 0.f, pB = 0.f;
            #pragma unroll
            for (int nf = 0; nf < 4; nf++) {
                pA += d[mf][nf][0] * d[mf][nf][0] + d[mf][nf][1] * d[mf][nf][1];
                pB += d[mf][nf][2] * d[mf][nf][2] + d[mf][nf][3] * d[mf][nf][3];
            }
            pA += __shfl_xor_sync(0xffffffffu, pA, 1);
            pA += __shfl_xor_sync(0xffffffffu, pA, 2);
            pB += __shfl_xor_sync(0xffffffffu, pB, 1);
            pB += __shfl_xor_sync(0xffffffffu, pB, 2);
            if ((lane & 3) == 0) {
                int lr = wm * 64 + mf * 16 + (lane >> 2);
                ss[lr * 4 + wn] = pA;
                ss[(lr + 8) * 4 + wn] = pB;
            }
        }
    }
    __syncthreads();

    const float* nsc = (hb < 16) ? qns : kns;
    float esc = (hb < 16) ? (1.0f / (float)HD) : 1.0f;
    __half* oph;
    int headmul;
    if (hb < 16)      { oph = qah; headmul = NH; }
    else if (hb < 20) { oph = kah; headmul = NG; }
    else              { oph = vah; headmul = NG; }
    int head = (hb < 16) ? hb : ((hb < 20) ? hb - 16 : hb - 20);

    #pragma unroll
    for (int mf = 0; mf < 4; mf++) {
        int lr = wm * 64 + mf * 16 + (lane >> 2);
        int rowA = by + lr, rowB = rowA + 8;
        int posA = rowA & (SEQ - 1), posB = rowB & (SEQ - 1);
        int bA = rowA >> 9, bB = rowB >> 9;
        float rinvA = 1.f, rinvB = 1.f;
        if (needs_norm) {
            float sA = ss[lr * 4] + ss[lr * 4 + 1] + ss[lr * 4 + 2] + ss[lr * 4 + 3];
            float sB = ss[(lr + 8) * 4] + ss[(lr + 8) * 4 + 1] +
                       ss[(lr + 8) * 4 + 2] + ss[(lr + 8) * 4 + 3];
            rinvA = rsqrtf(sA * (1.0f / HD) + 1e-6f);
            rinvB = rsqrtf(sB * (1.0f / HD) + 1e-6f);
        }
        size_t obA = ((size_t)(bA * headmul + head) * SEQ + posA) * HD;
        size_t obB = ((size_t)(bB * headmul + head) * SEQ + posB) * HD;
        #pragma unroll
        for (int nf = 0; nf < 4; nf++) {
            int c = c0 + nf * 8;
            if (needs_norm) {
                float sc0 = nsc[c], sc1 = nsc[c + 1];
                float invf = __expf(-(float)(c >> 1) * (9.210340371976184f / 64.0f));
                float snA, csA, snB, csB;
                __sincosf((float)posA * invf, &snA, &csA);
                __sincosf((float)posB * invf, &snB, &csB);
                float xA1 = d[mf][nf][0] * rinvA * sc0;
                float xA2 = d[mf][nf][1] * rinvA * sc1;
                float xB1 = d[mf][nf][2] * rinvB * sc0;
                float xB2 = d[mf][nf][3] * rinvB * sc1;
                *(__half2*)&oph[obA + c] = __floats2half2_rn(
                    (xA1 * csA - xA2 * snA) * esc, (xA1 * snA + xA2 * csA) * esc);
                *(__half2*)&oph[obB + c] = __floats2half2_rn(
                    (xB1 * csB - xB2 * snB) * esc, (xB1 * snB + xB2 * csB) * esc);
            } else {
                *(__half2*)&vah[obA + c] = __floats2half2_rn(d[mf][nf][0], d[mf][nf][1]);
                *(__half2*)&vah[obB + c] = __floats2half2_rn(d[mf][nf][2], d[mf][nf][3]);
            }
        }
    }
}

// ---------------------------------------------------------------------------
// Wo GEMM: plain fp16 single-product, bias, fp32 output.
// ---------------------------------------------------------------------------
__global__ __launch_bounds__(256, 1) void gemm_wo(
    const __half* __restrict__ Ahg, const __half* __restrict__ Bhg,
    const float* __restrict__ bias, float* __restrict__ C, int N)
{
    extern __shared__ char sm[];
    uint32_t sb = smem_to_u32(sm);
    int tid = threadIdx.x, lane = tid & 31, wid = tid >> 5;
    int wm = wid & 1, wn = wid >> 1;
    int bx = blockIdx.x * BN, by = blockIdx.y * BM;

    auto load_stage = [&](int s, int kt) {
        int k0 = kt * BK;
        uint32_t base = sb + s * QSTG_BYTES;
        #pragma unroll
        for (int t = 0; t < 4; t++) {
            int idx = tid + t * 256;
            int r = idx >> 3, c16 = idx & 7;
            uint32_t swz = SMEM_SWIZZLE_128B((uint32_t)(r * 128 + c16 * 16));
            cp16(base + Q_OFF_AH + swz, Ahg + (size_t)(by + r) * DIM + k0 + c16 * 8);
            cp16(base + Q_OFF_BH + swz, Bhg + (size_t)(bx + r) * DIM + k0 + c16 * 8);
        }
    };

    float d[4][4][4];
    #pragma unroll
    for (int i = 0; i < 4; i++)
        #pragma unroll
        for (int j = 0; j < 4; j++)
            #pragma unroll
            for (int q = 0; q < 4; q++) d[i][j][q] = 0.f;

    load_stage(0, 0); CP_COMMIT();
    load_stage(1, 1); CP_COMMIT();
    load_stage(2, 2); CP_COMMIT();

    for (int kt = 0; kt < NCH; kt++) {
        CP_WAIT2();
        __syncthreads();

        int s = kt % 3;
        uint32_t base = sb + s * QSTG_BYTES;
        int arow = wm * 64 + (lane & 15);
        int bro  = wn * 32 + (lane & 7) + ((lane >> 4) << 3);
        int bkh  = ((lane >> 3) & 1) << 3;

        #pragma unroll
        for (int ks = 0; ks < 4; ks++) {
            int acol = ks * 16 + ((lane >> 4) << 3);
            uint32_t ah[4][4], bh[4][2];
            #pragma unroll
            for (int mf = 0; mf < 4; mf++) {
                uint32_t off = SMEM_SWIZZLE_128B(
                    (uint32_t)((arow + mf * 16) * 128 + acol * 2));
                ldm4(ah[mf], base + Q_OFF_AH + off);
            }
            #pragma unroll
            for (int j2 = 0; j2 < 2; j2++) {
                uint32_t off = SMEM_SWIZZLE_128B(
                    (uint32_t)((bro + j2 * 16) * 128 + (ks * 16 + bkh) * 2));
                uint32_t r[4];
                ldm4(r, base + Q_OFF_BH + off);
                bh[j2 * 2][0] = r[0]; bh[j2 * 2][1] = r[1];
                bh[j2 * 2 + 1][0] = r[2]; bh[j2 * 2 + 1][1] = r[3];
            }
            #pragma unroll
            for (int mf = 0; mf < 4; mf++)
                #pragma unroll
                for (int nf = 0; nf < 4; nf++)
                    mma16816(d[mf][nf], ah[mf], bh[nf]);
        }
        __syncthreads();

        if (kt + 3 < NCH) load_stage(s, kt + 3);
        CP_COMMIT();
    }

    int row0 = by + wm * 64 + (lane >> 2);
    int col0 = bx + wn * 32 + (lane & 3) * 2;
    #pragma unroll
    for (int mf = 0; mf < 4; mf++)
        #pragma unroll
        for (int nf = 0; nf < 4; nf++) {
            int r = row0 + mf * 16;
            int c = col0 + nf * 8;
            float b0 = bias[c], b1 = bias[c + 1];
            float2 v0 = make_float2(d[mf][nf][0] + b0, d[mf][nf][1] + b1);
            float2 v1 = make_float2(d[mf][nf][2] + b0, d[mf][nf][3] + b1);
            *(float2*)&C[(size_t)r * N + c] = v0;
            *(float2*)&C[(size_t)(r + 8) * N + c] = v1;
        }
}

// ---------------------------------------------------------------------------
// HMMA flash attention. All operands plain fp16, single-product MMAs.
// smem: Q 32KB + 3 x (K 16K + V 16K) = 128KB
// ---------------------------------------------------------------------------
#define FA_STG 32768
#define FA_SMEM (32768 + 3 * FA_STG)   // 131072

__global__ __launch_bounds__(256, 1) void flash_attn_hmma(
    const __half* __restrict__ qh, const __half* __restrict__ kh,
    const __half* __restrict__ vh, __half* __restrict__ aoh)
{
    extern __shared__ char sm[];
    uint32_t sb = smem_to_u32(sm);
    int qb = (gridDim.x - 1) - blockIdx.x;
    int h = blockIdx.y, b = blockIdx.z;
    int g = h >> 2;
    int tid = threadIdx.x, lane = tid & 31, wid = tid >> 5;

    const size_t qbase  = ((size_t)(b * NH + h) * SEQ + qb * 128) * HD;
    const size_t kvbase = ((size_t)(b * NG + g) * SEQ) * HD;

    const uint32_t QH = sb;

    auto load_q = [&]() {
        #pragma unroll
        for (int t = 0; t < 8; t++) {
            int idx = tid + t * 256;
            int r = idx >> 4, c16 = idx & 15;
            uint32_t off = (uint32_t)((c16 >> 3) * 16384) +
                           SMEM_SWIZZLE_128B((uint32_t)(r * 128 + (c16 & 7) * 16));
            cp16(QH + off, qh + qbase + (size_t)r * HD + c16 * 8);
        }
    };
    auto load_kv = [&](int s, int kt) {
        uint32_t base = sb + 32768 + s * FA_STG;
        size_t kb = kvbase + (size_t)kt * 64 * HD;
        #pragma unroll
        for (int t = 0; t < 4; t++) {
            int idx = tid + t * 256;
            int r = idx >> 4, c16 = idx & 15;
            uint32_t off = (uint32_t)((c16 >> 3) * 8192) +
                           SMEM_SWIZZLE_128B((uint32_t)(r * 128 + (c16 & 7) * 16));
            size_t go = kb + (size_t)r * HD + c16 * 8;
            cp16(base + off,         kh + go);
            cp16(base + 16384 + off, vh + go);
        }
    };

    int nkt = 2 * qb + 2;
    load_q();
    if (0 < nkt) load_kv(0, 0);
    CP_COMMIT();
    if (1 < nkt) load_kv(1, 1);
    CP_COMMIT();
    if (2 < nkt) load_kv(2, 2);
    CP_COMMIT();

    float o[16][4];
    #pragma unroll
    for (int i = 0; i < 16; i++)
        #pragma unroll
        for (int j = 0; j < 4; j++) o[i][j] = 0.f;
    float mA = -1e30f, mB = -1e30f, lA = 0.f, lB = 0.f;

    int row0 = wid * 16;
    int sq = qb * 128 + row0;

    for (int kt = 0; kt < nkt; kt++) {
        CP_WAIT2();
        __syncthreads();

        int st = kt % 3;
        uint32_t KHb = sb + 32768 + st * FA_STG;
        uint32_t VHb = KHb + 16384;

        bool active = (kt * 64 <= sq + 15);
        if (active) {
            float sc[8][4];
            #pragma unroll
            for (int i = 0; i < 8; i++)
                #pragma unroll
                for (int j = 0; j < 4; j++) sc[i][j] = 0.f;

            int aro  = row0 + (lane & 15);
            int kro  = (lane & 7) + ((lane >> 4) << 3);
            int bkh  = ((lane >> 3) & 1) << 3;

            // S = Q K^T
            #pragma unroll
            for (int ks = 0; ks < 8; ks++) {
                int chk  = ks >> 2;
                int acol = (ks & 3) * 16 + ((lane >> 4) << 3);
                uint32_t aoff = (uint32_t)(chk * 16384) +
                                SMEM_SWIZZLE_128B((uint32_t)(aro * 128 + acol * 2));
                uint32_t ah[4];
                ldm4(ah, QH + aoff);

                int bcol = (ks & 3) * 16 + bkh;
                uint32_t bh[8][2];
                #pragma unroll
                for (int j2 = 0; j2 < 4; j2++) {
                    uint32_t boff = (uint32_t)(chk * 8192) +
                        SMEM_SWIZZLE_128B((uint32_t)((j2 * 16 + kro) * 128 + bcol * 2));
                    uint32_t r[4];
                    ldm4(r, KHb + boff);
                    bh[2*j2][0] = r[0]; bh[2*j2][1] = r[1];
                    bh[2*j2+1][0] = r[2]; bh[2*j2+1][1] = r[3];
                }
                #pragma unroll
                for (int nf = 0; nf < 8; nf++)
                    mma16816(sc[nf], ah, bh[nf]);
            }

            if (kt * 64 + 63 > sq) {
                int rA = sq + (lane >> 2), rB = rA + 8;
                #pragma unroll
                for (int nf = 0; nf < 8; nf++) {
                    int cbase = kt * 64 + nf * 8 + 2 * (lane & 3);
                    if (cbase     > rA) sc[nf][0] = -1e30f;
                    if (cbase + 1 > rA) sc[nf][1] = -1e30f;
                    if (cbase     > rB) sc[nf][2] = -1e30f;
                    if (cbase + 1 > rB) sc[nf][3] = -1e30f;
                }
            }

            float mtA = -1e30f, mtB = -1e30f;
            #pragma unroll
            for (int nf = 0; nf < 8; nf++) {
                mtA = fmaxf(mtA, fmaxf(sc[nf][0], sc[nf][1]));
                mtB = fmaxf(mtB, fmaxf(sc[nf][2], sc[nf][3]));
            }
            mtA = fmaxf(mtA, __shfl_xor_sync(0xffffffffu, mtA, 1));
            mtA = fmaxf(mtA, __shfl_xor_sync(0xffffffffu, mtA, 2));
            mtB = fmaxf(mtB, __shfl_xor_sync(0xffffffffu, mtB, 1));
            mtB = fmaxf(mtB, __shfl_xor_sync(0xffffffffu, mtB, 2));
            float nmA = fmaxf(mA, mtA), nmB = fmaxf(mB, mtB);
            float alA = __expf(mA - nmA), alB = __expf(mB - nmB);

            float suA = 0.f, suB = 0.f;
            #pragma unroll
            for (int nf = 0; nf < 8; nf++) {
                sc[nf][0] = __expf(sc[nf][0] - nmA); suA += sc[nf][0];
                sc[nf][1] = __expf(sc[nf][1] - nmA); suA += sc[nf][1];
                sc[nf][2] = __expf(sc[nf][2] - nmB); suB += sc[nf][2];
                sc[nf][3] = __expf(sc[nf][3] - nmB); suB += sc[nf][3];
            }
            suA += __shfl_xor_sync(0xffffffffu, suA, 1);
            suA += __shfl_xor_sync(0xffffffffu, suA, 2);
            suB += __shfl_xor_sync(0xffffffffu, suB, 1);
            suB += __shfl_xor_sync(0xffffffffu, suB, 2);
            lA = lA * alA + suA;
            lB = lB * alB + suB;
            mA = nmA; mB = nmB;
            #pragma unroll
            for (int nf = 0; nf < 16; nf++) {
                o[nf][0] *= alA; o[nf][1] *= alA;
                o[nf][2] *= alB; o[nf][3] *= alB;
            }

            // O += P V
            int vro = (lane & 7) + (((lane >> 3) & 1) << 3);
            int vch = (lane >> 4) << 3;
            #pragma unroll
            for (int kf = 0; kf < 4; kf++) {
                uint32_t aPh[4];
                aPh[0] = pk2h(sc[2*kf][0],   sc[2*kf][1]);
                aPh[1] = pk2h(sc[2*kf][2],   sc[2*kf][3]);
                aPh[2] = pk2h(sc[2*kf+1][0], sc[2*kf+1][1]);
                aPh[3] = pk2h(sc[2*kf+1][2], sc[2*kf+1][3]);
                #pragma unroll
                for (int j2 = 0; j2 < 8; j2++) {
                    int chk  = j2 >> 2;
                    int wcol = (j2 & 3) * 16 + vch;
                    uint32_t voff = (uint32_t)(chk * 8192) +
                        SMEM_SWIZZLE_128B((uint32_t)((kf * 16 + vro) * 128 + wcol * 2));
                    uint32_t rh[4];
                    ldm4t(rh, VHb + voff);
                    uint32_t bh0[2] = {rh[0], rh[1]}, bh1[2] = {rh[2], rh[3]};
                    mma16816(o[2*j2],   aPh, bh0);
                    mma16816(o[2*j2+1], aPh, bh1);
                }
            }
        }
        __syncthreads();

        if (kt + 3 < nkt) load_kv(kt % 3, kt + 3);
        CP_COMMIT();
    }

    float rlA = 1.0f / lA, rlB = 1.0f / lB;
    int sA = sq + (lane >> 2), sB = sA + 8;
    size_t oA = ((size_t)(b * SEQ + sA) * NH + h) * HD;
    size_t oB = ((size_t)(b * SEQ + sB) * NH + h) * HD;
    #pragma unroll
    for (int nf = 0; nf < 16; nf++) {
        int hd = nf * 8 + 2 * (lane & 3);
        *(__half2*)&aoh[oA + hd] = __floats2half2_rn(o[nf][0] * rlA, o[nf][1] * rlA);
        *(__half2*)&aoh[oB + hd] = __floats2half2_rn(o[nf][2] * rlB, o[nf][3] * rlB);
    }
}

// ---------------------------------------------------------------------------
extern "C" void kernel_launch(void* const* d_in, const int* in_sizes, int n_in,
                              void* d_out, int out_size)
{
    const float* x   = (const float*)d_in[0];
    const float* Wq  = (const float*)d_in[1];
    const float* bq  = (const float*)d_in[2];
    const float* Wk  = (const float*)d_in[3];
    const float* bk  = (const float*)d_in[4];
    const float* Wv  = (const float*)d_in[5];
    const float* bv  = (const float*)d_in[6];
    const float* Wo  = (const float*)d_in[7];
    const float* bo  = (const float*)d_in[8];
    const float* qns = (const float*)d_in[9];
    const float* kns = (const float*)d_in[10];
    float* out = (float*)d_out;

    __half *xhi, *aoh, *wh, *woh;
    __half *qah, *kah, *vah;
    float* bqkv;
    cudaGetSymbolAddress((void**)&xhi, g_xhi);
    cudaGetSymbolAddress((void**)&aoh, g_aoh);
    cudaGetSymbolAddress((void**)&wh,  g_wh);
    cudaGetSymbolAddress((void**)&woh, g_woh);
    cudaGetSymbolAddress((void**)&bqkv, g_bqkv);
    cudaGetSymbolAddress((void**)&qah, g_qah);
    cudaGetSymbolAddress((void**)&kah, g_kah);
    cudaGetSymbolAddress((void**)&vah, g_vah);

    cudaFuncSetAttribute(gemm_qkv, cudaFuncAttributeMaxDynamicSharedMemorySize, QGEMM_SMEM);
    cudaFuncSetAttribute(gemm_wo, cudaFuncAttributeMaxDynamicSharedMemorySize, QGEMM_SMEM);
    cudaFuncSetAttribute(flash_attn_hmma, cudaFuncAttributeMaxDynamicSharedMemorySize, FA_SMEM);

    const int n4 = MROWS * DIM / 4;

    // conversions
    convert_h<<<(n4 + 255) / 256, 256>>>(x, xhi, n4);
    transpose_h<<<dim3(DIM / 32, DIM / 32), dim3(32, 8)>>>(Wq, wh, DIM, DIM);
    transpose_h<<<dim3(KVD / 32, DIM / 32), dim3(32, 8)>>>(
        Wk, wh + (size_t)DIM * DIM, DIM, KVD);
    transpose_h<<<dim3(KVD / 32, DIM / 32), dim3(32, 8)>>>(
        Wv, wh + (size_t)(DIM + KVD) * DIM, DIM, KVD);
    transpose_h<<<dim3(DIM / 32, DIM / 32), dim3(32, 8)>>>(Wo, woh, DIM, DIM);
    bias_concat<<<(NQKV + 255) / 256, 256>>>(bq, bk, bv, bqkv);

    // fused QKV projection + rmsnorm + rope (q carries full 1/hd)
    gemm_qkv<<<dim3(NQKV / BN, MROWS / BM), 256, QGEMM_SMEM>>>(
        xhi, wh, bqkv, qns, kns, qah, kah, vah);

    // attention (HMMA, plain fp16)
    flash_attn_hmma<<<dim3(SEQ / 128, NH, BATCH), 256, FA_SMEM>>>(
        qah, kah, vah, aoh);

    // output projection (plain fp16)
    gemm_wo<<<dim3(DIM / BN, MROWS / BM), 256, QGEMM_SMEM>>>(
        aoh, woh, bo, out, DIM);
}

// round 12
// speedup vs baseline: 2.6122x; 1.1578x over previous
#include <cuda_runtime.h>
#include <cuda_fp16.h>
#include <cstdint>
#include <math.h>

#define BATCH 16
#define SEQ   512
#define DIM   2048
#define NH    16
#define NG    4
#define HD    128
#define MROWS (BATCH*SEQ)   // 8192
#define KVD   (NG*HD)       // 512
#define NQKV  (DIM + 2*KVD) // 3072

// ---------------------------------------------------------------------------
// scratch (device globals — no allocation allowed)
// ---------------------------------------------------------------------------
__device__ __half g_xhi[(size_t)MROWS * DIM];
__device__ __half g_aoh[(size_t)MROWS * DIM];   // attn out fp16 (b,s,H,hd)
__device__ __half g_wh[(size_t)NQKV * DIM];     // [Wq^T; Wk^T; Wv^T] fp16
__device__ __half g_woh[(size_t)DIM * DIM];     // Wo^T fp16
__device__ float  g_bqkv[NQKV];                 // [bq; bk; bv]

// attention operand buffers, (b, head, s, hd) layout, plain fp16
__device__ __half g_qah[(size_t)MROWS * DIM];
__device__ __half g_kah[(size_t)MROWS * KVD];
__device__ __half g_vah[(size_t)MROWS * KVD];

// ---------------------------------------------------------------------------
// helpers
// ---------------------------------------------------------------------------
__device__ __forceinline__ uint32_t smem_to_u32(const void* p) {
    uint32_t a;
    asm("{ .reg .u64 t; cvta.to.shared.u64 t, %1; cvt.u32.u64 %0, t; }" : "=r"(a) : "l"(p));
    return a;
}
#define SMEM_SWIZZLE_128B(bo) ((bo) ^ (((bo) >> 3) & 0x70))

__device__ __forceinline__ void cp16(uint32_t s, const void* g) {
    asm volatile("cp.async.cg.shared.global [%0], [%1], 16;" :: "r"(s), "l"(g) : "memory");
}
#define CP_COMMIT() asm volatile("cp.async.commit_group;" ::: "memory")
#define CP_WAIT2()  asm volatile("cp.async.wait_group 2;" ::: "memory")
__device__ __forceinline__ void ldm4(uint32_t* r, uint32_t a) {
    asm volatile("ldmatrix.sync.aligned.m8n8.x4.shared.b16 {%0,%1,%2,%3}, [%4];"
                 : "=r"(r[0]), "=r"(r[1]), "=r"(r[2]), "=r"(r[3]) : "r"(a));
}
__device__ __forceinline__ void ldm4t(uint32_t* r, uint32_t a) {
    asm volatile("ldmatrix.sync.aligned.m8n8.x4.trans.shared.b16 {%0,%1,%2,%3}, [%4];"
                 : "=r"(r[0]), "=r"(r[1]), "=r"(r[2]), "=r"(r[3]) : "r"(a));
}
__device__ __forceinline__ void mma16816(float* d, const uint32_t* a, const uint32_t* b) {
    asm volatile(
        "mma.sync.aligned.m16n8k16.row.col.f32.f16.f16.f32 "
        "{%0,%1,%2,%3},{%4,%5,%6,%7},{%8,%9},{%0,%1,%2,%3};"
        : "+f"(d[0]), "+f"(d[1]), "+f"(d[2]), "+f"(d[3])
        : "r"(a[0]), "r"(a[1]), "r"(a[2]), "r"(a[3]), "r"(b[0]), "r"(b[1]));
}
__device__ __forceinline__ uint32_t pk2h(float a, float b) {
    __half2 h = __floats2half2_rn(a, b);
    return *reinterpret_cast<uint32_t*>(&h);
}

// ---------------------------------------------------------------------------
// convert fp32 -> fp16
// ---------------------------------------------------------------------------
__global__ __launch_bounds__(256) void convert_h(
    const float* __restrict__ in, __half* __restrict__ hi, int n4)
{
    int i = blockIdx.x * 256 + threadIdx.x;
    if (i >= n4) return;
    float4 v = ((const float4*)in)[i];
    uint2 ph;
    ph.x = pk2h(v.x, v.y); ph.y = pk2h(v.z, v.w);
    ((uint2*)hi)[i] = ph;
}

// ---------------------------------------------------------------------------
// W [K, N] fp32 -> W^T [N, K] fp16
// ---------------------------------------------------------------------------
__global__ __launch_bounds__(256) void transpose_h(
    const float* __restrict__ W, __half* __restrict__ Th, int K, int N)
{
    __shared__ float tile[32][33];
    int n0 = blockIdx.x * 32, k0 = blockIdx.y * 32;
    int tx = threadIdx.x, ty = threadIdx.y;   // 32 x 8
    #pragma unroll
    for (int j = ty; j < 32; j += 8)
        tile[j][tx] = W[(size_t)(k0 + j) * N + n0 + tx];
    __syncthreads();
    #pragma unroll
    for (int j = ty; j < 32; j += 8)
        Th[(size_t)(n0 + j) * K + k0 + tx] = __float2half_rn(tile[tx][j]);
}

__global__ __launch_bounds__(256) void bias_concat(
    const float* __restrict__ bq, const float* __restrict__ bk,
    const float* __restrict__ bv, float* __restrict__ o)
{
    int i = blockIdx.x * 256 + threadIdx.x;
    if (i < DIM) o[i] = bq[i];
    else if (i < DIM + KVD) o[i] = bk[i - DIM];
    else if (i < NQKV) o[i] = bv[i - DIM - KVD];
}

// ---------------------------------------------------------------------------
// tile config — plain fp16 GEMM, stage = AH 16K + BH 16K, 3-stage
// ---------------------------------------------------------------------------
#define BM 128
#define BN 128
#define BK 64
#define NCH (DIM / BK)   // 32
#define QSTG_BYTES 32768
#define Q_OFF_AH 0
#define Q_OFF_BH 16384
#define QGEMM_SMEM (3 * QSTG_BYTES)   // 98304

// ---------------------------------------------------------------------------
// Fused QKV GEMM + RMSNorm + RoPE epilogue. Plain fp16; 2 CTAs/SM.
// ---------------------------------------------------------------------------
__global__ __launch_bounds__(256, 2) void gemm_qkv(
    const __half* __restrict__ Ahg, const __half* __restrict__ Bhg,
    const float* __restrict__ bias,
    const float* __restrict__ qns, const float* __restrict__ kns,
    __half* __restrict__ qah, __half* __restrict__ kah,
    __half* __restrict__ vah)
{
    extern __shared__ char sm[];
    uint32_t sb = smem_to_u32(sm);
    int tid = threadIdx.x, lane = tid & 31, wid = tid >> 5;
    int wm = wid & 1, wn = wid >> 1;
    int bx = blockIdx.x * BN, by = blockIdx.y * BM;

    auto load_stage = [&](int s, int kt) {
        int k0 = kt * BK;
        uint32_t base = sb + s * QSTG_BYTES;
        #pragma unroll
        for (int t = 0; t < 4; t++) {
            int idx = tid + t * 256;
            int r = idx >> 3, c16 = idx & 7;
            uint32_t swz = SMEM_SWIZZLE_128B((uint32_t)(r * 128 + c16 * 16));
            cp16(base + Q_OFF_AH + swz, Ahg + (size_t)(by + r) * DIM + k0 + c16 * 8);
            cp16(base + Q_OFF_BH + swz, Bhg + (size_t)(bx + r) * DIM + k0 + c16 * 8);
        }
    };

    float d[4][4][4];
    #pragma unroll
    for (int i = 0; i < 4; i++)
        #pragma unroll
        for (int j = 0; j < 4; j++)
            #pragma unroll
            for (int q = 0; q < 4; q++) d[i][j][q] = 0.f;

    load_stage(0, 0); CP_COMMIT();
    load_stage(1, 1); CP_COMMIT();
    load_stage(2, 2); CP_COMMIT();

    for (int kt = 0; kt < NCH; kt++) {
        CP_WAIT2();
        __syncthreads();

        int s = kt % 3;
        uint32_t base = sb + s * QSTG_BYTES;
        int arow = wm * 64 + (lane & 15);
        int bro  = wn * 32 + (lane & 7) + ((lane >> 4) << 3);
        int bkh  = ((lane >> 3) & 1) << 3;

        #pragma unroll
        for (int ks = 0; ks < 4; ks++) {
            int acol = ks * 16 + ((lane >> 4) << 3);
            uint32_t ah[4][4], bh[4][2];
            #pragma unroll
            for (int mf = 0; mf < 4; mf++) {
                uint32_t off = SMEM_SWIZZLE_128B(
                    (uint32_t)((arow + mf * 16) * 128 + acol * 2));
                ldm4(ah[mf], base + Q_OFF_AH + off);
            }
            #pragma unroll
            for (int j2 = 0; j2 < 2; j2++) {
                uint32_t off = SMEM_SWIZZLE_128B(
                    (uint32_t)((bro + j2 * 16) * 128 + (ks * 16 + bkh) * 2));
                uint32_t r[4];
                ldm4(r, base + Q_OFF_BH + off);
                bh[j2 * 2][0] = r[0]; bh[j2 * 2][1] = r[1];
                bh[j2 * 2 + 1][0] = r[2]; bh[j2 * 2 + 1][1] = r[3];
            }
            #pragma unroll
            for (int mf = 0; mf < 4; mf++)
                #pragma unroll
                for (int nf = 0; nf < 4; nf++)
                    mma16816(d[mf][nf], ah[mf], bh[nf]);
        }
        __syncthreads();

        if (kt + 3 < NCH) load_stage(s, kt + 3);
        CP_COMMIT();
    }

    // ---------------- fused epilogue ----------------
    int hb = blockIdx.x;             // 0..23
    bool needs_norm = (hb < 20);     // q and k blocks

    int c0 = wn * 32 + (lane & 3) * 2;
    #pragma unroll
    for (int mf = 0; mf < 4; mf++)
        #pragma unroll
        for (int nf = 0; nf < 4; nf++) {
            int c = c0 + nf * 8;
            float b0 = bias[bx + c], b1 = bias[bx + c + 1];
            d[mf][nf][0] += b0; d[mf][nf][1] += b1;
            d[mf][nf][2] += b0; d[mf][nf][3] += b1;
        }

    float* ss = (float*)sm;          // [128][4] partial row sums
    __syncthreads();

    if (needs_norm) {
        #pragma unroll
        for (int mf = 0; mf < 4; mf++) {
            float pA = 0.f, pB = 0.f;
            #pragma unroll
            for (int nf = 0; nf < 4; nf++) {
                pA += d[mf][nf][0] * d[mf][nf][0] + d[mf][nf][1] * d[mf][nf][1];
                pB += d[mf][nf][2] * d[mf][nf][2] + d[mf][nf][3] * d[mf][nf][3];
            }
            pA += __shfl_xor_sync(0xffffffffu, pA, 1);
            pA += __shfl_xor_sync(0xffffffffu, pA, 2);
            pB += __shfl_xor_sync(0xffffffffu, pB, 1);
            pB += __shfl_xor_sync(0xffffffffu, pB, 2);
            if ((lane & 3) == 0) {
                int lr = wm * 64 + mf * 16 + (lane >> 2);
                ss[lr * 4 + wn] = pA;
                ss[(lr + 8) * 4 + wn] = pB;
            }
        }
    }
    __syncthreads();

    const float* nsc = (hb < 16) ? qns : kns;
    float esc = (hb < 16) ? (1.0f / (float)HD) : 1.0f;
    __half* oph;
    int headmul;
    if (hb < 16)      { oph = qah; headmul = NH; }
    else if (hb < 20) { oph = kah; headmul = NG; }
    else              { oph = vah; headmul = NG; }
    int head = (hb < 16) ? hb : ((hb < 20) ? hb - 16 : hb - 20);

    #pragma unroll
    for (int mf = 0; mf < 4; mf++) {
        int lr = wm * 64 + mf * 16 + (lane >> 2);
        int rowA = by + lr, rowB = rowA + 8;
        int posA = rowA & (SEQ - 1), posB = rowB & (SEQ - 1);
        int bA = rowA >> 9, bB = rowB >> 9;
        float rinvA = 1.f, rinvB = 1.f;
        if (needs_norm) {
            float sA = ss[lr * 4] + ss[lr * 4 + 1] + ss[lr * 4 + 2] + ss[lr * 4 + 3];
            float sB = ss[(lr + 8) * 4] + ss[(lr + 8) * 4 + 1] +
                       ss[(lr + 8) * 4 + 2] + ss[(lr + 8) * 4 + 3];
            rinvA = rsqrtf(sA * (1.0f / HD) + 1e-6f);
            rinvB = rsqrtf(sB * (1.0f / HD) + 1e-6f);
        }
        size_t obA = ((size_t)(bA * headmul + head) * SEQ + posA) * HD;
        size_t obB = ((size_t)(bB * headmul + head) * SEQ + posB) * HD;
        #pragma unroll
        for (int nf = 0; nf < 4; nf++) {
            int c = c0 + nf * 8;
            if (needs_norm) {
                float sc0 = nsc[c], sc1 = nsc[c + 1];
                float invf = __expf(-(float)(c >> 1) * (9.210340371976184f / 64.0f));
                float snA, csA, snB, csB;
                __sincosf((float)posA * invf, &snA, &csA);
                __sincosf((float)posB * invf, &snB, &csB);
                float xA1 = d[mf][nf][0] * rinvA * sc0;
                float xA2 = d[mf][nf][1] * rinvA * sc1;
                float xB1 = d[mf][nf][2] * rinvB * sc0;
                float xB2 = d[mf][nf][3] * rinvB * sc1;
                *(__half2*)&oph[obA + c] = __floats2half2_rn(
                    (xA1 * csA - xA2 * snA) * esc, (xA1 * snA + xA2 * csA) * esc);
                *(__half2*)&oph[obB + c] = __floats2half2_rn(
                    (xB1 * csB - xB2 * snB) * esc, (xB1 * snB + xB2 * csB) * esc);
            } else {
                *(__half2*)&vah[obA + c] = __floats2half2_rn(d[mf][nf][0], d[mf][nf][1]);
                *(__half2*)&vah[obB + c] = __floats2half2_rn(d[mf][nf][2], d[mf][nf][3]);
            }
        }
    }
}

// ---------------------------------------------------------------------------
// Wo GEMM: plain fp16 single-product, bias, fp32 output; 2 CTAs/SM.
// ---------------------------------------------------------------------------
__global__ __launch_bounds__(256, 2) void gemm_wo(
    const __half* __restrict__ Ahg, const __half* __restrict__ Bhg,
    const float* __restrict__ bias, float* __restrict__ C, int N)
{
    extern __shared__ char sm[];
    uint32_t sb = smem_to_u32(sm);
    int tid = threadIdx.x, lane = tid & 31, wid = tid >> 5;
    int wm = wid & 1, wn = wid >> 1;
    int bx = blockIdx.x * BN, by = blockIdx.y * BM;

    auto load_stage = [&](int s, int kt) {
        int k0 = kt * BK;
        uint32_t base = sb + s * QSTG_BYTES;
        #pragma unroll
        for (int t = 0; t < 4; t++) {
            int idx = tid + t * 256;
            int r = idx >> 3, c16 = idx & 7;
            uint32_t swz = SMEM_SWIZZLE_128B((uint32_t)(r * 128 + c16 * 16));
            cp16(base + Q_OFF_AH + swz, Ahg + (size_t)(by + r) * DIM + k0 + c16 * 8);
            cp16(base + Q_OFF_BH + swz, Bhg + (size_t)(bx + r) * DIM + k0 + c16 * 8);
        }
    };

    float d[4][4][4];
    #pragma unroll
    for (int i = 0; i < 4; i++)
        #pragma unroll
        for (int j = 0; j < 4; j++)
            #pragma unroll
            for (int q = 0; q < 4; q++) d[i][j][q] = 0.f;

    load_stage(0, 0); CP_COMMIT();
    load_stage(1, 1); CP_COMMIT();
    load_stage(2, 2); CP_COMMIT();

    for (int kt = 0; kt < NCH; kt++) {
        CP_WAIT2();
        __syncthreads();

        int s = kt % 3;
        uint32_t base = sb + s * QSTG_BYTES;
        int arow = wm * 64 + (lane & 15);
        int bro  = wn * 32 + (lane & 7) + ((lane >> 4) << 3);
        int bkh  = ((lane >> 3) & 1) << 3;

        #pragma unroll
        for (int ks = 0; ks < 4; ks++) {
            int acol = ks * 16 + ((lane >> 4) << 3);
            uint32_t ah[4][4], bh[4][2];
            #pragma unroll
            for (int mf = 0; mf < 4; mf++) {
                uint32_t off = SMEM_SWIZZLE_128B(
                    (uint32_t)((arow + mf * 16) * 128 + acol * 2));
                ldm4(ah[mf], base + Q_OFF_AH + off);
            }
            #pragma unroll
            for (int j2 = 0; j2 < 2; j2++) {
                uint32_t off = SMEM_SWIZZLE_128B(
                    (uint32_t)((bro + j2 * 16) * 128 + (ks * 16 + bkh) * 2));
                uint32_t r[4];
                ldm4(r, base + Q_OFF_BH + off);
                bh[j2 * 2][0] = r[0]; bh[j2 * 2][1] = r[1];
                bh[j2 * 2 + 1][0] = r[2]; bh[j2 * 2 + 1][1] = r[3];
            }
            #pragma unroll
            for (int mf = 0; mf < 4; mf++)
                #pragma unroll
                for (int nf = 0; nf < 4; nf++)
                    mma16816(d[mf][nf], ah[mf], bh[nf]);
        }
        __syncthreads();

        if (kt + 3 < NCH) load_stage(s, kt + 3);
        CP_COMMIT();
    }

    int row0 = by + wm * 64 + (lane >> 2);
    int col0 = bx + wn * 32 + (lane & 3) * 2;
    #pragma unroll
    for (int mf = 0; mf < 4; mf++)
        #pragma unroll
        for (int nf = 0; nf < 4; nf++) {
            int r = row0 + mf * 16;
            int c = col0 + nf * 8;
            float b0 = bias[c], b1 = bias[c + 1];
            float2 v0 = make_float2(d[mf][nf][0] + b0, d[mf][nf][1] + b1);
            float2 v1 = make_float2(d[mf][nf][2] + b0, d[mf][nf][3] + b1);
            *(float2*)&C[(size_t)r * N + c] = v0;
            *(float2*)&C[(size_t)(r + 8) * N + c] = v1;
        }
}

// ---------------------------------------------------------------------------
// HMMA flash attention. All operands plain fp16, single-product MMAs.
// smem: Q 32KB + 3 x (K 16K + V 16K) = 128KB
// ---------------------------------------------------------------------------
#define FA_STG 32768
#define FA_SMEM (32768 + 3 * FA_STG)   // 131072

__global__ __launch_bounds__(256, 1) void flash_attn_hmma(
    const __half* __restrict__ qh, const __half* __restrict__ kh,
    const __half* __restrict__ vh, __half* __restrict__ aoh)
{
    extern __shared__ char sm[];
    uint32_t sb = smem_to_u32(sm);
    int qb = (gridDim.x - 1) - blockIdx.x;
    int h = blockIdx.y, b = blockIdx.z;
    int g = h >> 2;
    int tid = threadIdx.x, lane = tid & 31, wid = tid >> 5;

    const size_t qbase  = ((size_t)(b * NH + h) * SEQ + qb * 128) * HD;
    const size_t kvbase = ((size_t)(b * NG + g) * SEQ) * HD;

    const uint32_t QH = sb;

    auto load_q = [&]() {
        #pragma unroll
        for (int t = 0; t < 8; t++) {
            int idx = tid + t * 256;
            int r = idx >> 4, c16 = idx & 15;
            uint32_t off = (uint32_t)((c16 >> 3) * 16384) +
                           SMEM_SWIZZLE_128B((uint32_t)(r * 128 + (c16 & 7) * 16));
            cp16(QH + off, qh + qbase + (size_t)r * HD + c16 * 8);
        }
    };
    auto load_kv = [&](int s, int kt) {
        uint32_t base = sb + 32768 + s * FA_STG;
        size_t kb = kvbase + (size_t)kt * 64 * HD;
        #pragma unroll
        for (int t = 0; t < 4; t++) {
            int idx = tid + t * 256;
            int r = idx >> 4, c16 = idx & 15;
            uint32_t off = (uint32_t)((c16 >> 3) * 8192) +
                           SMEM_SWIZZLE_128B((uint32_t)(r * 128 + (c16 & 7) * 16));
            size_t go = kb + (size_t)r * HD + c16 * 8;
            cp16(base + off,         kh + go);
            cp16(base + 16384 + off, vh + go);
        }
    };

    int nkt = 2 * qb + 2;
    load_q();
    if (0 < nkt) load_kv(0, 0);
    CP_COMMIT();
    if (1 < nkt) load_kv(1, 1);
    CP_COMMIT();
    if (2 < nkt) load_kv(2, 2);
    CP_COMMIT();

    float o[16][4];
    #pragma unroll
    for (int i = 0; i < 16; i++)
        #pragma unroll
        for (int j = 0; j < 4; j++) o[i][j] = 0.f;
    float mA = -1e30f, mB = -1e30f, lA = 0.f, lB = 0.f;

    int row0 = wid * 16;
    int sq = qb * 128 + row0;

    for (int kt = 0; kt < nkt; kt++) {
        CP_WAIT2();
        __syncthreads();

        int st = kt % 3;
        uint32_t KHb = sb + 32768 + st * FA_STG;
        uint32_t VHb = KHb + 16384;

        bool active = (kt * 64 <= sq + 15);
        if (active) {
            float sc[8][4];
            #pragma unroll
            for (int i = 0; i < 8; i++)
                #pragma unroll
                for (int j = 0; j < 4; j++) sc[i][j] = 0.f;

            int aro  = row0 + (lane & 15);
            int kro  = (lane & 7) + ((lane >> 4) << 3);
            int bkh  = ((lane >> 3) & 1) << 3;

            // S = Q K^T
            #pragma unroll
            for (int ks = 0; ks < 8; ks++) {
                int chk  = ks >> 2;
                int acol = (ks & 3) * 16 + ((lane >> 4) << 3);
                uint32_t aoff = (uint32_t)(chk * 16384) +
                                SMEM_SWIZZLE_128B((uint32_t)(aro * 128 + acol * 2));
                uint32_t ah[4];
                ldm4(ah, QH + aoff);

                int bcol = (ks & 3) * 16 + bkh;
                uint32_t bh[8][2];
                #pragma unroll
                for (int j2 = 0; j2 < 4; j2++) {
                    uint32_t boff = (uint32_t)(chk * 8192) +
                        SMEM_SWIZZLE_128B((uint32_t)((j2 * 16 + kro) * 128 + bcol * 2));
                    uint32_t r[4];
                    ldm4(r, KHb + boff);
                    bh[2*j2][0] = r[0]; bh[2*j2][1] = r[1];
                    bh[2*j2+1][0] = r[2]; bh[2*j2+1][1] = r[3];
                }
                #pragma unroll
                for (int nf = 0; nf < 8; nf++)
                    mma16816(sc[nf], ah, bh[nf]);
            }

            if (kt * 64 + 63 > sq) {
                int rA = sq + (lane >> 2), rB = rA + 8;
                #pragma unroll
                for (int nf = 0; nf < 8; nf++) {
                    int cbase = kt * 64 + nf * 8 + 2 * (lane & 3);
                    if (cbase     > rA) sc[nf][0] = -1e30f;
                    if (cbase + 1 > rA) sc[nf][1] = -1e30f;
                    if (cbase     > rB) sc[nf][2] = -1e30f;
                    if (cbase + 1 > rB) sc[nf][3] = -1e30f;
                }
            }

            float mtA = -1e30f, mtB = -1e30f;
            #pragma unroll
            for (int nf = 0; nf < 8; nf++) {
                mtA = fmaxf(mtA, fmaxf(sc[nf][0], sc[nf][1]));
                mtB = fmaxf(mtB, fmaxf(sc[nf][2], sc[nf][3]));
            }
            mtA = fmaxf(mtA, __shfl_xor_sync(0xffffffffu, mtA, 1));
            mtA = fmaxf(mtA, __shfl_xor_sync(0xffffffffu, mtA, 2));
            mtB = fmaxf(mtB, __shfl_xor_sync(0xffffffffu, mtB, 1));
            mtB = fmaxf(mtB, __shfl_xor_sync(0xffffffffu, mtB, 2));
            float nmA = fmaxf(mA, mtA), nmB = fmaxf(mB, mtB);
            float alA = __expf(mA - nmA), alB = __expf(mB - nmB);

            float suA = 0.f, suB = 0.f;
            #pragma unroll
            for (int nf = 0; nf < 8; nf++) {
                sc[nf][0] = __expf(sc[nf][0] - nmA); suA += sc[nf][0];
                sc[nf][1] = __expf(sc[nf][1] - nmA); suA += sc[nf][1];
                sc[nf][2] = __expf(sc[nf][2] - nmB); suB += sc[nf][2];
                sc[nf][3] = __expf(sc[nf][3] - nmB); suB += sc[nf][3];
            }
            suA += __shfl_xor_sync(0xffffffffu, suA, 1);
            suA += __shfl_xor_sync(0xffffffffu, suA, 2);
            suB += __shfl_xor_sync(0xffffffffu, suB, 1);
            suB += __shfl_xor_sync(0xffffffffu, suB, 2);
            lA = lA * alA + suA;
            lB = lB * alB + suB;
            mA = nmA; mB = nmB;
            #pragma unroll
            for (int nf = 0; nf < 16; nf++) {
                o[nf][0] *= alA; o[nf][1] *= alA;
                o[nf][2] *= alB; o[nf][3] *= alB;
            }

            // O += P V
            int vro = (lane & 7) + (((lane >> 3) & 1) << 3);
            int vch = (lane >> 4) << 3;
            #pragma unroll
            for (int kf = 0; kf < 4; kf++) {
                uint32_t aPh[4];
                aPh[0] = pk2h(sc[2*kf][0],   sc[2*kf][1]);
                aPh[1] = pk2h(sc[2*kf][2],   sc[2*kf][3]);
                aPh[2] = pk2h(sc[2*kf+1][0], sc[2*kf+1][1]);
                aPh[3] = pk2h(sc[2*kf+1][2], sc[2*kf+1][3]);
                #pragma unroll
                for (int j2 = 0; j2 < 8; j2++) {
                    int chk  = j2 >> 2;
                    int wcol = (j2 & 3) * 16 + vch;
                    uint32_t voff = (uint32_t)(chk * 8192) +
                        SMEM_SWIZZLE_128B((uint32_t)((kf * 16 + vro) * 128 + wcol * 2));
                    uint32_t rh[4];
                    ldm4t(rh, VHb + voff);
                    uint32_t bh0[2] = {rh[0], rh[1]}, bh1[2] = {rh[2], rh[3]};
                    mma16816(o[2*j2],   aPh, bh0);
                    mma16816(o[2*j2+1], aPh, bh1);
                }
            }
        }
        __syncthreads();

        if (kt + 3 < nkt) load_kv(kt % 3, kt + 3);
        CP_COMMIT();
    }

    float rlA = 1.0f / lA, rlB = 1.0f / lB;
    int sA = sq + (lane >> 2), sB = sA + 8;
    size_t oA = ((size_t)(b * SEQ + sA) * NH + h) * HD;
    size_t oB = ((size_t)(b * SEQ + sB) * NH + h) * HD;
    #pragma unroll
    for (int nf = 0; nf < 16; nf++) {
        int hd = nf * 8 + 2 * (lane & 3);
        *(__half2*)&aoh[oA + hd] = __floats2half2_rn(o[nf][0] * rlA, o[nf][1] * rlA);
        *(__half2*)&aoh[oB + hd] = __floats2half2_rn(o[nf][2] * rlB, o[nf][3] * rlB);
    }
}

// ---------------------------------------------------------------------------
extern "C" void kernel_launch(void* const* d_in, const int* in_sizes, int n_in,
                              void* d_out, int out_size)
{
    const float* x   = (const float*)d_in[0];
    const float* Wq  = (const float*)d_in[1];
    const float* bq  = (const float*)d_in[2];
    const float* Wk  = (const float*)d_in[3];
    const float* bk  = (const float*)d_in[4];
    const float* Wv  = (const float*)d_in[5];
    const float* bv  = (const float*)d_in[6];
    const float* Wo  = (const float*)d_in[7];
    const float* bo  = (const float*)d_in[8];
    const float* qns = (const float*)d_in[9];
    const float* kns = (const float*)d_in[10];
    float* out = (float*)d_out;

    __half *xhi, *aoh, *wh, *woh;
    __half *qah, *kah, *vah;
    float* bqkv;
    cudaGetSymbolAddress((void**)&xhi, g_xhi);
    cudaGetSymbolAddress((void**)&aoh, g_aoh);
    cudaGetSymbolAddress((void**)&wh,  g_wh);
    cudaGetSymbolAddress((void**)&woh, g_woh);
    cudaGetSymbolAddress((void**)&bqkv, g_bqkv);
    cudaGetSymbolAddress((void**)&qah, g_qah);
    cudaGetSymbolAddress((void**)&kah, g_kah);
    cudaGetSymbolAddress((void**)&vah, g_vah);

    cudaFuncSetAttribute(gemm_qkv, cudaFuncAttributeMaxDynamicSharedMemorySize, QGEMM_SMEM);
    cudaFuncSetAttribute(gemm_wo, cudaFuncAttributeMaxDynamicSharedMemorySize, QGEMM_SMEM);
    cudaFuncSetAttribute(flash_attn_hmma, cudaFuncAttributeMaxDynamicSharedMemorySize, FA_SMEM);

    const int n4 = MROWS * DIM / 4;

    // conversions
    convert_h<<<(n4 + 255) / 256, 256>>>(x, xhi, n4);
    transpose_h<<<dim3(DIM / 32, DIM / 32), dim3(32, 8)>>>(Wq, wh, DIM, DIM);
    transpose_h<<<dim3(KVD / 32, DIM / 32), dim3(32, 8)>>>(
        Wk, wh + (size_t)DIM * DIM, DIM, KVD);
    transpose_h<<<dim3(KVD / 32, DIM / 32), dim3(32, 8)>>>(
        Wv, wh + (size_t)(DIM + KVD) * DIM, DIM, KVD);
    transpose_h<<<dim3(DIM / 32, DIM / 32), dim3(32, 8)>>>(Wo, woh, DIM, DIM);
    bias_concat<<<(NQKV + 255) / 256, 256>>>(bq, bk, bv, bqkv);

    // fused QKV projection + rmsnorm + rope (q carries full 1/hd)
    gemm_qkv<<<dim3(NQKV / BN, MROWS / BM), 256, QGEMM_SMEM>>>(
        xhi, wh, bqkv, qns, kns, qah, kah, vah);

    // attention (HMMA, plain fp16)
    flash_attn_hmma<<<dim3(SEQ / 128, NH, BATCH), 256, FA_SMEM>>>(
        qah, kah, vah, aoh);

    // output projection (plain fp16)
    gemm_wo<<<dim3(DIM / BN, MROWS / BM), 256, QGEMM_SMEM>>>(
        aoh, woh, bo, out, DIM);
}